// round 1
// baseline (speedup 1.0000x reference)
#include <cuda_runtime.h>
#include <math.h>

// Problem shape (hardcoded)
#define BB    2
#define QL    1024
#define MEML  1024
#define KL    2048          // QL + MEML
#define DM    1024
#define NH    16
#define DK    64
#define D3    3072          // 3*DM
#define NEGV  1e30f

// Scratch (device globals — no allocation allowed)
__device__ float g_cat[BB * KL * DM];            // 32 MB
__device__ float g_qkv[BB * KL * D3];            // 50 MB
__device__ float g_rproj[KL * DM];               //  8 MB
__device__ float g_scores[(size_t)BB * NH * QL * KL]; // 256 MB
__device__ float g_attn[BB * QL * DM];           //  8 MB

// ---------------------------------------------------------------------------
// cat = concat(inputs_mem, inputs) along seq dim
// ---------------------------------------------------------------------------
__global__ void build_cat(const float* __restrict__ inp,
                          const float* __restrict__ mem,
                          float* __restrict__ cat) {
    int idx = blockIdx.x * blockDim.x + threadIdx.x;   // float4 index
    // total float4 = BB*KL*DM/4 = 1,048,576
    int per_b = KL * (DM / 4);
    int b = idx / per_b;
    int rem = idx - b * per_b;
    int t = rem / (DM / 4);
    int c = rem - t * (DM / 4);
    const float4* src;
    if (t < MEML)
        src = (const float4*)(mem + ((size_t)b * MEML + t) * DM) + c;
    else
        src = (const float4*)(inp + ((size_t)b * QL + (t - MEML)) * DM) + c;
    ((float4*)(cat + ((size_t)b * KL + t) * DM))[c] = *src;
}

// ---------------------------------------------------------------------------
// Generic register-blocked SGEMM: C[M,N] = A[M,K] @ B[K,N]
// BM=BN=64, BK=16, 256 threads, 4x4 microtile. Requires M,N %64==0, K%16==0.
// ---------------------------------------------------------------------------
__global__ __launch_bounds__(256)
void sgemm64(const float* __restrict__ A, const float* __restrict__ B,
             float* __restrict__ C, int M, int N, int K,
             int lda, int ldb, int ldc) {
    __shared__ float As[16][68];
    __shared__ float Bs[16][64];
    int tid = threadIdx.x;
    int tx = tid & 15, ty = tid >> 4;
    int m0 = blockIdx.y * 64, n0 = blockIdx.x * 64;
    int lm = tid >> 2;             // 0..63 (A tile row)
    int lc = (tid & 3) * 4;        // 0..12 (A tile col, step 4)
    int br = tid >> 4;             // 0..15 (B tile row)
    int bc = (tid & 15) * 4;       // 0..60 (B tile col)
    float acc[4][4] = {};
    for (int k0 = 0; k0 < K; k0 += 16) {
        float4 a = *(const float4*)&A[(size_t)(m0 + lm) * lda + k0 + lc];
        As[lc + 0][lm] = a.x; As[lc + 1][lm] = a.y;
        As[lc + 2][lm] = a.z; As[lc + 3][lm] = a.w;
        *(float4*)&Bs[br][bc] =
            *(const float4*)&B[(size_t)(k0 + br) * ldb + n0 + bc];
        __syncthreads();
#pragma unroll
        for (int kk = 0; kk < 16; kk++) {
            float4 av = *(const float4*)&As[kk][ty * 4];
            float4 bv = *(const float4*)&Bs[kk][tx * 4];
            float ar[4] = {av.x, av.y, av.z, av.w};
            float brg[4] = {bv.x, bv.y, bv.z, bv.w};
#pragma unroll
            for (int bb = 0; bb < 4; bb++)
#pragma unroll
                for (int aa = 0; aa < 4; aa++)
                    acc[bb][aa] += ar[bb] * brg[aa];
        }
        __syncthreads();
    }
#pragma unroll
    for (int bb = 0; bb < 4; bb++) {
        float4 o = make_float4(acc[bb][0], acc[bb][1], acc[bb][2], acc[bb][3]);
        *(float4*)&C[(size_t)(m0 + ty * 4 + bb) * ldc + n0 + tx * 4] = o;
    }
}

// ---------------------------------------------------------------------------
// Fused score kernel: S[b,h,i,j] = ((q_i+u)·k_j + (q_i+v)·r_{j-i+QL-1}) * 0.125
// masked (j > i + MEML) -> -1e30.  64x64 tiles, 4x4 microtile.
// ---------------------------------------------------------------------------
__global__ __launch_bounds__(256)
void score_kernel(const float* __restrict__ qkv,
                  const float* __restrict__ rproj,
                  const float* __restrict__ u,
                  const float* __restrict__ v,
                  float* __restrict__ S) {
    int bh = blockIdx.z;
    int b = bh >> 4, h = bh & 15;
    int i0 = blockIdx.y * 64;
    int j0 = blockIdx.x * 64;
    int tid = threadIdx.x;
    int tx = tid & 15, ty = tid >> 4;

    float* srow_base = S + ((size_t)bh * QL) * KL;

    // Fully-masked tile: j0 > i0+63+MEML
    if (j0 >= i0 + 64 + MEML) {
#pragma unroll
        for (int bb = 0; bb < 4; bb++) {
            int i = i0 + ty * 4 + bb;
            float4 m = make_float4(-NEGV, -NEGV, -NEGV, -NEGV);
            *(float4*)&srow_base[(size_t)i * KL + j0 + tx * 4] = m;
        }
        return;
    }

    __shared__ float Au[16][68];
    __shared__ float Av[16][68];
    __shared__ float Ks[16][68];
    __shared__ float Rs[16][132];

    int lm = tid >> 2;            // 0..63
    int lc = (tid & 3) * 4;       // 0..12
    int base = j0 - i0 + 960;     // band start row in rproj (>= 0 guaranteed)
    float acc[4][4] = {};

    for (int kc = 0; kc < DK; kc += 16) {
        // Q tile (+u, +v)
        {
            size_t qrow = (size_t)(b * KL + MEML + i0 + lm) * D3 + h * DK + kc + lc;
            float4 q4 = *(const float4*)&qkv[qrow];
            float4 u4 = *(const float4*)&u[h * DK + kc + lc];
            float4 v4 = *(const float4*)&v[h * DK + kc + lc];
            Au[lc + 0][lm] = q4.x + u4.x; Au[lc + 1][lm] = q4.y + u4.y;
            Au[lc + 2][lm] = q4.z + u4.z; Au[lc + 3][lm] = q4.w + u4.w;
            Av[lc + 0][lm] = q4.x + v4.x; Av[lc + 1][lm] = q4.y + v4.y;
            Av[lc + 2][lm] = q4.z + v4.z; Av[lc + 3][lm] = q4.w + v4.w;
        }
        // K tile
        {
            size_t krow = (size_t)(b * KL + j0 + lm) * D3 + DM + h * DK + kc + lc;
            float4 k4 = *(const float4*)&qkv[krow];
            Ks[lc + 0][lm] = k4.x; Ks[lc + 1][lm] = k4.y;
            Ks[lc + 2][lm] = k4.z; Ks[lc + 3][lm] = k4.w;
        }
        // R band: 127 rows x 16 cols
        for (int e = tid; e < 127 * 16; e += 256) {
            int row = e >> 4;
            int cc = e & 15;
            int jj = base + row;
            float val = (jj < KL) ? rproj[(size_t)jj * DM + h * DK + kc + cc] : 0.0f;
            Rs[cc][row] = val;
        }
        __syncthreads();
#pragma unroll
        for (int kk = 0; kk < 16; kk++) {
            float4 a4 = *(const float4*)&Au[kk][ty * 4];
            float4 c4 = *(const float4*)&Av[kk][ty * 4];
            float4 k4 = *(const float4*)&Ks[kk][tx * 4];
            float au[4] = {a4.x, a4.y, a4.z, a4.w};
            float av[4] = {c4.x, c4.y, c4.z, c4.w};
            float kr[4] = {k4.x, k4.y, k4.z, k4.w};
            float rr[7];
            int dbase = tx * 4 - ty * 4 + 60;
#pragma unroll
            for (int t = 0; t < 7; t++) rr[t] = Rs[kk][dbase + t];
#pragma unroll
            for (int bb = 0; bb < 4; bb++)
#pragma unroll
                for (int aa = 0; aa < 4; aa++)
                    acc[bb][aa] += au[bb] * kr[aa] + av[bb] * rr[3 + aa - bb];
        }
        __syncthreads();
    }

    // mask + scale + store
#pragma unroll
    for (int bb = 0; bb < 4; bb++) {
        int i = i0 + ty * 4 + bb;
        float o[4];
#pragma unroll
        for (int aa = 0; aa < 4; aa++) {
            int j = j0 + tx * 4 + aa;
            o[aa] = (j > i + MEML) ? -NEGV : acc[bb][aa] * 0.125f;
        }
        *(float4*)&srow_base[(size_t)i * KL + j0 + tx * 4] =
            make_float4(o[0], o[1], o[2], o[3]);
    }
}

// ---------------------------------------------------------------------------
// Row softmax over KL=2048 elements, one block per row, 256 threads x 8 elems
// ---------------------------------------------------------------------------
__global__ __launch_bounds__(256)
void softmax_kernel(float* __restrict__ S) {
    size_t row = blockIdx.x;
    float* p = S + row * KL;
    int tid = threadIdx.x;
    __shared__ float red[256];
    float x[8];
    float mx = -INFINITY;
#pragma unroll
    for (int t = 0; t < 8; t++) {
        x[t] = p[tid + t * 256];
        mx = fmaxf(mx, x[t]);
    }
    red[tid] = mx;
    __syncthreads();
    for (int s = 128; s > 0; s >>= 1) {
        if (tid < s) red[tid] = fmaxf(red[tid], red[tid + s]);
        __syncthreads();
    }
    mx = red[0];
    __syncthreads();
    float sum = 0.0f;
#pragma unroll
    for (int t = 0; t < 8; t++) {
        x[t] = expf(x[t] - mx);
        sum += x[t];
    }
    red[tid] = sum;
    __syncthreads();
    for (int s = 128; s > 0; s >>= 1) {
        if (tid < s) red[tid] += red[tid + s];
        __syncthreads();
    }
    float inv = 1.0f / red[0];
#pragma unroll
    for (int t = 0; t < 8; t++) p[tid + t * 256] = x[t] * inv;
}

// ---------------------------------------------------------------------------
// attn[b,i,h*64+d] = sum_j W[b,h,i,j] * V[b,j,h,d]
// per (i-tile, bh): M=64 rows, N=64 (full dk), K=2048
// ---------------------------------------------------------------------------
__global__ __launch_bounds__(256)
void attn_kernel(const float* __restrict__ S,
                 const float* __restrict__ qkv,
                 float* __restrict__ attn) {
    int bh = blockIdx.y;
    int b = bh >> 4, h = bh & 15;
    int i0 = blockIdx.x * 64;
    const float* A = S + ((size_t)bh * QL) * KL;

    __shared__ float As[16][68];
    __shared__ float Bs[16][64];
    int tid = threadIdx.x;
    int tx = tid & 15, ty = tid >> 4;
    int lm = tid >> 2;
    int lc = (tid & 3) * 4;
    int br = tid >> 4;
    int bc = (tid & 15) * 4;
    float acc[4][4] = {};
    for (int k0 = 0; k0 < KL; k0 += 16) {
        float4 a = *(const float4*)&A[(size_t)(i0 + lm) * KL + k0 + lc];
        As[lc + 0][lm] = a.x; As[lc + 1][lm] = a.y;
        As[lc + 2][lm] = a.z; As[lc + 3][lm] = a.w;
        size_t vrow = (size_t)(b * KL + k0 + br) * D3 + 2 * DM + h * DK + bc;
        *(float4*)&Bs[br][bc] = *(const float4*)&qkv[vrow];
        __syncthreads();
#pragma unroll
        for (int kk = 0; kk < 16; kk++) {
            float4 av = *(const float4*)&As[kk][ty * 4];
            float4 bv = *(const float4*)&Bs[kk][tx * 4];
            float ar[4] = {av.x, av.y, av.z, av.w};
            float brg[4] = {bv.x, bv.y, bv.z, bv.w};
#pragma unroll
            for (int bb = 0; bb < 4; bb++)
#pragma unroll
                for (int aa = 0; aa < 4; aa++)
                    acc[bb][aa] += ar[bb] * brg[aa];
        }
        __syncthreads();
    }
#pragma unroll
    for (int bb = 0; bb < 4; bb++) {
        int i = i0 + ty * 4 + bb;
        *(float4*)&attn[(size_t)(b * QL + i) * DM + h * DK + tx * 4] =
            make_float4(acc[bb][0], acc[bb][1], acc[bb][2], acc[bb][3]);
    }
}

// ---------------------------------------------------------------------------
extern "C" void kernel_launch(void* const* d_in, const int* in_sizes, int n_in,
                              void* d_out, int out_size) {
    const float* inputs     = (const float*)d_in[0];
    const float* inputs_mem = (const float*)d_in[1];
    const float* r          = (const float*)d_in[2];
    const float* W          = (const float*)d_in[3];
    const float* W_r        = (const float*)d_in[4];
    const float* W_o        = (const float*)d_in[5];
    const float* u          = (const float*)d_in[6];
    const float* v          = (const float*)d_in[7];
    float* out = (float*)d_out;

    float *cat, *qkv, *rproj, *scores, *attn;
    cudaGetSymbolAddress((void**)&cat,    g_cat);
    cudaGetSymbolAddress((void**)&qkv,    g_qkv);
    cudaGetSymbolAddress((void**)&rproj,  g_rproj);
    cudaGetSymbolAddress((void**)&scores, g_scores);
    cudaGetSymbolAddress((void**)&attn,   g_attn);

    // 1. cat = concat(mem, inputs)
    build_cat<<<4096, 256>>>(inputs, inputs_mem, cat);
    // 2. qkv = cat @ W   (4096 x 3072 x 1024)
    sgemm64<<<dim3(D3 / 64, BB * KL / 64), 256>>>(cat, W, qkv,
                                                  BB * KL, D3, DM, DM, D3, D3);
    // 3. rproj = r @ W_r (2048 x 1024 x 1024)
    sgemm64<<<dim3(DM / 64, KL / 64), 256>>>(r, W_r, rproj,
                                             KL, DM, DM, DM, DM, DM);
    // 4. scores (ac + shifted bd, masked, scaled)
    score_kernel<<<dim3(KL / 64, QL / 64, BB * NH), 256>>>(qkv, rproj, u, v, scores);
    // 5. softmax
    softmax_kernel<<<BB * NH * QL, 256>>>(scores);
    // 6. attn = weights @ V
    attn_kernel<<<dim3(QL / 64, BB * NH), 256>>>(scores, qkv, attn);
    // 7. out = attn @ W_o (2048 x 1024 x 1024)
    sgemm64<<<dim3(DM / 64, BB * QL / 64), 256>>>(attn, W_o, out,
                                                  BB * QL, DM, DM, DM, DM, DM);
}

// round 3
// speedup vs baseline: 1.4312x; 1.4312x over previous
#include <cuda_runtime.h>
#include <cuda_bf16.h>
#include <math.h>
#include <stdint.h>

// Problem shape (hardcoded)
#define BB    2
#define QL    1024
#define MEML  1024
#define KL    2048          // QL + MEML
#define DM    1024
#define NH    16
#define DK    64
#define D3    3072          // 3*DM
#define NEGV  1e30f

// Scratch (device globals — no allocation allowed)
__device__ float g_cat[BB * KL * DM];            // 32 MB
__device__ float g_qkv[BB * KL * D3];            // 50 MB
__device__ float g_rproj[KL * DM];               //  8 MB
__device__ float g_scores[(size_t)BB * NH * QL * KL]; // 256 MB
__device__ float g_attn[BB * QL * DM];           //  8 MB

// ---------------------------------------------------------------------------
// mma.sync bf16 helpers
// ---------------------------------------------------------------------------
__device__ __forceinline__ void mma16816(float* d, const uint32_t* a,
                                         const uint32_t* b) {
    asm volatile(
        "mma.sync.aligned.m16n8k16.row.col.f32.bf16.bf16.f32 "
        "{%0,%1,%2,%3}, {%4,%5,%6,%7}, {%8,%9}, {%0,%1,%2,%3};"
        : "+f"(d[0]), "+f"(d[1]), "+f"(d[2]), "+f"(d[3])
        : "r"(a[0]), "r"(a[1]), "r"(a[2]), "r"(a[3]), "r"(b[0]), "r"(b[1]));
}

// smem strides (bf16 elements), padded for bank-conflict-free fragment loads
#define ASTR 40
#define BSTR 34
#define APLANE (128 * ASTR)            // 5120
#define BPLANE (128 * BSTR)            // 4352
#define AHI 0
#define ALO APLANE
#define BHI (2 * APLANE)
#define BLO (2 * APLANE + BPLANE)
#define STAGE_ELEMS (2 * APLANE + 2 * BPLANE)   // 18944 bf16 = 37888 B

extern __shared__ __align__(16) char dynsm[];

// ---------------------------------------------------------------------------
// bf16-split tensor-core GEMM: C[M,N] = A[M,K] @ B[K,N]  (fp32 in/out)
// BM=128, BN=NT (128 or 64), BK=32, 256 threads (8 warps: 4 m x 2 n).
// MODE 1: per-(b,h) attention weights@V with K-loop clamped past the mask.
// ---------------------------------------------------------------------------
template <int NT, int MODE>
__device__ __forceinline__ void load_stage(const float* __restrict__ Ab,
                                           const float* __restrict__ Bb,
                                           int lda, int ldb, int k0,
                                           __nv_bfloat16* st, int tid) {
    // A tile: 128 x 32 floats
#pragma unroll
    for (int i = 0; i < 4; i++) {
        int idx = tid + i * 256;
        int row = idx >> 3, c4 = (idx & 7) << 2;
        float4 a = *(const float4*)(Ab + (size_t)row * lda + k0 + c4);
        __nv_bfloat162 h01 = __floats2bfloat162_rn(a.x, a.y);
        __nv_bfloat162 h23 = __floats2bfloat162_rn(a.z, a.w);
        float lx = a.x - __bfloat162float(h01.x);
        float ly = a.y - __bfloat162float(h01.y);
        float lz = a.z - __bfloat162float(h23.x);
        float lw = a.w - __bfloat162float(h23.y);
        __nv_bfloat162 l01 = __floats2bfloat162_rn(lx, ly);
        __nv_bfloat162 l23 = __floats2bfloat162_rn(lz, lw);
        __nv_bfloat16* pa = st + AHI + row * ASTR + c4;
        *(__nv_bfloat162*)pa = h01;
        *(__nv_bfloat162*)(pa + 2) = h23;
        __nv_bfloat16* pl = pa + APLANE;
        *(__nv_bfloat162*)pl = l01;
        *(__nv_bfloat162*)(pl + 2) = l23;
    }
    // B tile: 32 x NT floats, transposed into [n][k]
    const int nf4 = NT / 4;
    const int nsh = (NT == 128) ? 5 : 4;
    const int iters = (32 * nf4) / 256;
#pragma unroll
    for (int i = 0; i < iters; i++) {
        int idx = tid + i * 256;
        int kk = idx >> nsh, nn = (idx & (nf4 - 1)) << 2;
        float4 b = *(const float4*)(Bb + (size_t)(k0 + kk) * ldb + nn);
        float vv[4] = {b.x, b.y, b.z, b.w};
#pragma unroll
        for (int t = 0; t < 4; t++) {
            __nv_bfloat16 h = __float2bfloat16_rn(vv[t]);
            __nv_bfloat16 l = __float2bfloat16_rn(vv[t] - __bfloat162float(h));
            st[BHI + (nn + t) * BSTR + kk] = h;
            st[BLO + (nn + t) * BSTR + kk] = l;
        }
    }
}

template <int NT, int MODE>
__global__ __launch_bounds__(256)
void gemm_bf16(const float* __restrict__ A, const float* __restrict__ B,
               float* __restrict__ C, int K, int lda, int ldb, int ldc) {
    int tid = threadIdx.x, lane = tid & 31, wid = tid >> 5;
    int wy = wid & 3, wx = wid >> 2;
    int m0 = blockIdx.y * 128, n0 = blockIdx.x * NT;

    if (MODE == 1) {
        int z = blockIdx.z, b = z >> 4, h = z & 15;
        A += (size_t)z * QL * KL;
        B += (size_t)b * KL * D3 + (size_t)h * DK;
        C += (size_t)b * QL * DM + (size_t)h * DK;
    }
    const float* Ab = A + (size_t)m0 * lda;
    const float* Bb = B + n0;

    int Klim = K;
    if (MODE == 1) {
        int km = m0 + 128 + MEML;       // weights are exactly 0 past the mask
        Klim = (K < km) ? K : km;
    }
    int NC = Klim >> 5;

    __nv_bfloat16* sm = (__nv_bfloat16*)dynsm;
    const int NJ = NT / 16;             // n8-tiles per warp
    float acc[2][NJ][4];
#pragma unroll
    for (int mi = 0; mi < 2; mi++)
#pragma unroll
        for (int nj = 0; nj < NJ; nj++)
#pragma unroll
            for (int q = 0; q < 4; q++) acc[mi][nj][q] = 0.0f;

    load_stage<NT, MODE>(Ab, Bb, lda, ldb, 0, sm, tid);
    __syncthreads();

    for (int c = 0; c < NC; c++) {
        const __nv_bfloat16* st = sm + (c & 1) * STAGE_ELEMS;
#pragma unroll
        for (int kk = 0; kk < 32; kk += 16) {
            uint32_t ah[2][4], al[2][4];
#pragma unroll
            for (int mi = 0; mi < 2; mi++) {
                int r = wy * 32 + mi * 16 + (lane >> 2);
                const __nv_bfloat16* p = st + AHI + r * ASTR + kk + ((lane & 3) << 1);
                ah[mi][0] = *(const uint32_t*)p;
                ah[mi][1] = *(const uint32_t*)(p + 8 * ASTR);
                ah[mi][2] = *(const uint32_t*)(p + 8);
                ah[mi][3] = *(const uint32_t*)(p + 8 * ASTR + 8);
                const __nv_bfloat16* pl = p + APLANE;
                al[mi][0] = *(const uint32_t*)pl;
                al[mi][1] = *(const uint32_t*)(pl + 8 * ASTR);
                al[mi][2] = *(const uint32_t*)(pl + 8);
                al[mi][3] = *(const uint32_t*)(pl + 8 * ASTR + 8);
            }
#pragma unroll
            for (int nj = 0; nj < NJ; nj++) {
                int n = wx * (NT / 2) + nj * 8 + (lane >> 2);
                const __nv_bfloat16* pb = st + BHI + n * BSTR + kk + ((lane & 3) << 1);
                uint32_t bh[2], bl[2];
                bh[0] = *(const uint32_t*)pb;
                bh[1] = *(const uint32_t*)(pb + 8);
                const __nv_bfloat16* pq = pb + BPLANE;
                bl[0] = *(const uint32_t*)pq;
                bl[1] = *(const uint32_t*)(pq + 8);
#pragma unroll
                for (int mi = 0; mi < 2; mi++) {
                    mma16816(acc[mi][nj], ah[mi], bh);
                    mma16816(acc[mi][nj], ah[mi], bl);
                    mma16816(acc[mi][nj], al[mi], bh);
                }
            }
        }
        if (c + 1 < NC)
            load_stage<NT, MODE>(Ab, Bb, lda, ldb, (c + 1) << 5,
                                 sm + ((c + 1) & 1) * STAGE_ELEMS, tid);
        __syncthreads();
    }

    // Epilogue
#pragma unroll
    for (int mi = 0; mi < 2; mi++) {
#pragma unroll
        for (int nj = 0; nj < NJ; nj++) {
            int r = m0 + wy * 32 + mi * 16 + (lane >> 2);
            int ncol = n0 + wx * (NT / 2) + nj * 8 + ((lane & 3) << 1);
            float2 v0 = make_float2(acc[mi][nj][0], acc[mi][nj][1]);
            float2 v1 = make_float2(acc[mi][nj][2], acc[mi][nj][3]);
            *(float2*)&C[(size_t)r * ldc + ncol] = v0;
            *(float2*)&C[(size_t)(r + 8) * ldc + ncol] = v1;
        }
    }
}

// ---------------------------------------------------------------------------
// cat = concat(inputs_mem, inputs) along seq dim
// ---------------------------------------------------------------------------
__global__ void build_cat(const float* __restrict__ inp,
                          const float* __restrict__ mem,
                          float* __restrict__ cat) {
    int idx = blockIdx.x * blockDim.x + threadIdx.x;
    int per_b = KL * (DM / 4);
    int b = idx / per_b;
    int rem = idx - b * per_b;
    int t = rem / (DM / 4);
    int c = rem - t * (DM / 4);
    const float4* src;
    if (t < MEML)
        src = (const float4*)(mem + ((size_t)b * MEML + t) * DM) + c;
    else
        src = (const float4*)(inp + ((size_t)b * QL + (t - MEML)) * DM) + c;
    ((float4*)(cat + ((size_t)b * KL + t) * DM))[c] = *src;
}

// ---------------------------------------------------------------------------
// Fused score kernel (unchanged from R1)
// ---------------------------------------------------------------------------
__global__ __launch_bounds__(256)
void score_kernel(const float* __restrict__ qkv,
                  const float* __restrict__ rproj,
                  const float* __restrict__ u,
                  const float* __restrict__ v,
                  float* __restrict__ S) {
    int bh = blockIdx.z;
    int b = bh >> 4, h = bh & 15;
    int i0 = blockIdx.y * 64;
    int j0 = blockIdx.x * 64;
    int tid = threadIdx.x;
    int tx = tid & 15, ty = tid >> 4;

    float* srow_base = S + ((size_t)bh * QL) * KL;

    if (j0 >= i0 + 64 + MEML) {
#pragma unroll
        for (int bb = 0; bb < 4; bb++) {
            int i = i0 + ty * 4 + bb;
            float4 m = make_float4(-NEGV, -NEGV, -NEGV, -NEGV);
            *(float4*)&srow_base[(size_t)i * KL + j0 + tx * 4] = m;
        }
        return;
    }

    __shared__ float Au[16][68];
    __shared__ float Av[16][68];
    __shared__ float Ks[16][68];
    __shared__ float Rs[16][132];

    int lm = tid >> 2;
    int lc = (tid & 3) * 4;
    int base = j0 - i0 + 960;
    float acc[4][4] = {};

    for (int kc = 0; kc < DK; kc += 16) {
        {
            size_t qrow = (size_t)(b * KL + MEML + i0 + lm) * D3 + h * DK + kc + lc;
            float4 q4 = *(const float4*)&qkv[qrow];
            float4 u4 = *(const float4*)&u[h * DK + kc + lc];
            float4 v4 = *(const float4*)&v[h * DK + kc + lc];
            Au[lc + 0][lm] = q4.x + u4.x; Au[lc + 1][lm] = q4.y + u4.y;
            Au[lc + 2][lm] = q4.z + u4.z; Au[lc + 3][lm] = q4.w + u4.w;
            Av[lc + 0][lm] = q4.x + v4.x; Av[lc + 1][lm] = q4.y + v4.y;
            Av[lc + 2][lm] = q4.z + v4.z; Av[lc + 3][lm] = q4.w + v4.w;
        }
        {
            size_t krow = (size_t)(b * KL + j0 + lm) * D3 + DM + h * DK + kc + lc;
            float4 k4 = *(const float4*)&qkv[krow];
            Ks[lc + 0][lm] = k4.x; Ks[lc + 1][lm] = k4.y;
            Ks[lc + 2][lm] = k4.z; Ks[lc + 3][lm] = k4.w;
        }
        for (int e = tid; e < 127 * 16; e += 256) {
            int row = e >> 4;
            int cc = e & 15;
            int jj = base + row;
            float val = (jj < KL) ? rproj[(size_t)jj * DM + h * DK + kc + cc] : 0.0f;
            Rs[cc][row] = val;
        }
        __syncthreads();
#pragma unroll
        for (int kk = 0; kk < 16; kk++) {
            float4 a4 = *(const float4*)&Au[kk][ty * 4];
            float4 c4 = *(const float4*)&Av[kk][ty * 4];
            float4 k4 = *(const float4*)&Ks[kk][tx * 4];
            float au[4] = {a4.x, a4.y, a4.z, a4.w};
            float av[4] = {c4.x, c4.y, c4.z, c4.w};
            float kr[4] = {k4.x, k4.y, k4.z, k4.w};
            float rr[7];
            int dbase = tx * 4 - ty * 4 + 60;
#pragma unroll
            for (int t = 0; t < 7; t++) rr[t] = Rs[kk][dbase + t];
#pragma unroll
            for (int bb = 0; bb < 4; bb++)
#pragma unroll
                for (int aa = 0; aa < 4; aa++)
                    acc[bb][aa] += au[bb] * kr[aa] + av[bb] * rr[3 + aa - bb];
        }
        __syncthreads();
    }

#pragma unroll
    for (int bb = 0; bb < 4; bb++) {
        int i = i0 + ty * 4 + bb;
        float o[4];
#pragma unroll
        for (int aa = 0; aa < 4; aa++) {
            int j = j0 + tx * 4 + aa;
            o[aa] = (j > i + MEML) ? -NEGV : acc[bb][aa] * 0.125f;
        }
        *(float4*)&srow_base[(size_t)i * KL + j0 + tx * 4] =
            make_float4(o[0], o[1], o[2], o[3]);
    }
}

// ---------------------------------------------------------------------------
// Row softmax over KL=2048 elements
// ---------------------------------------------------------------------------
__global__ __launch_bounds__(256)
void softmax_kernel(float* __restrict__ S) {
    size_t row = blockIdx.x;
    float* p = S + row * KL;
    int tid = threadIdx.x;
    __shared__ float red[256];
    float x[8];
    float mx = -INFINITY;
#pragma unroll
    for (int t = 0; t < 8; t++) {
        x[t] = p[tid + t * 256];
        mx = fmaxf(mx, x[t]);
    }
    red[tid] = mx;
    __syncthreads();
    for (int s = 128; s > 0; s >>= 1) {
        if (tid < s) red[tid] = fmaxf(red[tid], red[tid + s]);
        __syncthreads();
    }
    mx = red[0];
    __syncthreads();
    float sum = 0.0f;
#pragma unroll
    for (int t = 0; t < 8; t++) {
        x[t] = expf(x[t] - mx);
        sum += x[t];
    }
    red[tid] = sum;
    __syncthreads();
    for (int s = 128; s > 0; s >>= 1) {
        if (tid < s) red[tid] += red[tid + s];
        __syncthreads();
    }
    float inv = 1.0f / red[0];
#pragma unroll
    for (int t = 0; t < 8; t++) p[tid + t * 256] = x[t] * inv;
}

// ---------------------------------------------------------------------------
extern "C" void kernel_launch(void* const* d_in, const int* in_sizes, int n_in,
                              void* d_out, int out_size) {
    const float* inputs     = (const float*)d_in[0];
    const float* inputs_mem = (const float*)d_in[1];
    const float* r          = (const float*)d_in[2];
    const float* W          = (const float*)d_in[3];
    const float* W_r        = (const float*)d_in[4];
    const float* W_o        = (const float*)d_in[5];
    const float* u          = (const float*)d_in[6];
    const float* v          = (const float*)d_in[7];
    float* out = (float*)d_out;

    float *cat, *qkv, *rproj, *scores, *attn;
    cudaGetSymbolAddress((void**)&cat,    g_cat);
    cudaGetSymbolAddress((void**)&qkv,    g_qkv);
    cudaGetSymbolAddress((void**)&rproj,  g_rproj);
    cudaGetSymbolAddress((void**)&scores, g_scores);
    cudaGetSymbolAddress((void**)&attn,   g_attn);

    const int SMEM = 2 * STAGE_ELEMS * 2;   // 75776 bytes
    static int attr_done = 0;
    cudaFuncSetAttribute(gemm_bf16<128, 0>,
                         cudaFuncAttributeMaxDynamicSharedMemorySize, SMEM);
    cudaFuncSetAttribute(gemm_bf16<64, 1>,
                         cudaFuncAttributeMaxDynamicSharedMemorySize, SMEM);
    (void)attr_done;

    // 1. cat = concat(mem, inputs)
    build_cat<<<4096, 256>>>(inputs, inputs_mem, cat);
    // 2. qkv = cat @ W   (4096 x 3072 x 1024)
    gemm_bf16<128, 0><<<dim3(D3 / 128, (BB * KL) / 128), 256, SMEM>>>(
        cat, W, qkv, DM, DM, D3, D3);
    // 3. rproj = r @ W_r (2048 x 1024 x 1024)
    gemm_bf16<128, 0><<<dim3(DM / 128, KL / 128), 256, SMEM>>>(
        r, W_r, rproj, DM, DM, DM, DM);
    // 4. scores (ac + shifted bd, masked, scaled)
    score_kernel<<<dim3(KL / 64, QL / 64, BB * NH), 256>>>(qkv, rproj, u, v, scores);
    // 5. softmax
    softmax_kernel<<<BB * NH * QL, 256>>>(scores);
    // 6. attn = weights @ V   (per (b,h): 1024 x 64 x <=2048)
    gemm_bf16<64, 1><<<dim3(1, QL / 128, BB * NH), 256, SMEM>>>(
        scores, qkv + 2 * DM, attn, KL, KL, D3, DM);
    // 7. out = attn @ W_o (2048 x 1024 x 1024)
    gemm_bf16<128, 0><<<dim3(DM / 128, (BB * QL) / 128), 256, SMEM>>>(
        attn, W_o, out, DM, DM, DM, DM);
}

// round 4
// speedup vs baseline: 1.8298x; 1.2786x over previous
#include <cuda_runtime.h>
#include <cuda_bf16.h>
#include <math.h>
#include <stdint.h>

// Problem shape (hardcoded)
#define BB    2
#define QL    1024
#define MEML  1024
#define KL    2048          // QL + MEML
#define DM    1024
#define NH    16
#define DK    64
#define D3    3072          // 3*DM
#define NEGV  1e30f

// Scratch (device globals — no allocation allowed)
__device__ float g_cat[BB * KL * DM];            // 32 MB
__device__ float g_qkv[BB * KL * D3];            // 50 MB
__device__ float g_rproj[KL * DM];               //  8 MB
__device__ float g_scores[(size_t)BB * NH * QL * KL]; // 256 MB
__device__ float g_bdu[(size_t)BB * NH * QL * KL];    // 256 MB (unshifted bd)
__device__ float g_attn[BB * QL * DM];           //  8 MB

// ---------------------------------------------------------------------------
// mma.sync bf16 helpers
// ---------------------------------------------------------------------------
__device__ __forceinline__ void mma16816(float* d, const uint32_t* a,
                                         const uint32_t* b) {
    asm volatile(
        "mma.sync.aligned.m16n8k16.row.col.f32.bf16.bf16.f32 "
        "{%0,%1,%2,%3}, {%4,%5,%6,%7}, {%8,%9}, {%0,%1,%2,%3};"
        : "+f"(d[0]), "+f"(d[1]), "+f"(d[2]), "+f"(d[3])
        : "r"(a[0]), "r"(a[1]), "r"(a[2]), "r"(a[3]), "r"(b[0]), "r"(b[1]));
}

// smem strides (bf16 elements), padded for bank-conflict-free fragment loads
#define ASTR 40
#define BSTR 34
#define APLANE (128 * ASTR)            // 5120
#define BPLANE (128 * BSTR)            // 4352
#define AHI 0
#define ALO APLANE
#define BHI (2 * APLANE)
#define BLO (2 * APLANE + BPLANE)
#define STAGE_ELEMS (2 * APLANE + 2 * BPLANE)   // 18944 bf16 = 37888 B

extern __shared__ __align__(16) char dynsm[];

// ---------------------------------------------------------------------------
// bf16-split tensor-core GEMM: C[M,N] = A[M,K] @ B[K,N]  (fp32 in/out)
// BM=128, BN=NT (128 or 64), BK=32, 256 threads (8 warps: 4 m x 2 n).
// MODE 1: per-(b,h) attention weights@V with K-loop clamped past the mask.
// ---------------------------------------------------------------------------
template <int NT, int MODE>
__device__ __forceinline__ void load_stage(const float* __restrict__ Ab,
                                           const float* __restrict__ Bb,
                                           int lda, int ldb, int k0,
                                           __nv_bfloat16* st, int tid) {
#pragma unroll
    for (int i = 0; i < 4; i++) {
        int idx = tid + i * 256;
        int row = idx >> 3, c4 = (idx & 7) << 2;
        float4 a = *(const float4*)(Ab + (size_t)row * lda + k0 + c4);
        __nv_bfloat162 h01 = __floats2bfloat162_rn(a.x, a.y);
        __nv_bfloat162 h23 = __floats2bfloat162_rn(a.z, a.w);
        float lx = a.x - __bfloat162float(h01.x);
        float ly = a.y - __bfloat162float(h01.y);
        float lz = a.z - __bfloat162float(h23.x);
        float lw = a.w - __bfloat162float(h23.y);
        __nv_bfloat162 l01 = __floats2bfloat162_rn(lx, ly);
        __nv_bfloat162 l23 = __floats2bfloat162_rn(lz, lw);
        __nv_bfloat16* pa = st + AHI + row * ASTR + c4;
        *(__nv_bfloat162*)pa = h01;
        *(__nv_bfloat162*)(pa + 2) = h23;
        __nv_bfloat16* pl = pa + APLANE;
        *(__nv_bfloat162*)pl = l01;
        *(__nv_bfloat162*)(pl + 2) = l23;
    }
    const int nf4 = NT / 4;
    const int nsh = (NT == 128) ? 5 : 4;
    const int iters = (32 * nf4) / 256;
#pragma unroll
    for (int i = 0; i < iters; i++) {
        int idx = tid + i * 256;
        int kk = idx >> nsh, nn = (idx & (nf4 - 1)) << 2;
        float4 b = *(const float4*)(Bb + (size_t)(k0 + kk) * ldb + nn);
        float vv[4] = {b.x, b.y, b.z, b.w};
#pragma unroll
        for (int t = 0; t < 4; t++) {
            __nv_bfloat16 h = __float2bfloat16_rn(vv[t]);
            __nv_bfloat16 l = __float2bfloat16_rn(vv[t] - __bfloat162float(h));
            st[BHI + (nn + t) * BSTR + kk] = h;
            st[BLO + (nn + t) * BSTR + kk] = l;
        }
    }
}

template <int NT, int MODE>
__global__ __launch_bounds__(256)
void gemm_bf16(const float* __restrict__ A, const float* __restrict__ B,
               float* __restrict__ C, int K, int lda, int ldb, int ldc) {
    int tid = threadIdx.x, lane = tid & 31, wid = tid >> 5;
    int wy = wid & 3, wx = wid >> 2;
    int m0 = blockIdx.y * 128, n0 = blockIdx.x * NT;

    if (MODE == 1) {
        int z = blockIdx.z, b = z >> 4, h = z & 15;
        A += (size_t)z * QL * KL;
        B += (size_t)b * KL * D3 + (size_t)h * DK;
        C += (size_t)b * QL * DM + (size_t)h * DK;
    }
    const float* Ab = A + (size_t)m0 * lda;
    const float* Bb = B + n0;

    int Klim = K;
    if (MODE == 1) {
        int km = m0 + 128 + MEML;
        Klim = (K < km) ? K : km;
    }
    int NC = Klim >> 5;

    __nv_bfloat16* sm = (__nv_bfloat16*)dynsm;
    const int NJ = NT / 16;
    float acc[2][NJ][4];
#pragma unroll
    for (int mi = 0; mi < 2; mi++)
#pragma unroll
        for (int nj = 0; nj < NJ; nj++)
#pragma unroll
            for (int q = 0; q < 4; q++) acc[mi][nj][q] = 0.0f;

    load_stage<NT, MODE>(Ab, Bb, lda, ldb, 0, sm, tid);
    __syncthreads();

    for (int c = 0; c < NC; c++) {
        const __nv_bfloat16* st = sm + (c & 1) * STAGE_ELEMS;
#pragma unroll
        for (int kk = 0; kk < 32; kk += 16) {
            uint32_t ah[2][4], al[2][4];
#pragma unroll
            for (int mi = 0; mi < 2; mi++) {
                int r = wy * 32 + mi * 16 + (lane >> 2);
                const __nv_bfloat16* p = st + AHI + r * ASTR + kk + ((lane & 3) << 1);
                ah[mi][0] = *(const uint32_t*)p;
                ah[mi][1] = *(const uint32_t*)(p + 8 * ASTR);
                ah[mi][2] = *(const uint32_t*)(p + 8);
                ah[mi][3] = *(const uint32_t*)(p + 8 * ASTR + 8);
                const __nv_bfloat16* pl = p + APLANE;
                al[mi][0] = *(const uint32_t*)pl;
                al[mi][1] = *(const uint32_t*)(pl + 8 * ASTR);
                al[mi][2] = *(const uint32_t*)(pl + 8);
                al[mi][3] = *(const uint32_t*)(pl + 8 * ASTR + 8);
            }
#pragma unroll
            for (int nj = 0; nj < NJ; nj++) {
                int n = wx * (NT / 2) + nj * 8 + (lane >> 2);
                const __nv_bfloat16* pb = st + BHI + n * BSTR + kk + ((lane & 3) << 1);
                uint32_t bh[2], bl[2];
                bh[0] = *(const uint32_t*)pb;
                bh[1] = *(const uint32_t*)(pb + 8);
                const __nv_bfloat16* pq = pb + BPLANE;
                bl[0] = *(const uint32_t*)pq;
                bl[1] = *(const uint32_t*)(pq + 8);
#pragma unroll
                for (int mi = 0; mi < 2; mi++) {
                    mma16816(acc[mi][nj], ah[mi], bh);
                    mma16816(acc[mi][nj], ah[mi], bl);
                    mma16816(acc[mi][nj], al[mi], bh);
                }
            }
        }
        if (c + 1 < NC)
            load_stage<NT, MODE>(Ab, Bb, lda, ldb, (c + 1) << 5,
                                 sm + ((c + 1) & 1) * STAGE_ELEMS, tid);
        __syncthreads();
    }

#pragma unroll
    for (int mi = 0; mi < 2; mi++) {
#pragma unroll
        for (int nj = 0; nj < NJ; nj++) {
            int r = m0 + wy * 32 + mi * 16 + (lane >> 2);
            int ncol = n0 + wx * (NT / 2) + nj * 8 + ((lane & 3) << 1);
            float2 v0 = make_float2(acc[mi][nj][0], acc[mi][nj][1]);
            float2 v1 = make_float2(acc[mi][nj][2], acc[mi][nj][3]);
            *(float2*)&C[(size_t)r * ldc + ncol] = v0;
            *(float2*)&C[(size_t)(r + 8) * ldc + ncol] = v1;
        }
    }
}

// ---------------------------------------------------------------------------
// Score GEMMs on tensor cores.
// MODE 0: AC[i,j] = (q_i + u_h) . k_j     (skip fully masked tiles)
// MODE 1: U[i,p]  = (q_i + v_h) . r_p     (skip never-read tiles)
// Per (b,h): M=1024 (i), N=2048 (j/p), K=64. 128x128 tiles, one-shot K load.
// smem planes stride 72 (64 + 8 pad).
// ---------------------------------------------------------------------------
#define SSTR 72
#define SPLANE (128 * SSTR)            // 9216 elems

template <int MODE>
__global__ __launch_bounds__(256)
void score_gemm(const float* __restrict__ qkv,
                const float* __restrict__ rproj,
                const float* __restrict__ u,
                const float* __restrict__ v,
                float* __restrict__ C) {
    int bh = blockIdx.z;
    int b = bh >> 4, h = bh & 15;
    int i0 = blockIdx.y * 128;
    int j0 = blockIdx.x * 128;

    if (MODE == 0) { if (j0 - i0 >= 1152) return; }
    else           { if (i0 + j0 <= 768) return; }

    int tid = threadIdx.x, lane = tid & 31, wid = tid >> 5;
    int wy = wid & 3, wx = wid >> 2;

    __nv_bfloat16* sm = (__nv_bfloat16*)dynsm;
    __nv_bfloat16* Ah = sm;
    __nv_bfloat16* Al = sm + SPLANE;
    __nv_bfloat16* Bh = sm + 2 * SPLANE;
    __nv_bfloat16* Bl = sm + 3 * SPLANE;

    const float* uv = (MODE == 0) ? u : v;

    // Load A = Q tile + u/v : 128 rows x 64 cols
#pragma unroll
    for (int it = 0; it < 8; it++) {
        int e = tid + it * 256;
        int row = e >> 4, c4 = (e & 15) << 2;
        size_t addr = (size_t)(b * KL + MEML + i0 + row) * D3 + h * DK + c4;
        float4 a = *(const float4*)(qkv + addr);
        float4 w = *(const float4*)(uv + h * DK + c4);
        a.x += w.x; a.y += w.y; a.z += w.z; a.w += w.w;
        __nv_bfloat162 h01 = __floats2bfloat162_rn(a.x, a.y);
        __nv_bfloat162 h23 = __floats2bfloat162_rn(a.z, a.w);
        __nv_bfloat162 l01 = __floats2bfloat162_rn(a.x - __bfloat162float(h01.x),
                                                   a.y - __bfloat162float(h01.y));
        __nv_bfloat162 l23 = __floats2bfloat162_rn(a.z - __bfloat162float(h23.x),
                                                   a.w - __bfloat162float(h23.y));
        int off = row * SSTR + c4;
        *(__nv_bfloat162*)(Ah + off) = h01;
        *(__nv_bfloat162*)(Ah + off + 2) = h23;
        *(__nv_bfloat162*)(Al + off) = l01;
        *(__nv_bfloat162*)(Al + off + 2) = l23;
    }
    // Load B tile (row n = key/rel position, 64 cols)
#pragma unroll
    for (int it = 0; it < 8; it++) {
        int e = tid + it * 256;
        int row = e >> 4, c4 = (e & 15) << 2;
        size_t addr;
        if (MODE == 0)
            addr = (size_t)(b * KL + j0 + row) * D3 + DM + h * DK + c4;
        else
            addr = (size_t)(j0 + row) * DM + h * DK + c4;
        const float* src = (MODE == 0) ? qkv : rproj;
        float4 a = *(const float4*)(src + addr);
        __nv_bfloat162 h01 = __floats2bfloat162_rn(a.x, a.y);
        __nv_bfloat162 h23 = __floats2bfloat162_rn(a.z, a.w);
        __nv_bfloat162 l01 = __floats2bfloat162_rn(a.x - __bfloat162float(h01.x),
                                                   a.y - __bfloat162float(h01.y));
        __nv_bfloat162 l23 = __floats2bfloat162_rn(a.z - __bfloat162float(h23.x),
                                                   a.w - __bfloat162float(h23.y));
        int off = row * SSTR + c4;
        *(__nv_bfloat162*)(Bh + off) = h01;
        *(__nv_bfloat162*)(Bh + off + 2) = h23;
        *(__nv_bfloat162*)(Bl + off) = l01;
        *(__nv_bfloat162*)(Bl + off + 2) = l23;
    }
    __syncthreads();

    float acc[2][8][4];
#pragma unroll
    for (int mi = 0; mi < 2; mi++)
#pragma unroll
        for (int nj = 0; nj < 8; nj++)
#pragma unroll
            for (int q = 0; q < 4; q++) acc[mi][nj][q] = 0.0f;

#pragma unroll
    for (int kk = 0; kk < 64; kk += 16) {
        uint32_t ah[2][4], al[2][4];
#pragma unroll
        for (int mi = 0; mi < 2; mi++) {
            int r = wy * 32 + mi * 16 + (lane >> 2);
            const __nv_bfloat16* p = Ah + r * SSTR + kk + ((lane & 3) << 1);
            ah[mi][0] = *(const uint32_t*)p;
            ah[mi][1] = *(const uint32_t*)(p + 8 * SSTR);
            ah[mi][2] = *(const uint32_t*)(p + 8);
            ah[mi][3] = *(const uint32_t*)(p + 8 * SSTR + 8);
            const __nv_bfloat16* pl = p + SPLANE;
            al[mi][0] = *(const uint32_t*)pl;
            al[mi][1] = *(const uint32_t*)(pl + 8 * SSTR);
            al[mi][2] = *(const uint32_t*)(pl + 8);
            al[mi][3] = *(const uint32_t*)(pl + 8 * SSTR + 8);
        }
#pragma unroll
        for (int nj = 0; nj < 8; nj++) {
            int n = wx * 64 + nj * 8 + (lane >> 2);
            const __nv_bfloat16* pb = Bh + n * SSTR + kk + ((lane & 3) << 1);
            uint32_t bhf[2], blf[2];
            bhf[0] = *(const uint32_t*)pb;
            bhf[1] = *(const uint32_t*)(pb + 8);
            const __nv_bfloat16* pq = pb + SPLANE;
            blf[0] = *(const uint32_t*)pq;
            blf[1] = *(const uint32_t*)(pq + 8);
#pragma unroll
            for (int mi = 0; mi < 2; mi++) {
                mma16816(acc[mi][nj], ah[mi], bhf);
                mma16816(acc[mi][nj], ah[mi], blf);
                mma16816(acc[mi][nj], al[mi], bhf);
            }
        }
    }

    float* Cb = C + (size_t)bh * QL * KL;
#pragma unroll
    for (int mi = 0; mi < 2; mi++) {
#pragma unroll
        for (int nj = 0; nj < 8; nj++) {
            int r = i0 + wy * 32 + mi * 16 + (lane >> 2);
            int ncol = j0 + wx * 64 + nj * 8 + ((lane & 3) << 1);
            *(float2*)&Cb[(size_t)r * KL + ncol] =
                make_float2(acc[mi][nj][0], acc[mi][nj][1]);
            *(float2*)&Cb[(size_t)(r + 8) * KL + ncol] =
                make_float2(acc[mi][nj][2], acc[mi][nj][3]);
        }
    }
}

// ---------------------------------------------------------------------------
// cat = concat(inputs_mem, inputs) along seq dim
// ---------------------------------------------------------------------------
__global__ void build_cat(const float* __restrict__ inp,
                          const float* __restrict__ mem,
                          float* __restrict__ cat) {
    int idx = blockIdx.x * blockDim.x + threadIdx.x;
    int per_b = KL * (DM / 4);
    int b = idx / per_b;
    int rem = idx - b * per_b;
    int t = rem / (DM / 4);
    int c = rem - t * (DM / 4);
    const float4* src;
    if (t < MEML)
        src = (const float4*)(mem + ((size_t)b * MEML + t) * DM) + c;
    else
        src = (const float4*)(inp + ((size_t)b * QL + (t - MEML)) * DM) + c;
    ((float4*)(cat + ((size_t)b * KL + t) * DM))[c] = *src;
}

// ---------------------------------------------------------------------------
// Fused rel-shift + mask + scale + softmax.
// Row (bh, i): w[j] = softmax_j( (AC[i,j] + U[i, j+1023-i]) * 0.125 ), j<=i+MEML
// Writes weights in-place over AC. Masked entries get exact 0.
// ---------------------------------------------------------------------------
__global__ __launch_bounds__(256)
void fused_softmax(float* __restrict__ AC, const float* __restrict__ U) {
    int rid = blockIdx.x;                 // bh*1024 + i
    int i = rid & (QL - 1);
    float* p = AC + (size_t)rid * KL;
    const float* uu = U + (size_t)rid * KL + (QL - 1 - i);
    int jmax = i + MEML;
    int tid = threadIdx.x;
    __shared__ float red[256];

    float x[8];
    float mx = -INFINITY;
#pragma unroll
    for (int t = 0; t < 8; t++) {
        int j = tid + t * 256;
        if (j <= jmax) {
            x[t] = (p[j] + uu[j]) * 0.125f;
            mx = fmaxf(mx, x[t]);
        } else {
            x[t] = -INFINITY;
        }
    }
    red[tid] = mx;
    __syncthreads();
    for (int s = 128; s > 0; s >>= 1) {
        if (tid < s) red[tid] = fmaxf(red[tid], red[tid + s]);
        __syncthreads();
    }
    mx = red[0];
    __syncthreads();
    float sum = 0.0f;
#pragma unroll
    for (int t = 0; t < 8; t++) {
        x[t] = expf(x[t] - mx);
        sum += x[t];
    }
    red[tid] = sum;
    __syncthreads();
    for (int s = 128; s > 0; s >>= 1) {
        if (tid < s) red[tid] += red[tid + s];
        __syncthreads();
    }
    float inv = 1.0f / red[0];
#pragma unroll
    for (int t = 0; t < 8; t++) p[tid + t * 256] = x[t] * inv;
}

// ---------------------------------------------------------------------------
extern "C" void kernel_launch(void* const* d_in, const int* in_sizes, int n_in,
                              void* d_out, int out_size) {
    const float* inputs     = (const float*)d_in[0];
    const float* inputs_mem = (const float*)d_in[1];
    const float* r          = (const float*)d_in[2];
    const float* W          = (const float*)d_in[3];
    const float* W_r        = (const float*)d_in[4];
    const float* W_o        = (const float*)d_in[5];
    const float* u          = (const float*)d_in[6];
    const float* v          = (const float*)d_in[7];
    float* out = (float*)d_out;

    float *cat, *qkv, *rproj, *scores, *bdu, *attn;
    cudaGetSymbolAddress((void**)&cat,    g_cat);
    cudaGetSymbolAddress((void**)&qkv,    g_qkv);
    cudaGetSymbolAddress((void**)&rproj,  g_rproj);
    cudaGetSymbolAddress((void**)&scores, g_scores);
    cudaGetSymbolAddress((void**)&bdu,    g_bdu);
    cudaGetSymbolAddress((void**)&attn,   g_attn);

    const int SMEM = 2 * STAGE_ELEMS * 2;      // 75776 bytes
    const int SSMEM = 4 * SPLANE * 2;          // 73728 bytes
    cudaFuncSetAttribute(gemm_bf16<128, 0>,
                         cudaFuncAttributeMaxDynamicSharedMemorySize, SMEM);
    cudaFuncSetAttribute(gemm_bf16<64, 1>,
                         cudaFuncAttributeMaxDynamicSharedMemorySize, SMEM);
    cudaFuncSetAttribute(score_gemm<0>,
                         cudaFuncAttributeMaxDynamicSharedMemorySize, SSMEM);
    cudaFuncSetAttribute(score_gemm<1>,
                         cudaFuncAttributeMaxDynamicSharedMemorySize, SSMEM);

    // 1. cat = concat(mem, inputs)
    build_cat<<<4096, 256>>>(inputs, inputs_mem, cat);
    // 2. qkv = cat @ W   (4096 x 3072 x 1024)
    gemm_bf16<128, 0><<<dim3(D3 / 128, (BB * KL) / 128), 256, SMEM>>>(
        cat, W, qkv, DM, DM, D3, D3);
    // 3. rproj = r @ W_r (2048 x 1024 x 1024)
    gemm_bf16<128, 0><<<dim3(DM / 128, KL / 128), 256, SMEM>>>(
        r, W_r, rproj, DM, DM, DM, DM);
    // 4a. AC = (Q+u) @ K^T  -> scores (raw)
    score_gemm<0><<<dim3(KL / 128, QL / 128, BB * NH), 256, SSMEM>>>(
        qkv, rproj, u, v, scores);
    // 4b. U = (Q+v) @ Rproj^T -> bdu (raw, unshifted)
    score_gemm<1><<<dim3(KL / 128, QL / 128, BB * NH), 256, SSMEM>>>(
        qkv, rproj, u, v, bdu);
    // 5. fused shift+mask+scale+softmax (in-place on scores)
    fused_softmax<<<BB * NH * QL, 256>>>(scores, bdu);
    // 6. attn = weights @ V   (per (b,h): 1024 x 64 x <=2048)
    gemm_bf16<64, 1><<<dim3(1, QL / 128, BB * NH), 256, SMEM>>>(
        scores, qkv + 2 * DM, attn, KL, KL, D3, DM);
    // 7. out = attn @ W_o (2048 x 1024 x 1024)
    gemm_bf16<128, 0><<<dim3(DM / 128, (BB * QL) / 128), 256, SMEM>>>(
        attn, W_o, out, DM, DM, DM, DM);
}

// round 5
// speedup vs baseline: 1.8714x; 1.0227x over previous
#include <cuda_runtime.h>
#include <cuda_bf16.h>
#include <math.h>
#include <stdint.h>

#define BB    2
#define QL    1024
#define MEML  1024
#define KL    2048
#define DM    1024
#define NH    16
#define DK    64
#define D3    3072

typedef __nv_bfloat16  bf16;
typedef __nv_bfloat162 bf162;

// ---------------- scratch (device globals, no allocation) ----------------
__device__ bf16 g_catH[BB * KL * DM], g_catL[BB * KL * DM];
__device__ bf16 g_WH[DM * D3],  g_WL[DM * D3];
__device__ bf16 g_WrH[DM * DM], g_WrL[DM * DM];
__device__ bf16 g_WoH[DM * DM], g_WoL[DM * DM];
__device__ bf16 g_rsH[KL * DM], g_rsL[KL * DM];
__device__ bf16 g_qkvH[BB * KL * D3], g_qkvL[BB * KL * D3];
__device__ bf16 g_rpH[KL * DM], g_rpL[KL * DM];
__device__ bf16 g_attnH[BB * QL * DM], g_attnL[BB * QL * DM];
__device__ float g_scores[(size_t)BB * NH * QL * KL];
__device__ float g_bdu[(size_t)BB * NH * QL * KL];
__device__ bf16 g_wtH[(size_t)BB * NH * QL * KL];
__device__ bf16 g_wtL[(size_t)BB * NH * QL * KL];
__device__ float g_biasU[BB * NH * KL];
__device__ float g_biasV[NH * KL];

// ---------------- helpers ----------------
__device__ __forceinline__ void split1(float x, bf16& h, bf16& l) {
    h = __float2bfloat16_rn(x);
    l = __float2bfloat16_rn(x - __bfloat162float(h));
}
__device__ __forceinline__ void cp16(uint32_t dst, const void* src) {
    asm volatile("cp.async.cg.shared.global [%0], [%1], 16;\n" :: "r"(dst), "l"(src));
}
__device__ __forceinline__ void cp_commit() {
    asm volatile("cp.async.commit_group;\n");
}
__device__ __forceinline__ void cp_wait0() {
    asm volatile("cp.async.wait_group 0;\n");
}
__device__ __forceinline__ void mma16816(float* d, const uint32_t* a,
                                         const uint32_t* b) {
    asm volatile(
        "mma.sync.aligned.m16n8k16.row.col.f32.bf16.bf16.f32 "
        "{%0,%1,%2,%3}, {%4,%5,%6,%7}, {%8,%9}, {%0,%1,%2,%3};"
        : "+f"(d[0]), "+f"(d[1]), "+f"(d[2]), "+f"(d[3])
        : "r"(a[0]), "r"(a[1]), "r"(a[2]), "r"(a[3]), "r"(b[0]), "r"(b[1]));
}

extern __shared__ __align__(16) char dynsm[];

// ---------------- split + cat kernels ----------------
__global__ void split_kernel(const float* __restrict__ src,
                             bf16* __restrict__ H, bf16* __restrict__ L,
                             int n2) {
    int i = blockIdx.x * 256 + threadIdx.x;   // 2-element units
    if (i >= n2) return;
    float2 v = *(const float2*)(src + 2 * (size_t)i);
    bf16 h0, l0, h1, l1;
    split1(v.x, h0, l0); split1(v.y, h1, l1);
    bf162 vh; vh.x = h0; vh.y = h1;
    bf162 vl; vl.x = l0; vl.y = l1;
    *(bf162*)(H + 2 * (size_t)i) = vh;
    *(bf162*)(L + 2 * (size_t)i) = vl;
}

__global__ void build_cat_split(const float* __restrict__ inp,
                                const float* __restrict__ mem,
                                bf16* __restrict__ H, bf16* __restrict__ L) {
    int idx = blockIdx.x * 256 + threadIdx.x;     // float2 units
    int per_b = KL * (DM / 2);
    int b = idx / per_b;
    int rem = idx - b * per_b;
    int t = rem / (DM / 2);
    int c = rem - t * (DM / 2);
    const float2* s;
    if (t < MEML) s = (const float2*)(mem + ((size_t)b * MEML + t) * DM) + c;
    else          s = (const float2*)(inp + ((size_t)b * QL + (t - MEML)) * DM) + c;
    float2 v = *s;
    bf16 h0, l0, h1, l1;
    split1(v.x, h0, l0); split1(v.y, h1, l1);
    bf162 vh; vh.x = h0; vh.y = h1;
    bf162 vl; vl.x = l0; vl.y = l1;
    size_t o = ((size_t)b * KL + t) * DM + 2 * c;
    *(bf162*)(H + o) = vh;
    *(bf162*)(L + o) = vl;
}

// ---------------- plane GEMM ----------------
// C[M,N] = (AH+AL)[M,K] @ (BH+BL)[K,N], 3-term split, fp32 accum.
// BM=128, BN=NT, BK=32. A: [m][k] via cp.async. B: [k][n] global -> [n][k] smem.
// MODE 1: per-(b,h) weights@V with K clamp. COUT 1: write hi/lo planes.
#define ASTR2 40
#define APL2  (128 * ASTR2)
#define BSTR2 34

template <int NT, int MODE, int COUT>
__global__ __launch_bounds__(256)
void gemm_pl(const bf16* __restrict__ AH, const bf16* __restrict__ AL,
             const bf16* __restrict__ BH, const bf16* __restrict__ BL,
             float* __restrict__ C, bf16* __restrict__ CH, bf16* __restrict__ CL,
             int K, int lda, int ldb, int ldc) {
    constexpr int BPL2 = NT * BSTR2;
    constexpr int STG = 2 * APL2 + 2 * BPL2;
    constexpr int ITB = (NT == 128) ? 4 : 2;
    constexpr int NJ = NT / 16;
    int tid = threadIdx.x, lane = tid & 31, wid = tid >> 5;
    int wy = wid & 3, wx = wid >> 2;
    int m0 = blockIdx.y * 128, n0 = blockIdx.x * NT;

    if (MODE == 1) {
        int z = blockIdx.z, b = z >> 4, h = z & 15;
        AH += (size_t)z * QL * KL;  AL += (size_t)z * QL * KL;
        BH += (size_t)b * KL * D3 + (size_t)h * DK;
        BL += (size_t)b * KL * D3 + (size_t)h * DK;
        CH += (size_t)b * QL * DM + (size_t)h * DK;
        CL += (size_t)b * QL * DM + (size_t)h * DK;
    }
    const bf16* AbH = AH + (size_t)m0 * lda;
    const bf16* AbL = AL + (size_t)m0 * lda;
    const bf16* BbH = BH + n0;
    const bf16* BbL = BL + n0;

    int Klim = K;
    if (MODE == 1) { int km = m0 + 128 + MEML; Klim = K < km ? K : km; }
    int NC = Klim >> 5;

    bf16* sm = (bf16*)dynsm;
    uint2 pbh[ITB], pbl[ITB];

    auto loadA = [&](int k0, int s) {
        bf16* base = sm + s * STG;
        uint32_t dh = (uint32_t)__cvta_generic_to_shared(base);
        uint32_t dl = (uint32_t)__cvta_generic_to_shared(base + APL2);
#pragma unroll
        for (int it = 0; it < 2; it++) {
            int e = tid + it * 256;
            int row = e >> 2, ch = (e & 3) << 3;
            size_t src = (size_t)row * lda + k0 + ch;
            uint32_t doff = (uint32_t)(row * ASTR2 + ch) * 2;
            cp16(dh + doff, AbH + src);
            cp16(dl + doff, AbL + src);
        }
    };
    auto ldB = [&](int k0) {
#pragma unroll
        for (int i = 0; i < ITB; i++) {
            int e = tid + i * 256;
            int kk = e / (NT / 4), nq = (e % (NT / 4)) * 4;
            size_t src = (size_t)(k0 + kk) * ldb + nq;
            pbh[i] = *(const uint2*)(BbH + src);
            pbl[i] = *(const uint2*)(BbL + src);
        }
    };
    auto stB = [&](int s) {
        bf16* bh = sm + s * STG + 2 * APL2;
        bf16* bl = bh + BPL2;
#pragma unroll
        for (int i = 0; i < ITB; i++) {
            int e = tid + i * 256;
            int kk = e / (NT / 4), nq = (e % (NT / 4)) * 4;
            bf16 vh[4]; *(uint2*)vh = pbh[i];
            bf16 vl[4]; *(uint2*)vl = pbl[i];
#pragma unroll
            for (int t = 0; t < 4; t++) {
                bh[(nq + t) * BSTR2 + kk] = vh[t];
                bl[(nq + t) * BSTR2 + kk] = vl[t];
            }
        }
    };

    float acc[2][NJ][4];
#pragma unroll
    for (int mi = 0; mi < 2; mi++)
#pragma unroll
        for (int nj = 0; nj < NJ; nj++)
#pragma unroll
            for (int q = 0; q < 4; q++) acc[mi][nj][q] = 0.0f;

    loadA(0, 0); cp_commit();
    ldB(0); stB(0);
    cp_wait0();
    __syncthreads();

    for (int c = 0; c < NC; c++) {
        int s = c & 1;
        if (c + 1 < NC) {
            loadA((c + 1) << 5, s ^ 1); cp_commit();
            ldB((c + 1) << 5);
        }
        const bf16* st = sm + s * STG;
#pragma unroll
        for (int kk = 0; kk < 32; kk += 16) {
            uint32_t ah[2][4], al[2][4];
#pragma unroll
            for (int mi = 0; mi < 2; mi++) {
                int r = wy * 32 + mi * 16 + (lane >> 2);
                const bf16* p = st + r * ASTR2 + kk + ((lane & 3) << 1);
                ah[mi][0] = *(const uint32_t*)p;
                ah[mi][1] = *(const uint32_t*)(p + 8 * ASTR2);
                ah[mi][2] = *(const uint32_t*)(p + 8);
                ah[mi][3] = *(const uint32_t*)(p + 8 * ASTR2 + 8);
                const bf16* pl = p + APL2;
                al[mi][0] = *(const uint32_t*)pl;
                al[mi][1] = *(const uint32_t*)(pl + 8 * ASTR2);
                al[mi][2] = *(const uint32_t*)(pl + 8);
                al[mi][3] = *(const uint32_t*)(pl + 8 * ASTR2 + 8);
            }
#pragma unroll
            for (int nj = 0; nj < NJ; nj++) {
                int n = wx * (NT / 2) + nj * 8 + (lane >> 2);
                const bf16* pb = st + 2 * APL2 + n * BSTR2 + kk + ((lane & 3) << 1);
                uint32_t bh[2], bl[2];
                bh[0] = *(const uint32_t*)pb;
                bh[1] = *(const uint32_t*)(pb + 8);
                const bf16* pq = pb + BPL2;
                bl[0] = *(const uint32_t*)pq;
                bl[1] = *(const uint32_t*)(pq + 8);
#pragma unroll
                for (int mi = 0; mi < 2; mi++) {
                    mma16816(acc[mi][nj], ah[mi], bh);
                    mma16816(acc[mi][nj], ah[mi], bl);
                    mma16816(acc[mi][nj], al[mi], bh);
                }
            }
        }
        if (c + 1 < NC) {
            stB(s ^ 1);
            cp_wait0();
        }
        __syncthreads();
    }

#pragma unroll
    for (int mi = 0; mi < 2; mi++) {
#pragma unroll
        for (int nj = 0; nj < NJ; nj++) {
            int r = m0 + wy * 32 + mi * 16 + (lane >> 2);
            int ncol = n0 + wx * (NT / 2) + nj * 8 + ((lane & 3) << 1);
            if (COUT == 0) {
                *(float2*)&C[(size_t)r * ldc + ncol] =
                    make_float2(acc[mi][nj][0], acc[mi][nj][1]);
                *(float2*)&C[(size_t)(r + 8) * ldc + ncol] =
                    make_float2(acc[mi][nj][2], acc[mi][nj][3]);
            } else {
#pragma unroll
                for (int hh = 0; hh < 2; hh++) {
                    bf16 h0, l0, h1, l1;
                    split1(acc[mi][nj][2 * hh + 0], h0, l0);
                    split1(acc[mi][nj][2 * hh + 1], h1, l1);
                    bf162 vh; vh.x = h0; vh.y = h1;
                    bf162 vl; vl.x = l0; vl.y = l1;
                    size_t o = (size_t)(r + 8 * hh) * ldc + ncol;
                    *(bf162*)(CH + o) = vh;
                    *(bf162*)(CL + o) = vl;
                }
            }
        }
    }
}

// ---------------- score GEMMs (Q@K^T and Q@R^T), planes, 2 j-tiles/block ----
#define SSTR 72
#define SPL  (128 * SSTR)

template <int MODE>
__global__ __launch_bounds__(256)
void score_pl(const bf16* __restrict__ qH, const bf16* __restrict__ qL,
              const bf16* __restrict__ rH, const bf16* __restrict__ rL,
              float* __restrict__ Cout) {
    int bh = blockIdx.z, b = bh >> 4, h = bh & 15;
    int i0 = blockIdx.y * 128, j0 = blockIdx.x * 256;
    bool act[2];
    if (MODE == 0) {
        act[0] = (j0 - i0) < 1152;
        act[1] = (j0 + 128 - i0) < 1152;
        if (!act[0]) return;
    } else {
        act[0] = (i0 + j0) > 768;
        act[1] = (i0 + j0 + 128) > 768;
        if (!act[1]) return;
    }
    int tid = threadIdx.x, lane = tid & 31, wid = tid >> 5;
    int wy = wid & 3, wx = wid >> 2;

    bf16* sm = (bf16*)dynsm;
    // A: Q rows [i0..i0+128) x 64
    {
        const bf16* AbH = qH + (size_t)(b * KL + MEML + i0) * D3 + h * DK;
        const bf16* AbL = qL + (size_t)(b * KL + MEML + i0) * D3 + h * DK;
        uint32_t dh = (uint32_t)__cvta_generic_to_shared(sm);
        uint32_t dl = (uint32_t)__cvta_generic_to_shared(sm + SPL);
#pragma unroll
        for (int it = 0; it < 4; it++) {
            int e = tid + it * 256;
            int row = e >> 3, ch = (e & 7) << 3;
            size_t src = (size_t)row * D3 + ch;
            uint32_t doff = (uint32_t)(row * SSTR + ch) * 2;
            cp16(dh + doff, AbH + src);
            cp16(dl + doff, AbL + src);
        }
    }
#pragma unroll
    for (int jt = 0; jt < 2; jt++) {
        if (!act[jt]) continue;
        int j1 = j0 + jt * 128;
        const bf16 *BbH, *BbL;
        size_t ldrow;
        if (MODE == 0) {
            BbH = qH + (size_t)(b * KL + j1) * D3 + DM + h * DK;
            BbL = qL + (size_t)(b * KL + j1) * D3 + DM + h * DK;
            ldrow = D3;
        } else {
            BbH = rH + (size_t)j1 * DM + h * DK;
            BbL = rL + (size_t)j1 * DM + h * DK;
            ldrow = DM;
        }
        bf16* dsth = sm + (2 + 2 * jt) * SPL;
        uint32_t dh = (uint32_t)__cvta_generic_to_shared(dsth);
        uint32_t dl = (uint32_t)__cvta_generic_to_shared(dsth + SPL);
#pragma unroll
        for (int it = 0; it < 4; it++) {
            int e = tid + it * 256;
            int row = e >> 3, ch = (e & 7) << 3;
            size_t src = (size_t)row * ldrow + ch;
            uint32_t doff = (uint32_t)(row * SSTR + ch) * 2;
            cp16(dh + doff, BbH + src);
            cp16(dl + doff, BbL + src);
        }
    }
    cp_commit();
    cp_wait0();
    __syncthreads();

    float* Cb = Cout + (size_t)bh * QL * KL;
#pragma unroll
    for (int jt = 0; jt < 2; jt++) {
        if (!act[jt]) continue;
        const bf16* smB = sm + (2 + 2 * jt) * SPL;
        float acc[2][8][4];
#pragma unroll
        for (int mi = 0; mi < 2; mi++)
#pragma unroll
            for (int nj = 0; nj < 8; nj++)
#pragma unroll
                for (int q = 0; q < 4; q++) acc[mi][nj][q] = 0.0f;
#pragma unroll
        for (int kk = 0; kk < 64; kk += 16) {
            uint32_t ah[2][4], al[2][4];
#pragma unroll
            for (int mi = 0; mi < 2; mi++) {
                int r = wy * 32 + mi * 16 + (lane >> 2);
                const bf16* p = sm + r * SSTR + kk + ((lane & 3) << 1);
                ah[mi][0] = *(const uint32_t*)p;
                ah[mi][1] = *(const uint32_t*)(p + 8 * SSTR);
                ah[mi][2] = *(const uint32_t*)(p + 8);
                ah[mi][3] = *(const uint32_t*)(p + 8 * SSTR + 8);
                const bf16* pl = p + SPL;
                al[mi][0] = *(const uint32_t*)pl;
                al[mi][1] = *(const uint32_t*)(pl + 8 * SSTR);
                al[mi][2] = *(const uint32_t*)(pl + 8);
                al[mi][3] = *(const uint32_t*)(pl + 8 * SSTR + 8);
            }
#pragma unroll
            for (int nj = 0; nj < 8; nj++) {
                int n = wx * 64 + nj * 8 + (lane >> 2);
                const bf16* pb = smB + n * SSTR + kk + ((lane & 3) << 1);
                uint32_t bhf[2], blf[2];
                bhf[0] = *(const uint32_t*)pb;
                bhf[1] = *(const uint32_t*)(pb + 8);
                const bf16* pq = pb + SPL;
                blf[0] = *(const uint32_t*)pq;
                blf[1] = *(const uint32_t*)(pq + 8);
#pragma unroll
                for (int mi = 0; mi < 2; mi++) {
                    mma16816(acc[mi][nj], ah[mi], bhf);
                    mma16816(acc[mi][nj], ah[mi], blf);
                    mma16816(acc[mi][nj], al[mi], bhf);
                }
            }
        }
        int j1 = j0 + jt * 128;
#pragma unroll
        for (int mi = 0; mi < 2; mi++) {
#pragma unroll
            for (int nj = 0; nj < 8; nj++) {
                int r = i0 + wy * 32 + mi * 16 + (lane >> 2);
                int ncol = j1 + wx * 64 + nj * 8 + ((lane & 3) << 1);
                *(float2*)&Cb[(size_t)r * KL + ncol] =
                    make_float2(acc[mi][nj][0], acc[mi][nj][1]);
                *(float2*)&Cb[(size_t)(r + 8) * KL + ncol] =
                    make_float2(acc[mi][nj][2], acc[mi][nj][3]);
            }
        }
    }
}

// ---------------- bias kernels: u.K and v.R ----------------
__global__ void bias_u_kernel(const bf16* __restrict__ kH,
                              const bf16* __restrict__ kL,
                              const float* __restrict__ u,
                              float* __restrict__ bU) {
    int idx = blockIdx.x * 256 + threadIdx.x;      // 65536
    int bh = idx >> 11, j = idx & 2047;
    int b = bh >> 4, h = bh & 15;
    const bf16* ph = kH + (size_t)(b * KL + j) * D3 + DM + h * DK;
    const bf16* pl = kL + (size_t)(b * KL + j) * D3 + DM + h * DK;
    const float* uu = u + h * DK;
    float s = 0.0f;
#pragma unroll
    for (int d = 0; d < DK; d++)
        s += (__bfloat162float(ph[d]) + __bfloat162float(pl[d])) * uu[d];
    bU[idx] = s;
}
__global__ void bias_v_kernel(const bf16* __restrict__ rpH,
                              const bf16* __restrict__ rpL,
                              const float* __restrict__ v,
                              float* __restrict__ bV) {
    int idx = blockIdx.x * 256 + threadIdx.x;      // 32768
    int h = idx >> 11, p = idx & 2047;
    const bf16* ph = rpH + (size_t)p * DM + h * DK;
    const bf16* pl = rpL + (size_t)p * DM + h * DK;
    const float* vv = v + h * DK;
    float s = 0.0f;
#pragma unroll
    for (int d = 0; d < DK; d++)
        s += (__bfloat162float(ph[d]) + __bfloat162float(pl[d])) * vv[d];
    bV[idx] = s;
}

// ---------------- fused shift+bias+mask+softmax -> weight planes ------------
__global__ __launch_bounds__(256)
void fused_softmax2(const float* __restrict__ AC, const float* __restrict__ U,
                    const float* __restrict__ bU, const float* __restrict__ bV,
                    bf16* __restrict__ WH, bf16* __restrict__ WL) {
    int rid = blockIdx.x;
    int bh = rid >> 10, h = bh & 15, i = rid & 1023;
    const float* p = AC + (size_t)rid * KL;
    const float* q = U + (size_t)rid * KL + (QL - 1 - i);
    const float* bu = bU + bh * KL;
    const float* bv = bV + h * KL + (QL - 1 - i);
    int jmax = i + MEML;
    int tile_end = (i & ~127) + 128 + MEML;
    int tid = threadIdx.x;
    __shared__ float red[256];
    float x[8];
    float mx = -INFINITY;
#pragma unroll
    for (int t = 0; t < 8; t++) {
        int j = tid + t * 256;
        if (j <= jmax) {
            x[t] = (p[j] + bu[j] + q[j] + bv[j]) * 0.125f;
            mx = fmaxf(mx, x[t]);
        } else {
            x[t] = -INFINITY;
        }
    }
    red[tid] = mx;
    __syncthreads();
    for (int s = 128; s > 0; s >>= 1) {
        if (tid < s) red[tid] = fmaxf(red[tid], red[tid + s]);
        __syncthreads();
    }
    mx = red[0];
    __syncthreads();
    float sum = 0.0f;
#pragma unroll
    for (int t = 0; t < 8; t++) {
        x[t] = expf(x[t] - mx);
        sum += x[t];
    }
    red[tid] = sum;
    __syncthreads();
    for (int s = 128; s > 0; s >>= 1) {
        if (tid < s) red[tid] += red[tid + s];
        __syncthreads();
    }
    float inv = 1.0f / red[0];
    size_t base = (size_t)rid * KL;
#pragma unroll
    for (int t = 0; t < 8; t++) {
        int j = tid + t * 256;
        if (j < tile_end) {
            float w = x[t] * inv;
            bf16 hh, ll;
            split1(w, hh, ll);
            WH[base + j] = hh;
            WL[base + j] = ll;
        }
    }
}

// ---------------------------------------------------------------------------
extern "C" void kernel_launch(void* const* d_in, const int* in_sizes, int n_in,
                              void* d_out, int out_size) {
    const float* inputs     = (const float*)d_in[0];
    const float* inputs_mem = (const float*)d_in[1];
    const float* r          = (const float*)d_in[2];
    const float* W          = (const float*)d_in[3];
    const float* W_r        = (const float*)d_in[4];
    const float* W_o        = (const float*)d_in[5];
    const float* u          = (const float*)d_in[6];
    const float* v          = (const float*)d_in[7];
    float* out = (float*)d_out;

    bf16 *catH, *catL, *WH, *WL, *WrH, *WrL, *WoH, *WoL, *rsH, *rsL;
    bf16 *qkvH, *qkvL, *rpH, *rpL, *attnH, *attnL, *wtH, *wtL;
    float *scores, *bdu, *biasU, *biasV;
    cudaGetSymbolAddress((void**)&catH, g_catH);  cudaGetSymbolAddress((void**)&catL, g_catL);
    cudaGetSymbolAddress((void**)&WH, g_WH);      cudaGetSymbolAddress((void**)&WL, g_WL);
    cudaGetSymbolAddress((void**)&WrH, g_WrH);    cudaGetSymbolAddress((void**)&WrL, g_WrL);
    cudaGetSymbolAddress((void**)&WoH, g_WoH);    cudaGetSymbolAddress((void**)&WoL, g_WoL);
    cudaGetSymbolAddress((void**)&rsH, g_rsH);    cudaGetSymbolAddress((void**)&rsL, g_rsL);
    cudaGetSymbolAddress((void**)&qkvH, g_qkvH);  cudaGetSymbolAddress((void**)&qkvL, g_qkvL);
    cudaGetSymbolAddress((void**)&rpH, g_rpH);    cudaGetSymbolAddress((void**)&rpL, g_rpL);
    cudaGetSymbolAddress((void**)&attnH, g_attnH);cudaGetSymbolAddress((void**)&attnL, g_attnL);
    cudaGetSymbolAddress((void**)&wtH, g_wtH);    cudaGetSymbolAddress((void**)&wtL, g_wtL);
    cudaGetSymbolAddress((void**)&scores, g_scores);
    cudaGetSymbolAddress((void**)&bdu, g_bdu);
    cudaGetSymbolAddress((void**)&biasU, g_biasU);
    cudaGetSymbolAddress((void**)&biasV, g_biasV);

    const int SM128 = (2 * APL2 + 2 * 128 * BSTR2) * 2 * 2;  // 75776
    const int SM64  = (2 * APL2 + 2 * 64 * BSTR2) * 2 * 2;   // 58368
    const int SMSC  = 6 * SPL * 2;                            // 110592
    cudaFuncSetAttribute(gemm_pl<128, 0, 1>, cudaFuncAttributeMaxDynamicSharedMemorySize, SM128);
    cudaFuncSetAttribute(gemm_pl<128, 0, 0>, cudaFuncAttributeMaxDynamicSharedMemorySize, SM128);
    cudaFuncSetAttribute(gemm_pl<64, 1, 1>,  cudaFuncAttributeMaxDynamicSharedMemorySize, SM64);
    cudaFuncSetAttribute(score_pl<0>, cudaFuncAttributeMaxDynamicSharedMemorySize, SMSC);
    cudaFuncSetAttribute(score_pl<1>, cudaFuncAttributeMaxDynamicSharedMemorySize, SMSC);

    // 0. split weights + r, build cat planes
    split_kernel<<<(DM * D3 / 2 + 255) / 256, 256>>>(W, WH, WL, DM * D3 / 2);
    split_kernel<<<(DM * DM / 2 + 255) / 256, 256>>>(W_r, WrH, WrL, DM * DM / 2);
    split_kernel<<<(DM * DM / 2 + 255) / 256, 256>>>(W_o, WoH, WoL, DM * DM / 2);
    split_kernel<<<(KL * DM / 2 + 255) / 256, 256>>>(r, rsH, rsL, KL * DM / 2);
    build_cat_split<<<BB * KL * DM / 2 / 256, 256>>>(inputs, inputs_mem, catH, catL);
    // 1. qkv = cat @ W  -> planes
    gemm_pl<128, 0, 1><<<dim3(D3 / 128, BB * KL / 128), 256, SM128>>>(
        catH, catL, WH, WL, nullptr, qkvH, qkvL, DM, DM, D3, D3);
    // 2. rproj = r @ W_r -> planes
    gemm_pl<128, 0, 1><<<dim3(DM / 128, KL / 128), 256, SM128>>>(
        rsH, rsL, WrH, WrL, nullptr, rpH, rpL, DM, DM, DM, DM);
    // 3. biases
    bias_u_kernel<<<BB * NH * KL / 256, 256>>>(qkvH, qkvL, u, biasU);
    bias_v_kernel<<<NH * KL / 256, 256>>>(rpH, rpL, v, biasV);
    // 4. AC = Q @ K^T ; Ubd = Q @ R^T
    score_pl<0><<<dim3(KL / 256, QL / 128, BB * NH), 256, SMSC>>>(
        qkvH, qkvL, rpH, rpL, scores);
    score_pl<1><<<dim3(KL / 256, QL / 128, BB * NH), 256, SMSC>>>(
        qkvH, qkvL, rpH, rpL, bdu);
    // 5. fused shift+bias+mask+softmax -> weight planes
    fused_softmax2<<<BB * NH * QL, 256>>>(scores, bdu, biasU, biasV, wtH, wtL);
    // 6. attn = weights @ V -> planes  (K clamped past mask)
    gemm_pl<64, 1, 1><<<dim3(1, QL / 128, BB * NH), 256, SM64>>>(
        wtH, wtL, qkvH + 2 * DM, qkvL + 2 * DM, nullptr, attnH, attnL,
        KL, KL, D3, DM);
    // 7. out = attn @ W_o (fp32)
    gemm_pl<128, 0, 0><<<dim3(DM / 128, BB * QL / 128), 256, SM128>>>(
        attnH, attnL, WoH, WoL, out, nullptr, nullptr, DM, DM, DM, DM);
}

// round 7
// speedup vs baseline: 1.9882x; 1.0624x over previous
#include <cuda_runtime.h>
#include <cuda_fp16.h>
#include <math.h>
#include <stdint.h>

#define BB    2
#define QL    1024
#define MEML  1024
#define KL    2048
#define DM    1024
#define NH    16
#define DK    64
#define D3    3072

typedef __half  f16;
typedef __half2 f162;

// ---------------- scratch (device globals, no allocation) ----------------
__device__ f16 g_catH[BB * KL * DM], g_catL[BB * KL * DM];
__device__ f16 g_W1[DM * D3];
__device__ f16 g_Wr1[DM * DM];
__device__ f16 g_Wo1[DM * DM];
__device__ f16 g_rsH[KL * DM], g_rsL[KL * DM];
__device__ f16 g_qkvH[BB * KL * D3], g_qkvL[BB * KL * D3];
__device__ f16 g_rpH[KL * DM], g_rpL[KL * DM];
__device__ f16 g_attnH[BB * QL * DM], g_attnL[BB * QL * DM];
__device__ f16 g_scores[(size_t)BB * NH * QL * KL];   // AC * 0.125, fp16
__device__ f16 g_bdu[(size_t)BB * NH * QL * KL];      // Q@R^T * 0.125, fp16
__device__ f16 g_wt[(size_t)BB * NH * QL * KL];       // softmax weights, fp16
__device__ float g_biasU[BB * NH * KL];
__device__ float g_biasV[NH * KL];

// ---------------- helpers ----------------
__device__ __forceinline__ void split1(float x, f16& h, f16& l) {
    h = __float2half_rn(x);
    l = __float2half_rn(x - __half2float(h));
}
__device__ __forceinline__ void cp16(uint32_t dst, const void* src) {
    asm volatile("cp.async.cg.shared.global [%0], [%1], 16;\n" :: "r"(dst), "l"(src));
}
__device__ __forceinline__ void cp_commit() {
    asm volatile("cp.async.commit_group;\n");
}
__device__ __forceinline__ void cp_wait0() {
    asm volatile("cp.async.wait_group 0;\n");
}
__device__ __forceinline__ void mmaf16(float* d, const uint32_t* a,
                                       const uint32_t* b) {
    asm volatile(
        "mma.sync.aligned.m16n8k16.row.col.f32.f16.f16.f32 "
        "{%0,%1,%2,%3}, {%4,%5,%6,%7}, {%8,%9}, {%0,%1,%2,%3};"
        : "+f"(d[0]), "+f"(d[1]), "+f"(d[2]), "+f"(d[3])
        : "r"(a[0]), "r"(a[1]), "r"(a[2]), "r"(a[3]), "r"(b[0]), "r"(b[1]));
}
#define LDSM4(R, addr)                                                        \
    asm volatile("ldmatrix.sync.aligned.m8n8.x4.shared.b16 {%0,%1,%2,%3}, [%4];" \
                 : "=r"((R)[0]), "=r"((R)[1]), "=r"((R)[2]), "=r"((R)[3])     \
                 : "r"(addr))

extern __shared__ __align__(16) char dynsm[];

// ---------------- ingest kernels ----------------
__global__ void split_single(const float* __restrict__ src,
                             f16* __restrict__ H, int n2) {
    int i = blockIdx.x * 256 + threadIdx.x;
    if (i >= n2) return;
    float2 v = *(const float2*)(src + 2 * (size_t)i);
    *(f162*)(H + 2 * (size_t)i) = __floats2half2_rn(v.x, v.y);
}
__global__ void split_pair(const float* __restrict__ src,
                           f16* __restrict__ H, f16* __restrict__ L, int n2) {
    int i = blockIdx.x * 256 + threadIdx.x;
    if (i >= n2) return;
    float2 v = *(const float2*)(src + 2 * (size_t)i);
    f16 h0, l0, h1, l1;
    split1(v.x, h0, l0); split1(v.y, h1, l1);
    f162 vh; vh.x = h0; vh.y = h1;
    f162 vl; vl.x = l0; vl.y = l1;
    *(f162*)(H + 2 * (size_t)i) = vh;
    *(f162*)(L + 2 * (size_t)i) = vl;
}
__global__ void build_cat_split(const float* __restrict__ inp,
                                const float* __restrict__ mem,
                                f16* __restrict__ H, f16* __restrict__ L) {
    int idx = blockIdx.x * 256 + threadIdx.x;
    int per_b = KL * (DM / 2);
    int b = idx / per_b;
    int rem = idx - b * per_b;
    int t = rem / (DM / 2);
    int c = rem - t * (DM / 2);
    const float2* s;
    if (t < MEML) s = (const float2*)(mem + ((size_t)b * MEML + t) * DM) + c;
    else          s = (const float2*)(inp + ((size_t)b * QL + (t - MEML)) * DM) + c;
    float2 v = *s;
    f16 h0, l0, h1, l1;
    split1(v.x, h0, l0); split1(v.y, h1, l1);
    f162 vh; vh.x = h0; vh.y = h1;
    f162 vl; vl.x = l0; vl.y = l1;
    size_t o = ((size_t)b * KL + t) * DM + 2 * c;
    *(f162*)(H + o) = vh;
    *(f162*)(L + o) = vl;
}

// ---------------- unified fp16 GEMM ----------------
// C = A @ B. A [m][k] (split if ASPL), B [k][n] global -> [n][k] smem
// (split if BSPL). 2-term: C = Ah.B + Al.B (ASPL) or A.Bh + A.Bl (BSPL).
// BM=128, BN=NT, BK=32, 256 thr (8 warps 4x2).
// MODE 1: per-(b,h) weights@V, K clamped. COUT 0: fp32 C. COUT 1: planes.
#define ASTR2 40
#define APL2  (128 * ASTR2)
#define BSTR2 40                     // 80 B rows: 16B-aligned for ldmatrix

template <int NT, int ASPL, int BSPL, int MODE, int COUT>
__global__ __launch_bounds__(256)
void gemm_f16(const f16* __restrict__ AH, const f16* __restrict__ AL,
              const f16* __restrict__ BH, const f16* __restrict__ BL,
              float* __restrict__ C, f16* __restrict__ CH, f16* __restrict__ CL,
              int K, int lda, int ldb, int ldc) {
    constexpr int BPL2 = NT * BSTR2;
    constexpr int ANP = ASPL ? 2 : 1;
    constexpr int BNP = BSPL ? 2 : 1;
    constexpr int STG = ANP * APL2 + BNP * BPL2;
    constexpr int ITB = (NT == 128) ? 4 : 2;
    constexpr int NJ = NT / 16;
    int tid = threadIdx.x, lane = tid & 31, wid = tid >> 5;
    int wy = wid & 3, wx = wid >> 2;
    int m0 = blockIdx.y * 128, n0 = blockIdx.x * NT;

    if (MODE == 1) {
        int z = blockIdx.z, b = z >> 4, h = z & 15;
        AH += (size_t)z * QL * KL;
        BH += (size_t)b * KL * D3 + (size_t)h * DK;
        BL += (size_t)b * KL * D3 + (size_t)h * DK;
        CH += (size_t)b * QL * DM + (size_t)h * DK;
        CL += (size_t)b * QL * DM + (size_t)h * DK;
    }
    const f16* AbH = AH + (size_t)m0 * lda;
    const f16* AbL = ASPL ? (AL + (size_t)m0 * lda) : nullptr;
    const f16* BbH = BH + n0;
    const f16* BbL = BSPL ? (BL + n0) : nullptr;

    int Klim = K;
    if (MODE == 1) { int km = m0 + 128 + MEML; Klim = K < km ? K : km; }
    int NC = Klim >> 5;

    f16* sm = (f16*)dynsm;
    uint2 pbh[ITB], pbl[ITB];

    auto loadA = [&](int k0, int s) {
        f16* base = sm + s * STG;
        uint32_t dh = (uint32_t)__cvta_generic_to_shared(base);
#pragma unroll
        for (int it = 0; it < 2; it++) {
            int e = tid + it * 256;
            int row = e >> 2, ch = (e & 3) << 3;
            size_t src = (size_t)row * lda + k0 + ch;
            uint32_t doff = (uint32_t)(row * ASTR2 + ch) * 2;
            cp16(dh + doff, AbH + src);
            if (ASPL) cp16(dh + APL2 * 2 + doff, AbL + src);
        }
    };
    auto ldB = [&](int k0) {
#pragma unroll
        for (int i = 0; i < ITB; i++) {
            int e = tid + i * 256;
            int kk = e / (NT / 4), nq = (e % (NT / 4)) * 4;
            size_t src = (size_t)(k0 + kk) * ldb + nq;
            pbh[i] = *(const uint2*)(BbH + src);
            if (BSPL) pbl[i] = *(const uint2*)(BbL + src);
        }
    };
    auto stB = [&](int s) {
        f16* bh = sm + s * STG + ANP * APL2;
#pragma unroll
        for (int i = 0; i < ITB; i++) {
            int e = tid + i * 256;
            int kk = e / (NT / 4), nq = (e % (NT / 4)) * 4;
            f16 vh[4]; *(uint2*)vh = pbh[i];
#pragma unroll
            for (int t = 0; t < 4; t++) bh[(nq + t) * BSTR2 + kk] = vh[t];
            if (BSPL) {
                f16 vl[4]; *(uint2*)vl = pbl[i];
#pragma unroll
                for (int t = 0; t < 4; t++)
                    bh[BPL2 + (nq + t) * BSTR2 + kk] = vl[t];
            }
        }
    };

    float acc[2][NJ][4];
#pragma unroll
    for (int mi = 0; mi < 2; mi++)
#pragma unroll
        for (int nj = 0; nj < NJ; nj++)
#pragma unroll
            for (int q = 0; q < 4; q++) acc[mi][nj][q] = 0.0f;

    loadA(0, 0); cp_commit();
    ldB(0); stB(0);
    cp_wait0();
    __syncthreads();

    // ldmatrix lane addressing
    int arow = (lane & 15);
    int acol = (lane & 16) >> 1;          // 0 or 8
    int brow = (lane & 7) + ((lane & 16) >> 1);
    int bcol = (lane & 8);

    for (int c = 0; c < NC; c++) {
        int s = c & 1;
        if (c + 1 < NC) {
            loadA((c + 1) << 5, s ^ 1); cp_commit();
            ldB((c + 1) << 5);
        }
        const f16* st = sm + s * STG;
        uint32_t sa = (uint32_t)__cvta_generic_to_shared(st);
        uint32_t sb = sa + ANP * APL2 * 2;
#pragma unroll
        for (int kk = 0; kk < 32; kk += 16) {
            uint32_t ah[2][4], al[2][4];
#pragma unroll
            for (int mi = 0; mi < 2; mi++) {
                int r = wy * 32 + mi * 16 + arow;
                uint32_t ad = sa + (uint32_t)(r * ASTR2 + kk + acol) * 2;
                LDSM4(ah[mi], ad);
                if (ASPL) LDSM4(al[mi], ad + APL2 * 2);
            }
#pragma unroll
            for (int njp = 0; njp < NJ / 2; njp++) {
                int n = wx * (NT / 2) + njp * 16 + brow;
                uint32_t bd = sb + (uint32_t)(n * BSTR2 + kk + bcol) * 2;
                uint32_t bf[4], blf[4];
                LDSM4(bf, bd);
                if (BSPL) LDSM4(blf, bd + BPL2 * 2);
#pragma unroll
                for (int mi = 0; mi < 2; mi++) {
                    mmaf16(acc[mi][2 * njp + 0], ah[mi], bf + 0);
                    mmaf16(acc[mi][2 * njp + 1], ah[mi], bf + 2);
                    if (ASPL) {
                        mmaf16(acc[mi][2 * njp + 0], al[mi], bf + 0);
                        mmaf16(acc[mi][2 * njp + 1], al[mi], bf + 2);
                    }
                    if (BSPL) {
                        mmaf16(acc[mi][2 * njp + 0], ah[mi], blf + 0);
                        mmaf16(acc[mi][2 * njp + 1], ah[mi], blf + 2);
                    }
                }
            }
        }
        if (c + 1 < NC) { stB(s ^ 1); cp_wait0(); }
        __syncthreads();
    }

#pragma unroll
    for (int mi = 0; mi < 2; mi++) {
#pragma unroll
        for (int nj = 0; nj < NJ; nj++) {
            int r = m0 + wy * 32 + mi * 16 + (lane >> 2);
            int ncol = n0 + wx * (NT / 2) + nj * 8 + ((lane & 3) << 1);
            if (COUT == 0) {
                *(float2*)&C[(size_t)r * ldc + ncol] =
                    make_float2(acc[mi][nj][0], acc[mi][nj][1]);
                *(float2*)&C[(size_t)(r + 8) * ldc + ncol] =
                    make_float2(acc[mi][nj][2], acc[mi][nj][3]);
            } else {
#pragma unroll
                for (int hh = 0; hh < 2; hh++) {
                    f16 h0, l0, h1, l1;
                    split1(acc[mi][nj][2 * hh + 0], h0, l0);
                    split1(acc[mi][nj][2 * hh + 1], h1, l1);
                    f162 vh; vh.x = h0; vh.y = h1;
                    f162 vl; vl.x = l0; vl.y = l1;
                    size_t o = (size_t)(r + 8 * hh) * ldc + ncol;
                    *(f162*)(CH + o) = vh;
                    *(f162*)(CL + o) = vl;
                }
            }
        }
    }
}

// ---------------- score GEMMs: out = (Q @ B^T) * 0.125 in fp16 --------------
#define SSTR 72
#define SPL  (128 * SSTR)

template <int MODE>
__global__ __launch_bounds__(256)
void score_f16(const f16* __restrict__ qH, const f16* __restrict__ qL,
               const f16* __restrict__ rp, f16* __restrict__ Cout) {
    int bh = blockIdx.z, b = bh >> 4, h = bh & 15;
    int i0 = blockIdx.y * 128, j0 = blockIdx.x * 256;
    bool act[2];
    if (MODE == 0) {
        act[0] = (j0 - i0) < 1152;
        act[1] = (j0 + 128 - i0) < 1152;
        if (!act[0]) return;
    } else {
        act[0] = (i0 + j0) > 768;
        act[1] = (i0 + j0 + 128) > 768;
        if (!act[1]) return;
    }
    int tid = threadIdx.x, lane = tid & 31, wid = tid >> 5;
    int wy = wid & 3, wx = wid >> 2;

    f16* sm = (f16*)dynsm;
    // A: Q rows [i0, i0+128) x 64, hi+lo planes
    {
        const f16* AbH = qH + (size_t)(b * KL + MEML + i0) * D3 + h * DK;
        const f16* AbL = qL + (size_t)(b * KL + MEML + i0) * D3 + h * DK;
        uint32_t dh = (uint32_t)__cvta_generic_to_shared(sm);
#pragma unroll
        for (int it = 0; it < 4; it++) {
            int e = tid + it * 256;
            int row = e >> 3, ch = (e & 7) << 3;
            size_t src = (size_t)row * D3 + ch;
            uint32_t doff = (uint32_t)(row * SSTR + ch) * 2;
            cp16(dh + doff, AbH + src);
            cp16(dh + SPL * 2 + doff, AbL + src);
        }
    }
#pragma unroll
    for (int jt = 0; jt < 2; jt++) {
        if (!act[jt]) continue;
        int j1 = j0 + jt * 128;
        const f16* Bb;
        size_t ldrow;
        if (MODE == 0) { Bb = qH + (size_t)(b * KL + j1) * D3 + DM + h * DK; ldrow = D3; }
        else           { Bb = rp + (size_t)j1 * DM + h * DK; ldrow = DM; }
        uint32_t dh = (uint32_t)__cvta_generic_to_shared(sm + (2 + jt) * SPL);
#pragma unroll
        for (int it = 0; it < 4; it++) {
            int e = tid + it * 256;
            int row = e >> 3, ch = (e & 7) << 3;
            cp16(dh + (uint32_t)(row * SSTR + ch) * 2, Bb + (size_t)row * ldrow + ch);
        }
    }
    cp_commit();
    cp_wait0();
    __syncthreads();

    int arow = (lane & 15);
    int acol = (lane & 16) >> 1;
    int brow = (lane & 7) + ((lane & 16) >> 1);
    int bcol = (lane & 8);
    uint32_t sa = (uint32_t)__cvta_generic_to_shared(sm);

    f16* Cb = Cout + (size_t)bh * QL * KL;
#pragma unroll
    for (int jt = 0; jt < 2; jt++) {
        if (!act[jt]) continue;
        uint32_t sb = sa + (2 + jt) * SPL * 2;
        float acc[2][8][4];
#pragma unroll
        for (int mi = 0; mi < 2; mi++)
#pragma unroll
            for (int nj = 0; nj < 8; nj++)
#pragma unroll
                for (int q = 0; q < 4; q++) acc[mi][nj][q] = 0.0f;
#pragma unroll
        for (int kk = 0; kk < 64; kk += 16) {
            uint32_t ah[2][4], al[2][4];
#pragma unroll
            for (int mi = 0; mi < 2; mi++) {
                int r = wy * 32 + mi * 16 + arow;
                uint32_t ad = sa + (uint32_t)(r * SSTR + kk + acol) * 2;
                LDSM4(ah[mi], ad);
                LDSM4(al[mi], ad + SPL * 2);
            }
#pragma unroll
            for (int njp = 0; njp < 4; njp++) {
                int n = wx * 64 + njp * 16 + brow;
                uint32_t bd = sb + (uint32_t)(n * SSTR + kk + bcol) * 2;
                uint32_t bf[4];
                LDSM4(bf, bd);
#pragma unroll
                for (int mi = 0; mi < 2; mi++) {
                    mmaf16(acc[mi][2 * njp + 0], ah[mi], bf + 0);
                    mmaf16(acc[mi][2 * njp + 1], ah[mi], bf + 2);
                    mmaf16(acc[mi][2 * njp + 0], al[mi], bf + 0);
                    mmaf16(acc[mi][2 * njp + 1], al[mi], bf + 2);
                }
            }
        }
        int j1 = j0 + jt * 128;
#pragma unroll
        for (int mi = 0; mi < 2; mi++) {
#pragma unroll
            for (int nj = 0; nj < 8; nj++) {
                int r = i0 + wy * 32 + mi * 16 + (lane >> 2);
                int ncol = j1 + wx * 64 + nj * 8 + ((lane & 3) << 1);
                *(f162*)&Cb[(size_t)r * KL + ncol] =
                    __floats2half2_rn(acc[mi][nj][0] * 0.125f,
                                      acc[mi][nj][1] * 0.125f);
                *(f162*)&Cb[(size_t)(r + 8) * KL + ncol] =
                    __floats2half2_rn(acc[mi][nj][2] * 0.125f,
                                      acc[mi][nj][3] * 0.125f);
            }
        }
    }
}

// ---------------- bias kernels (pre-scaled by 0.125) ----------------
__global__ void bias_u_kernel(const f16* __restrict__ kH,
                              const f16* __restrict__ kL,
                              const float* __restrict__ u,
                              float* __restrict__ bU) {
    int idx = blockIdx.x * 256 + threadIdx.x;
    int bh = idx >> 11, j = idx & 2047;
    int b = bh >> 4, h = bh & 15;
    const f16* ph = kH + (size_t)(b * KL + j) * D3 + DM + h * DK;
    const f16* pl = kL + (size_t)(b * KL + j) * D3 + DM + h * DK;
    const float* uu = u + h * DK;
    float s = 0.0f;
#pragma unroll
    for (int d = 0; d < DK; d++)
        s += (__half2float(ph[d]) + __half2float(pl[d])) * uu[d];
    bU[idx] = s * 0.125f;
}
__global__ void bias_v_kernel(const f16* __restrict__ rpH,
                              const f16* __restrict__ rpL,
                              const float* __restrict__ v,
                              float* __restrict__ bV) {
    int idx = blockIdx.x * 256 + threadIdx.x;
    int h = idx >> 11, p = idx & 2047;
    const f16* ph = rpH + (size_t)p * DM + h * DK;
    const f16* pl = rpL + (size_t)p * DM + h * DK;
    const float* vv = v + h * DK;
    float s = 0.0f;
#pragma unroll
    for (int d = 0; d < DK; d++)
        s += (__half2float(ph[d]) + __half2float(pl[d])) * vv[d];
    bV[idx] = s * 0.125f;
}

// ---------------- fused shift+bias+mask+softmax -> fp16 weights -------------
__global__ __launch_bounds__(256)
void fused_softmax3(const f16* __restrict__ AC, const f16* __restrict__ U,
                    const float* __restrict__ bU, const float* __restrict__ bV,
                    f16* __restrict__ WT) {
    int rid = blockIdx.x;
    int bh = rid >> 10, h = bh & 15, i = rid & 1023;
    const f16* p = AC + (size_t)rid * KL;
    const f16* q = U + (size_t)rid * KL + (QL - 1 - i);
    const float* bu = bU + bh * KL;
    const float* bv = bV + h * KL + (QL - 1 - i);
    int jmax = i + MEML;
    int tile_end = (i & ~127) + 128 + MEML;
    int tid = threadIdx.x;
    __shared__ float red[256];
    float x[8];
    float mx = -INFINITY;
#pragma unroll
    for (int t = 0; t < 4; t++) {
        int j2 = tid + t * 256;      // pair index
        int j = 2 * j2;
        f162 pv = *(const f162*)(p + j);
        float2 buv = *(const float2*)(bu + j);
        float q0 = __half2float(q[j]), q1 = __half2float(q[j + 1]);
        float x0 = __half2float(pv.x) + buv.x + q0 + bv[j];
        float x1 = __half2float(pv.y) + buv.y + q1 + bv[j + 1];
        x[2 * t + 0] = (j     <= jmax) ? x0 : -INFINITY;
        x[2 * t + 1] = (j + 1 <= jmax) ? x1 : -INFINITY;
        mx = fmaxf(mx, fmaxf(x[2 * t], x[2 * t + 1]));
    }
    red[tid] = mx;
    __syncthreads();
    for (int s = 128; s > 0; s >>= 1) {
        if (tid < s) red[tid] = fmaxf(red[tid], red[tid + s]);
        __syncthreads();
    }
    mx = red[0];
    __syncthreads();
    float sum = 0.0f;
#pragma unroll
    for (int t = 0; t < 8; t++) {
        x[t] = __expf(x[t] - mx);
        sum += x[t];
    }
    red[tid] = sum;
    __syncthreads();
    for (int s = 128; s > 0; s >>= 1) {
        if (tid < s) red[tid] += red[tid + s];
        __syncthreads();
    }
    float inv = 1.0f / red[0];
    f16* w = WT + (size_t)rid * KL;
#pragma unroll
    for (int t = 0; t < 4; t++) {
        int j2 = tid + t * 256;
        int j = 2 * j2;
        if (j < tile_end)
            *(f162*)(w + j) = __floats2half2_rn(x[2 * t] * inv, x[2 * t + 1] * inv);
    }
}

// ---------------------------------------------------------------------------
extern "C" void kernel_launch(void* const* d_in, const int* in_sizes, int n_in,
                              void* d_out, int out_size) {
    const float* inputs     = (const float*)d_in[0];
    const float* inputs_mem = (const float*)d_in[1];
    const float* r          = (const float*)d_in[2];
    const float* W          = (const float*)d_in[3];
    const float* W_r        = (const float*)d_in[4];
    const float* W_o        = (const float*)d_in[5];
    const float* u          = (const float*)d_in[6];
    const float* v          = (const float*)d_in[7];
    float* out = (float*)d_out;

    f16 *catH, *catL, *W1, *Wr1, *Wo1, *rsH, *rsL;
    f16 *qkvH, *qkvL, *rpH, *rpL, *attnH, *attnL, *wt, *scores, *bdu;
    float *biasU, *biasV;
    cudaGetSymbolAddress((void**)&catH, g_catH);  cudaGetSymbolAddress((void**)&catL, g_catL);
    cudaGetSymbolAddress((void**)&W1, g_W1);
    cudaGetSymbolAddress((void**)&Wr1, g_Wr1);
    cudaGetSymbolAddress((void**)&Wo1, g_Wo1);
    cudaGetSymbolAddress((void**)&rsH, g_rsH);    cudaGetSymbolAddress((void**)&rsL, g_rsL);
    cudaGetSymbolAddress((void**)&qkvH, g_qkvH);  cudaGetSymbolAddress((void**)&qkvL, g_qkvL);
    cudaGetSymbolAddress((void**)&rpH, g_rpH);    cudaGetSymbolAddress((void**)&rpL, g_rpL);
    cudaGetSymbolAddress((void**)&attnH, g_attnH);cudaGetSymbolAddress((void**)&attnL, g_attnL);
    cudaGetSymbolAddress((void**)&wt, g_wt);
    cudaGetSymbolAddress((void**)&scores, g_scores);
    cudaGetSymbolAddress((void**)&bdu, g_bdu);
    cudaGetSymbolAddress((void**)&biasU, g_biasU);
    cudaGetSymbolAddress((void**)&biasV, g_biasV);

    // smem sizes (bytes)
    const int SM_A128 = (2 * APL2 + 128 * BSTR2) * 2 * 2;       // A-split, B-single, NT=128
    const int SM_AT   = (APL2 + 2 * 64 * BSTR2) * 2 * 2;        // A-single, B-split, NT=64
    const int SMSC    = 4 * SPL * 2;                            // score kernel
    cudaFuncSetAttribute(gemm_f16<128, 1, 0, 0, 1>, cudaFuncAttributeMaxDynamicSharedMemorySize, SM_A128);
    cudaFuncSetAttribute(gemm_f16<128, 1, 0, 0, 0>, cudaFuncAttributeMaxDynamicSharedMemorySize, SM_A128);
    cudaFuncSetAttribute(gemm_f16<64, 0, 1, 1, 1>,  cudaFuncAttributeMaxDynamicSharedMemorySize, SM_AT);
    cudaFuncSetAttribute(score_f16<0>, cudaFuncAttributeMaxDynamicSharedMemorySize, SMSC);
    cudaFuncSetAttribute(score_f16<1>, cudaFuncAttributeMaxDynamicSharedMemorySize, SMSC);

    // 0. ingest
    split_single<<<DM * D3 / 2 / 256, 256>>>(W, W1, DM * D3 / 2);
    split_single<<<DM * DM / 2 / 256, 256>>>(W_r, Wr1, DM * DM / 2);
    split_single<<<DM * DM / 2 / 256, 256>>>(W_o, Wo1, DM * DM / 2);
    split_pair<<<KL * DM / 2 / 256, 256>>>(r, rsH, rsL, KL * DM / 2);
    build_cat_split<<<BB * KL * DM / 2 / 256, 256>>>(inputs, inputs_mem, catH, catL);
    // 1. qkv = cat @ W  (A split, B single) -> planes
    gemm_f16<128, 1, 0, 0, 1><<<dim3(D3 / 128, BB * KL / 128), 256, SM_A128>>>(
        catH, catL, W1, nullptr, nullptr, qkvH, qkvL, DM, DM, D3, D3);
    // 2. rproj = r @ W_r -> planes
    gemm_f16<128, 1, 0, 0, 1><<<dim3(DM / 128, KL / 128), 256, SM_A128>>>(
        rsH, rsL, Wr1, nullptr, nullptr, rpH, rpL, DM, DM, DM, DM);
    // 3. biases (pre-scaled)
    bias_u_kernel<<<BB * NH * KL / 256, 256>>>(qkvH, qkvL, u, biasU);
    bias_v_kernel<<<NH * KL / 256, 256>>>(rpH, rpL, v, biasV);
    // 4. AC = Q @ K^T * 0.125 ; BDU = Q @ R^T * 0.125  (fp16 out)
    score_f16<0><<<dim3(KL / 256, QL / 128, BB * NH), 256, SMSC>>>(
        qkvH, qkvL, nullptr, scores);
    score_f16<1><<<dim3(KL / 256, QL / 128, BB * NH), 256, SMSC>>>(
        qkvH, qkvL, rpH, bdu);
    // 5. fused shift+bias+mask+softmax -> fp16 weights
    fused_softmax3<<<BB * NH * QL, 256>>>(scores, bdu, biasU, biasV, wt);
    // 6. attn = weights @ V  (A single, B split) -> planes, K clamped
    gemm_f16<64, 0, 1, 1, 1><<<dim3(1, QL / 128, BB * NH), 256, SM_AT>>>(
        wt, nullptr, qkvH + 2 * DM, qkvL + 2 * DM, nullptr, attnH, attnL,
        KL, KL, D3, DM);
    // 7. out = attn @ W_o (A split, B single, fp32 out)
    gemm_f16<128, 1, 0, 0, 0><<<dim3(DM / 128, BB * QL / 128), 256, SM_A128>>>(
        attnH, attnL, Wo1, nullptr, out, nullptr, nullptr, DM, DM, DM, DM);
}

// round 8
// speedup vs baseline: 2.0531x; 1.0326x over previous
#include <cuda_runtime.h>
#include <cuda_fp16.h>
#include <math.h>
#include <stdint.h>

#define BB    2
#define QL    1024
#define MEML  1024
#define KL    2048
#define DM    1024
#define NH    16
#define DK    64
#define D3    3072

typedef __half  f16;
typedef __half2 f162;

// ---------------- scratch (device globals, no allocation) ----------------
__device__ f16 g_catH[BB * KL * DM], g_catL[BB * KL * DM];
__device__ f16 g_W1[DM * D3];
__device__ f16 g_Wr1[DM * DM];
__device__ f16 g_Wo1[DM * DM];
__device__ f16 g_rsH[KL * DM], g_rsL[KL * DM];
__device__ f16 g_qkvH[BB * KL * D3], g_qkvL[BB * KL * D3];
__device__ f16 g_rpH[KL * DM], g_rpL[KL * DM];
__device__ f16 g_attnH[BB * QL * DM], g_attnL[BB * QL * DM];
__device__ f16 g_scores[(size_t)BB * NH * QL * KL];   // AC * 0.125, fp16
__device__ f16 g_bdu[(size_t)BB * NH * QL * KL];      // Q@R^T * 0.125, fp16
__device__ f16 g_wt[(size_t)BB * NH * QL * KL];       // softmax weights, fp16
__device__ float g_biasU[BB * NH * KL];
__device__ float g_biasV[NH * KL];

// ---------------- helpers ----------------
__device__ __forceinline__ void split1(float x, f16& h, f16& l) {
    h = __float2half_rn(x);
    l = __float2half_rn(x - __half2float(h));
}
__device__ __forceinline__ void cp16(uint32_t dst, const void* src) {
    asm volatile("cp.async.cg.shared.global [%0], [%1], 16;\n" :: "r"(dst), "l"(src));
}
__device__ __forceinline__ void cp_commit() {
    asm volatile("cp.async.commit_group;\n");
}
__device__ __forceinline__ void cp_wait0() {
    asm volatile("cp.async.wait_group 0;\n");
}
__device__ __forceinline__ void mmaf16(float* d, const uint32_t* a,
                                       const uint32_t* b) {
    asm volatile(
        "mma.sync.aligned.m16n8k16.row.col.f32.f16.f16.f32 "
        "{%0,%1,%2,%3}, {%4,%5,%6,%7}, {%8,%9}, {%0,%1,%2,%3};"
        : "+f"(d[0]), "+f"(d[1]), "+f"(d[2]), "+f"(d[3])
        : "r"(a[0]), "r"(a[1]), "r"(a[2]), "r"(a[3]), "r"(b[0]), "r"(b[1]));
}
#define LDSM4(R, addr)                                                        \
    asm volatile("ldmatrix.sync.aligned.m8n8.x4.shared.b16 {%0,%1,%2,%3}, [%4];" \
                 : "=r"((R)[0]), "=r"((R)[1]), "=r"((R)[2]), "=r"((R)[3])     \
                 : "r"(addr))

extern __shared__ __align__(16) char dynsm[];

// ---------------- ingest kernels ----------------
__global__ void split_single(const float* __restrict__ src,
                             f16* __restrict__ H, int n2) {
    int i = blockIdx.x * 256 + threadIdx.x;
    if (i >= n2) return;
    float2 v = *(const float2*)(src + 2 * (size_t)i);
    *(f162*)(H + 2 * (size_t)i) = __floats2half2_rn(v.x, v.y);
}
__global__ void split_pair(const float* __restrict__ src,
                           f16* __restrict__ H, f16* __restrict__ L, int n2) {
    int i = blockIdx.x * 256 + threadIdx.x;
    if (i >= n2) return;
    float2 v = *(const float2*)(src + 2 * (size_t)i);
    f16 h0, l0, h1, l1;
    split1(v.x, h0, l0); split1(v.y, h1, l1);
    f162 vh; vh.x = h0; vh.y = h1;
    f162 vl; vl.x = l0; vl.y = l1;
    *(f162*)(H + 2 * (size_t)i) = vh;
    *(f162*)(L + 2 * (size_t)i) = vl;
}
__global__ void build_cat_split(const float* __restrict__ inp,
                                const float* __restrict__ mem,
                                f16* __restrict__ H, f16* __restrict__ L) {
    int idx = blockIdx.x * 256 + threadIdx.x;
    int per_b = KL * (DM / 2);
    int b = idx / per_b;
    int rem = idx - b * per_b;
    int t = rem / (DM / 2);
    int c = rem - t * (DM / 2);
    const float2* s;
    if (t < MEML) s = (const float2*)(mem + ((size_t)b * MEML + t) * DM) + c;
    else          s = (const float2*)(inp + ((size_t)b * QL + (t - MEML)) * DM) + c;
    float2 v = *s;
    f16 h0, l0, h1, l1;
    split1(v.x, h0, l0); split1(v.y, h1, l1);
    f162 vh; vh.x = h0; vh.y = h1;
    f162 vl; vl.x = l0; vl.y = l1;
    size_t o = ((size_t)b * KL + t) * DM + 2 * c;
    *(f162*)(H + o) = vh;
    *(f162*)(L + o) = vl;
}

// ---------------- unified fp16 GEMM ----------------
#define ASTR2 40
#define APL2  (128 * ASTR2)
#define BSTR2 40                     // 80 B rows: 16B-aligned for ldmatrix

template <int NT, int ASPL, int BSPL, int MODE, int COUT>
__global__ __launch_bounds__(256, 2)
void gemm_f16(const f16* __restrict__ AH, const f16* __restrict__ AL,
              const f16* __restrict__ BH, const f16* __restrict__ BL,
              float* __restrict__ C, f16* __restrict__ CH, f16* __restrict__ CL,
              int K, int lda, int ldb, int ldc) {
    constexpr int BPL2 = NT * BSTR2;
    constexpr int ANP = ASPL ? 2 : 1;
    constexpr int BNP = BSPL ? 2 : 1;
    constexpr int STG = ANP * APL2 + BNP * BPL2;
    constexpr int ITB = (NT == 128) ? 4 : 2;
    constexpr int NJ = NT / 16;
    int tid = threadIdx.x, lane = tid & 31, wid = tid >> 5;
    int wy = wid & 3, wx = wid >> 2;
    int m0 = blockIdx.y * 128, n0 = blockIdx.x * NT;

    if (MODE == 1) {
        int z = blockIdx.z, b = z >> 4, h = z & 15;
        AH += (size_t)z * QL * KL;
        BH += (size_t)b * KL * D3 + (size_t)h * DK;
        BL += (size_t)b * KL * D3 + (size_t)h * DK;
        CH += (size_t)b * QL * DM + (size_t)h * DK;
        CL += (size_t)b * QL * DM + (size_t)h * DK;
    }
    const f16* AbH = AH + (size_t)m0 * lda;
    const f16* AbL = ASPL ? (AL + (size_t)m0 * lda) : nullptr;
    const f16* BbH = BH + n0;
    const f16* BbL = BSPL ? (BL + n0) : nullptr;

    int Klim = K;
    if (MODE == 1) { int km = m0 + 128 + MEML; Klim = K < km ? K : km; }
    int NC = Klim >> 5;

    f16* sm = (f16*)dynsm;
    uint2 pbh[ITB], pbl[ITB];

    auto loadA = [&](int k0, int s) {
        f16* base = sm + s * STG;
        uint32_t dh = (uint32_t)__cvta_generic_to_shared(base);
#pragma unroll
        for (int it = 0; it < 2; it++) {
            int e = tid + it * 256;
            int row = e >> 2, ch = (e & 3) << 3;
            size_t src = (size_t)row * lda + k0 + ch;
            uint32_t doff = (uint32_t)(row * ASTR2 + ch) * 2;
            cp16(dh + doff, AbH + src);
            if (ASPL) cp16(dh + APL2 * 2 + doff, AbL + src);
        }
    };
    auto ldB = [&](int k0) {
#pragma unroll
        for (int i = 0; i < ITB; i++) {
            int e = tid + i * 256;
            int kk = e / (NT / 4), nq = (e % (NT / 4)) * 4;
            size_t src = (size_t)(k0 + kk) * ldb + nq;
            pbh[i] = *(const uint2*)(BbH + src);
            if (BSPL) pbl[i] = *(const uint2*)(BbL + src);
        }
    };
    auto stB = [&](int s) {
        f16* bh = sm + s * STG + ANP * APL2;
#pragma unroll
        for (int i = 0; i < ITB; i++) {
            int e = tid + i * 256;
            int kk = e / (NT / 4), nq = (e % (NT / 4)) * 4;
            f16 vh[4]; *(uint2*)vh = pbh[i];
#pragma unroll
            for (int t = 0; t < 4; t++) bh[(nq + t) * BSTR2 + kk] = vh[t];
            if (BSPL) {
                f16 vl[4]; *(uint2*)vl = pbl[i];
#pragma unroll
                for (int t = 0; t < 4; t++)
                    bh[BPL2 + (nq + t) * BSTR2 + kk] = vl[t];
            }
        }
    };

    float acc[2][NJ][4];
#pragma unroll
    for (int mi = 0; mi < 2; mi++)
#pragma unroll
        for (int nj = 0; nj < NJ; nj++)
#pragma unroll
            for (int q = 0; q < 4; q++) acc[mi][nj][q] = 0.0f;

    loadA(0, 0); cp_commit();
    ldB(0); stB(0);
    cp_wait0();
    __syncthreads();

    int arow = (lane & 15);
    int acol = (lane & 16) >> 1;          // 0 or 8
    int brow = (lane & 7) + ((lane & 16) >> 1);
    int bcol = (lane & 8);

    for (int c = 0; c < NC; c++) {
        int s = c & 1;
        if (c + 1 < NC) {
            loadA((c + 1) << 5, s ^ 1); cp_commit();
            ldB((c + 1) << 5);
        }
        const f16* st = sm + s * STG;
        uint32_t sa = (uint32_t)__cvta_generic_to_shared(st);
        uint32_t sb = sa + ANP * APL2 * 2;
#pragma unroll
        for (int kk = 0; kk < 32; kk += 16) {
            uint32_t ah[2][4], al[2][4];
#pragma unroll
            for (int mi = 0; mi < 2; mi++) {
                int r = wy * 32 + mi * 16 + arow;
                uint32_t ad = sa + (uint32_t)(r * ASTR2 + kk + acol) * 2;
                LDSM4(ah[mi], ad);
                if (ASPL) LDSM4(al[mi], ad + APL2 * 2);
            }
#pragma unroll
            for (int njp = 0; njp < NJ / 2; njp++) {
                int n = wx * (NT / 2) + njp * 16 + brow;
                uint32_t bd = sb + (uint32_t)(n * BSTR2 + kk + bcol) * 2;
                uint32_t bf[4], blf[4];
                LDSM4(bf, bd);
                if (BSPL) LDSM4(blf, bd + BPL2 * 2);
#pragma unroll
                for (int mi = 0; mi < 2; mi++) {
                    mmaf16(acc[mi][2 * njp + 0], ah[mi], bf + 0);
                    mmaf16(acc[mi][2 * njp + 1], ah[mi], bf + 2);
                    if (ASPL) {
                        mmaf16(acc[mi][2 * njp + 0], al[mi], bf + 0);
                        mmaf16(acc[mi][2 * njp + 1], al[mi], bf + 2);
                    }
                    if (BSPL) {
                        mmaf16(acc[mi][2 * njp + 0], ah[mi], blf + 0);
                        mmaf16(acc[mi][2 * njp + 1], ah[mi], blf + 2);
                    }
                }
            }
        }
        if (c + 1 < NC) { stB(s ^ 1); cp_wait0(); }
        __syncthreads();
    }

#pragma unroll
    for (int mi = 0; mi < 2; mi++) {
#pragma unroll
        for (int nj = 0; nj < NJ; nj++) {
            int r = m0 + wy * 32 + mi * 16 + (lane >> 2);
            int ncol = n0 + wx * (NT / 2) + nj * 8 + ((lane & 3) << 1);
            if (COUT == 0) {
                *(float2*)&C[(size_t)r * ldc + ncol] =
                    make_float2(acc[mi][nj][0], acc[mi][nj][1]);
                *(float2*)&C[(size_t)(r + 8) * ldc + ncol] =
                    make_float2(acc[mi][nj][2], acc[mi][nj][3]);
            } else {
#pragma unroll
                for (int hh = 0; hh < 2; hh++) {
                    f16 h0, l0, h1, l1;
                    split1(acc[mi][nj][2 * hh + 0], h0, l0);
                    split1(acc[mi][nj][2 * hh + 1], h1, l1);
                    f162 vh; vh.x = h0; vh.y = h1;
                    f162 vl; vl.x = l0; vl.y = l1;
                    size_t o = (size_t)(r + 8 * hh) * ldc + ncol;
                    *(f162*)(CH + o) = vh;
                    *(f162*)(CL + o) = vl;
                }
            }
        }
    }
}

// ---------------- merged score GEMM: z<32 -> AC (Q@K^T), z>=32 -> BD (Q@R^T)
#define SSTR 72
#define SPL  (128 * SSTR)

__global__ __launch_bounds__(256, 2)
void score_f16(const f16* __restrict__ qH, const f16* __restrict__ qL,
               const f16* __restrict__ rp,
               f16* __restrict__ AC, f16* __restrict__ BD) {
    int z = blockIdx.z;
    int mode = (z >= BB * NH) ? 1 : 0;
    int bh = mode ? (z - BB * NH) : z;
    int b = bh >> 4, h = bh & 15;
    int i0 = blockIdx.y * 128, j0 = blockIdx.x * 256;
    bool act[2];
    if (mode == 0) {
        act[0] = (j0 - i0) < 1152;
        act[1] = (j0 + 128 - i0) < 1152;
        if (!act[0]) return;
    } else {
        act[0] = (i0 + j0) > 768;
        act[1] = (i0 + j0 + 128) > 768;
        if (!act[1]) return;
    }
    int tid = threadIdx.x, lane = tid & 31, wid = tid >> 5;
    int wy = wid & 3, wx = wid >> 2;

    f16* sm = (f16*)dynsm;
    {
        const f16* AbH = qH + (size_t)(b * KL + MEML + i0) * D3 + h * DK;
        const f16* AbL = qL + (size_t)(b * KL + MEML + i0) * D3 + h * DK;
        uint32_t dh = (uint32_t)__cvta_generic_to_shared(sm);
#pragma unroll
        for (int it = 0; it < 4; it++) {
            int e = tid + it * 256;
            int row = e >> 3, ch = (e & 7) << 3;
            size_t src = (size_t)row * D3 + ch;
            uint32_t doff = (uint32_t)(row * SSTR + ch) * 2;
            cp16(dh + doff, AbH + src);
            cp16(dh + SPL * 2 + doff, AbL + src);
        }
    }
#pragma unroll
    for (int jt = 0; jt < 2; jt++) {
        if (!act[jt]) continue;
        int j1 = j0 + jt * 128;
        const f16* Bb;
        size_t ldrow;
        if (mode == 0) { Bb = qH + (size_t)(b * KL + j1) * D3 + DM + h * DK; ldrow = D3; }
        else           { Bb = rp + (size_t)j1 * DM + h * DK; ldrow = DM; }
        uint32_t dh = (uint32_t)__cvta_generic_to_shared(sm + (2 + jt) * SPL);
#pragma unroll
        for (int it = 0; it < 4; it++) {
            int e = tid + it * 256;
            int row = e >> 3, ch = (e & 7) << 3;
            cp16(dh + (uint32_t)(row * SSTR + ch) * 2, Bb + (size_t)row * ldrow + ch);
        }
    }
    cp_commit();
    cp_wait0();
    __syncthreads();

    int arow = (lane & 15);
    int acol = (lane & 16) >> 1;
    int brow = (lane & 7) + ((lane & 16) >> 1);
    int bcol = (lane & 8);
    uint32_t sa = (uint32_t)__cvta_generic_to_shared(sm);

    f16* Cb = (mode ? BD : AC) + (size_t)bh * QL * KL;
#pragma unroll
    for (int jt = 0; jt < 2; jt++) {
        if (!act[jt]) continue;
        uint32_t sb = sa + (2 + jt) * SPL * 2;
        float acc[2][8][4];
#pragma unroll
        for (int mi = 0; mi < 2; mi++)
#pragma unroll
            for (int nj = 0; nj < 8; nj++)
#pragma unroll
                for (int q = 0; q < 4; q++) acc[mi][nj][q] = 0.0f;
#pragma unroll
        for (int kk = 0; kk < 64; kk += 16) {
            uint32_t ah[2][4], al[2][4];
#pragma unroll
            for (int mi = 0; mi < 2; mi++) {
                int r = wy * 32 + mi * 16 + arow;
                uint32_t ad = sa + (uint32_t)(r * SSTR + kk + acol) * 2;
                LDSM4(ah[mi], ad);
                LDSM4(al[mi], ad + SPL * 2);
            }
#pragma unroll
            for (int njp = 0; njp < 4; njp++) {
                int n = wx * 64 + njp * 16 + brow;
                uint32_t bd = sb + (uint32_t)(n * SSTR + kk + bcol) * 2;
                uint32_t bf[4];
                LDSM4(bf, bd);
#pragma unroll
                for (int mi = 0; mi < 2; mi++) {
                    mmaf16(acc[mi][2 * njp + 0], ah[mi], bf + 0);
                    mmaf16(acc[mi][2 * njp + 1], ah[mi], bf + 2);
                    mmaf16(acc[mi][2 * njp + 0], al[mi], bf + 0);
                    mmaf16(acc[mi][2 * njp + 1], al[mi], bf + 2);
                }
            }
        }
        int j1 = j0 + jt * 128;
#pragma unroll
        for (int mi = 0; mi < 2; mi++) {
#pragma unroll
            for (int nj = 0; nj < 8; nj++) {
                int r = i0 + wy * 32 + mi * 16 + (lane >> 2);
                int ncol = j1 + wx * 64 + nj * 8 + ((lane & 3) << 1);
                *(f162*)&Cb[(size_t)r * KL + ncol] =
                    __floats2half2_rn(acc[mi][nj][0] * 0.125f,
                                      acc[mi][nj][1] * 0.125f);
                *(f162*)&Cb[(size_t)(r + 8) * KL + ncol] =
                    __floats2half2_rn(acc[mi][nj][2] * 0.125f,
                                      acc[mi][nj][3] * 0.125f);
            }
        }
    }
}

// ---------------- bias kernels (pre-scaled by 0.125) ----------------
__global__ void bias_u_kernel(const f16* __restrict__ kH,
                              const f16* __restrict__ kL,
                              const float* __restrict__ u,
                              float* __restrict__ bU) {
    int idx = blockIdx.x * 256 + threadIdx.x;
    int bh = idx >> 11, j = idx & 2047;
    int b = bh >> 4, h = bh & 15;
    const f16* ph = kH + (size_t)(b * KL + j) * D3 + DM + h * DK;
    const f16* pl = kL + (size_t)(b * KL + j) * D3 + DM + h * DK;
    const float* uu = u + h * DK;
    float s = 0.0f;
#pragma unroll
    for (int d = 0; d < DK; d++)
        s += (__half2float(ph[d]) + __half2float(pl[d])) * uu[d];
    bU[idx] = s * 0.125f;
}
__global__ void bias_v_kernel(const f16* __restrict__ rpH,
                              const f16* __restrict__ rpL,
                              const float* __restrict__ v,
                              float* __restrict__ bV) {
    int idx = blockIdx.x * 256 + threadIdx.x;
    int h = idx >> 11, p = idx & 2047;
    const f16* ph = rpH + (size_t)p * DM + h * DK;
    const f16* pl = rpL + (size_t)p * DM + h * DK;
    const float* vv = v + h * DK;
    float s = 0.0f;
#pragma unroll
    for (int d = 0; d < DK; d++)
        s += (__half2float(ph[d]) + __half2float(pl[d])) * vv[d];
    bV[idx] = s * 0.125f;
}

// ---------------- fused shift+bias+mask+softmax -> fp16 weights -------------
__global__ __launch_bounds__(256)
void fused_softmax3(const f16* __restrict__ AC, const f16* __restrict__ U,
                    const float* __restrict__ bU, const float* __restrict__ bV,
                    f16* __restrict__ WT) {
    int rid = blockIdx.x;
    int bh = rid >> 10, h = bh & 15, i = rid & 1023;
    const f16* p = AC + (size_t)rid * KL;
    const f16* q = U + (size_t)rid * KL + (QL - 1 - i);
    const float* bu = bU + bh * KL;
    const float* bv = bV + h * KL + (QL - 1 - i);
    int jmax = i + MEML;
    int tile_end = (i & ~127) + 128 + MEML;
    int tid = threadIdx.x;
    __shared__ float red[256];
    float x[8];
    float mx = -INFINITY;
#pragma unroll
    for (int t = 0; t < 4; t++) {
        int j2 = tid + t * 256;      // pair index
        int j = 2 * j2;
        f162 pv = *(const f162*)(p + j);
        float2 buv = *(const float2*)(bu + j);
        float q0 = __half2float(q[j]), q1 = __half2float(q[j + 1]);
        float x0 = __half2float(pv.x) + buv.x + q0 + bv[j];
        float x1 = __half2float(pv.y) + buv.y + q1 + bv[j + 1];
        x[2 * t + 0] = (j     <= jmax) ? x0 : -INFINITY;
        x[2 * t + 1] = (j + 1 <= jmax) ? x1 : -INFINITY;
        mx = fmaxf(mx, fmaxf(x[2 * t], x[2 * t + 1]));
    }
    red[tid] = mx;
    __syncthreads();
    for (int s = 128; s > 0; s >>= 1) {
        if (tid < s) red[tid] = fmaxf(red[tid], red[tid + s]);
        __syncthreads();
    }
    mx = red[0];
    __syncthreads();
    float sum = 0.0f;
#pragma unroll
    for (int t = 0; t < 8; t++) {
        x[t] = __expf(x[t] - mx);
        sum += x[t];
    }
    red[tid] = sum;
    __syncthreads();
    for (int s = 128; s > 0; s >>= 1) {
        if (tid < s) red[tid] += red[tid + s];
        __syncthreads();
    }
    float inv = 1.0f / red[0];
    f16* w = WT + (size_t)rid * KL;
#pragma unroll
    for (int t = 0; t < 4; t++) {
        int j2 = tid + t * 256;
        int j = 2 * j2;
        if (j < tile_end)
            *(f162*)(w + j) = __floats2half2_rn(x[2 * t] * inv, x[2 * t + 1] * inv);
    }
}

// ---------------------------------------------------------------------------
extern "C" void kernel_launch(void* const* d_in, const int* in_sizes, int n_in,
                              void* d_out, int out_size) {
    const float* inputs     = (const float*)d_in[0];
    const float* inputs_mem = (const float*)d_in[1];
    const float* r          = (const float*)d_in[2];
    const float* W          = (const float*)d_in[3];
    const float* W_r        = (const float*)d_in[4];
    const float* W_o        = (const float*)d_in[5];
    const float* u          = (const float*)d_in[6];
    const float* v          = (const float*)d_in[7];
    float* out = (float*)d_out;

    f16 *catH, *catL, *W1, *Wr1, *Wo1, *rsH, *rsL;
    f16 *qkvH, *qkvL, *rpH, *rpL, *attnH, *attnL, *wt, *scores, *bdu;
    float *biasU, *biasV;
    cudaGetSymbolAddress((void**)&catH, g_catH);  cudaGetSymbolAddress((void**)&catL, g_catL);
    cudaGetSymbolAddress((void**)&W1, g_W1);
    cudaGetSymbolAddress((void**)&Wr1, g_Wr1);
    cudaGetSymbolAddress((void**)&Wo1, g_Wo1);
    cudaGetSymbolAddress((void**)&rsH, g_rsH);    cudaGetSymbolAddress((void**)&rsL, g_rsL);
    cudaGetSymbolAddress((void**)&qkvH, g_qkvH);  cudaGetSymbolAddress((void**)&qkvL, g_qkvL);
    cudaGetSymbolAddress((void**)&rpH, g_rpH);    cudaGetSymbolAddress((void**)&rpL, g_rpL);
    cudaGetSymbolAddress((void**)&attnH, g_attnH);cudaGetSymbolAddress((void**)&attnL, g_attnL);
    cudaGetSymbolAddress((void**)&wt, g_wt);
    cudaGetSymbolAddress((void**)&scores, g_scores);
    cudaGetSymbolAddress((void**)&bdu, g_bdu);
    cudaGetSymbolAddress((void**)&biasU, g_biasU);
    cudaGetSymbolAddress((void**)&biasV, g_biasV);

    // smem sizes (bytes)
    const int SM_A128 = (2 * APL2 + 128 * BSTR2) * 2 * 2;       // A-split, B-single, NT=128
    const int SM_AT   = (APL2 + 2 * 64 * BSTR2) * 2 * 2;        // A-single, B-split, NT=64
    const int SMSC    = 4 * SPL * 2;                            // score kernel
    cudaFuncSetAttribute(gemm_f16<128, 1, 0, 0, 1>, cudaFuncAttributeMaxDynamicSharedMemorySize, SM_A128);
    cudaFuncSetAttribute(gemm_f16<128, 1, 0, 0, 0>, cudaFuncAttributeMaxDynamicSharedMemorySize, SM_A128);
    cudaFuncSetAttribute(gemm_f16<64, 0, 1, 1, 1>,  cudaFuncAttributeMaxDynamicSharedMemorySize, SM_AT);
    cudaFuncSetAttribute(score_f16, cudaFuncAttributeMaxDynamicSharedMemorySize, SMSC);

    // 0. ingest
    split_single<<<DM * D3 / 2 / 256, 256>>>(W, W1, DM * D3 / 2);
    split_single<<<DM * DM / 2 / 256, 256>>>(W_r, Wr1, DM * DM / 2);
    split_single<<<DM * DM / 2 / 256, 256>>>(W_o, Wo1, DM * DM / 2);
    split_pair<<<KL * DM / 2 / 256, 256>>>(r, rsH, rsL, KL * DM / 2);
    build_cat_split<<<BB * KL * DM / 2 / 256, 256>>>(inputs, inputs_mem, catH, catL);
    // 1. qkv = cat @ W  (A split, B single) -> planes
    gemm_f16<128, 1, 0, 0, 1><<<dim3(D3 / 128, BB * KL / 128), 256, SM_A128>>>(
        catH, catL, W1, nullptr, nullptr, qkvH, qkvL, DM, DM, D3, D3);
    // 2. rproj = r @ W_r -> planes
    gemm_f16<128, 1, 0, 0, 1><<<dim3(DM / 128, KL / 128), 256, SM_A128>>>(
        rsH, rsL, Wr1, nullptr, nullptr, rpH, rpL, DM, DM, DM, DM);
    // 3. biases (pre-scaled)
    bias_u_kernel<<<BB * NH * KL / 256, 256>>>(qkvH, qkvL, u, biasU);
    bias_v_kernel<<<NH * KL / 256, 256>>>(rpH, rpL, v, biasV);
    // 4. merged score GEMMs: z<32 AC, z>=32 BD  (fp16 out, pre-scaled)
    score_f16<<<dim3(KL / 256, QL / 128, 2 * BB * NH), 256, SMSC>>>(
        qkvH, qkvL, rpH, scores, bdu);
    // 5. fused shift+bias+mask+softmax -> fp16 weights
    fused_softmax3<<<BB * NH * QL, 256>>>(scores, bdu, biasU, biasV, wt);
    // 6. attn = weights @ V  (A single, B split) -> planes, K clamped
    gemm_f16<64, 0, 1, 1, 1><<<dim3(1, QL / 128, BB * NH), 256, SM_AT>>>(
        wt, nullptr, qkvH + 2 * DM, qkvL + 2 * DM, nullptr, attnH, attnL,
        KL, KL, D3, DM);
    // 7. out = attn @ W_o (A split, B single, fp32 out)
    gemm_f16<128, 1, 0, 0, 0><<<dim3(DM / 128, BB * QL / 128), 256, SM_A128>>>(
        attnH, attnL, Wo1, nullptr, out, nullptr, nullptr, DM, DM, DM, DM);
}

// round 10
// speedup vs baseline: 3.1478x; 1.5332x over previous
#include <cuda_runtime.h>
#include <cuda_fp16.h>
#include <math.h>
#include <stdint.h>

#define BB    2
#define QL    1024
#define MEML  1024
#define KL    2048
#define DM    1024
#define NH    16
#define DK    64
#define D3    3072

typedef __half  f16;
typedef __half2 f162;

// ---------------- scratch (device globals, no allocation) ----------------
__device__ f16 g_catH[BB * KL * DM], g_catL[BB * KL * DM];
__device__ f16 g_W1[DM * D3];
__device__ f16 g_Wr1[DM * DM];
__device__ f16 g_Wo1[DM * DM];
__device__ f16 g_rsH[KL * DM], g_rsL[KL * DM];
__device__ f16 g_qkvH[BB * KL * D3], g_qkvL[BB * KL * D3];
__device__ f16 g_rpH[KL * DM], g_rpL[KL * DM];
__device__ f16 g_attnH[BB * QL * DM], g_attnL[BB * QL * DM];
__device__ f16 g_scores[(size_t)BB * NH * QL * KL];   // AC * 0.125, fp16
__device__ f16 g_bdu[(size_t)BB * NH * QL * KL];      // Q@R^T * 0.125, fp16
__device__ f16 g_wt[(size_t)BB * NH * QL * KL];       // softmax weights, fp16
__device__ float g_biasU[BB * NH * KL];
__device__ float g_biasV[NH * KL];

// ---------------- helpers ----------------
__device__ __forceinline__ void split1(float x, f16& h, f16& l) {
    h = __float2half_rn(x);
    l = __float2half_rn(x - __half2float(h));
}
__device__ __forceinline__ void cp16(uint32_t dst, const void* src) {
    asm volatile("cp.async.cg.shared.global [%0], [%1], 16;\n" :: "r"(dst), "l"(src));
}
__device__ __forceinline__ void cp_commit() {
    asm volatile("cp.async.commit_group;\n");
}
__device__ __forceinline__ void cp_wait0() {
    asm volatile("cp.async.wait_group 0;\n");
}
__device__ __forceinline__ void mmaf16(float* d, const uint32_t* a,
                                       const uint32_t* b) {
    asm volatile(
        "mma.sync.aligned.m16n8k16.row.col.f32.f16.f16.f32 "
        "{%0,%1,%2,%3}, {%4,%5,%6,%7}, {%8,%9}, {%0,%1,%2,%3};"
        : "+f"(d[0]), "+f"(d[1]), "+f"(d[2]), "+f"(d[3])
        : "r"(a[0]), "r"(a[1]), "r"(a[2]), "r"(a[3]), "r"(b[0]), "r"(b[1]));
}
#define LDSM4(R, addr)                                                        \
    asm volatile("ldmatrix.sync.aligned.m8n8.x4.shared.b16 {%0,%1,%2,%3}, [%4];" \
                 : "=r"((R)[0]), "=r"((R)[1]), "=r"((R)[2]), "=r"((R)[3])     \
                 : "r"(addr))
#define LDSM4T(R, addr)                                                       \
    asm volatile("ldmatrix.sync.aligned.m8n8.x4.trans.shared.b16 {%0,%1,%2,%3}, [%4];" \
                 : "=r"((R)[0]), "=r"((R)[1]), "=r"((R)[2]), "=r"((R)[3])     \
                 : "r"(addr))

extern __shared__ __align__(16) char dynsm[];

// ---------------- ingest kernels ----------------
__global__ void split_single(const float* __restrict__ src,
                             f16* __restrict__ H, int n2) {
    int i = blockIdx.x * 256 + threadIdx.x;
    if (i >= n2) return;
    float2 v = *(const float2*)(src + 2 * (size_t)i);
    *(f162*)(H + 2 * (size_t)i) = __floats2half2_rn(v.x, v.y);
}
__global__ void split_pair(const float* __restrict__ src,
                           f16* __restrict__ H, f16* __restrict__ L, int n2) {
    int i = blockIdx.x * 256 + threadIdx.x;
    if (i >= n2) return;
    float2 v = *(const float2*)(src + 2 * (size_t)i);
    f16 h0, l0, h1, l1;
    split1(v.x, h0, l0); split1(v.y, h1, l1);
    f162 vh; vh.x = h0; vh.y = h1;
    f162 vl; vl.x = l0; vl.y = l1;
    *(f162*)(H + 2 * (size_t)i) = vh;
    *(f162*)(L + 2 * (size_t)i) = vl;
}
__global__ void build_cat_split(const float* __restrict__ inp,
                                const float* __restrict__ mem,
                                f16* __restrict__ H, f16* __restrict__ L) {
    int idx = blockIdx.x * 256 + threadIdx.x;
    int per_b = KL * (DM / 2);
    int b = idx / per_b;
    int rem = idx - b * per_b;
    int t = rem / (DM / 2);
    int c = rem - t * (DM / 2);
    const float2* s;
    if (t < MEML) s = (const float2*)(mem + ((size_t)b * MEML + t) * DM) + c;
    else          s = (const float2*)(inp + ((size_t)b * QL + (t - MEML)) * DM) + c;
    float2 v = *s;
    f16 h0, l0, h1, l1;
    split1(v.x, h0, l0); split1(v.y, h1, l1);
    f162 vh; vh.x = h0; vh.y = h1;
    f162 vl; vl.x = l0; vl.y = l1;
    size_t o = ((size_t)b * KL + t) * DM + 2 * c;
    *(f162*)(H + o) = vh;
    *(f162*)(L + o) = vl;
}

// ---------------- unified fp16 GEMM (trans-B, no smem transpose) ------------
// A [m][k] (split if ASPL), B kept natural [k][n] (split if BSPL), ldmatrix
// trans for B fragments. BM=128, BN=NT, BK=32, 256 thr (8 warps 4x2).
// MODE 1: per-(b,h) weights@V, K clamped past mask.
// MODE 2: Q-part of qkv: rows remapped to query rows only.
#define ASTR2 40
#define APL2  (128 * ASTR2)

template <int NT, int ASPL, int BSPL, int MODE, int COUT>
__global__ __launch_bounds__(256, 2)
void gemm_f16(const f16* __restrict__ AH, const f16* __restrict__ AL,
              const f16* __restrict__ BH, const f16* __restrict__ BL,
              float* __restrict__ C, f16* __restrict__ CH, f16* __restrict__ CL,
              int K, int lda, int ldb, int ldc) {
    constexpr int NTP = NT + 8;          // padded n-stride (16B-aligned rows)
    constexpr int BPL = 32 * NTP;        // B plane (halves) per stage
    constexpr int ANP = ASPL ? 2 : 1;
    constexpr int BNP = BSPL ? 2 : 1;
    constexpr int STG = ANP * APL2 + BNP * BPL;
    constexpr int NJ = NT / 16;
    int tid = threadIdx.x, lane = tid & 31, wid = tid >> 5;
    int wy = wid & 3, wx = wid >> 2;
    int m0, n0 = blockIdx.x * NT;

    if (MODE == 2) {
        int by = blockIdx.y, b = by >> 3;
        m0 = b * KL + MEML + (by & 7) * 128;     // query rows only
    } else {
        m0 = blockIdx.y * 128;
    }
    if (MODE == 1) {
        int z = blockIdx.z, b = z >> 4, h = z & 15;
        AH += (size_t)z * QL * KL;
        BH += (size_t)b * KL * D3 + (size_t)h * DK;
        BL += (size_t)b * KL * D3 + (size_t)h * DK;
        CH += (size_t)b * QL * DM + (size_t)h * DK;
        CL += (size_t)b * QL * DM + (size_t)h * DK;
    }
    const f16* AbH = AH + (size_t)m0 * lda;
    const f16* AbL = ASPL ? (AL + (size_t)m0 * lda) : nullptr;
    const f16* BbH = BH + n0;
    const f16* BbL = BSPL ? (BL + n0) : nullptr;

    int Klim = K;
    if (MODE == 1) { int km = (blockIdx.y * 128) + 128 + MEML; Klim = K < km ? K : km; }
    int NC = Klim >> 5;

    f16* sm = (f16*)dynsm;

    auto loadAB = [&](int k0, int s) {
        f16* base = sm + s * STG;
        uint32_t da = (uint32_t)__cvta_generic_to_shared(base);
        uint32_t db = da + ANP * APL2 * 2;
        // A: 128x32, 512 16B-chunks
#pragma unroll
        for (int it = 0; it < 2; it++) {
            int e = tid + it * 256;
            int row = e >> 2, ch = (e & 3) << 3;
            size_t src = (size_t)row * lda + k0 + ch;
            uint32_t doff = (uint32_t)(row * ASTR2 + ch) * 2;
            cp16(da + doff, AbH + src);
            if (ASPL) cp16(da + APL2 * 2 + doff, AbL + src);
        }
        // B: 32 x NT natural layout, NT/8 chunks per row
        constexpr int CPR = NT / 8;
        constexpr int ITB = (32 * CPR) / 256;
#pragma unroll
        for (int it = 0; it < ITB; it++) {
            int e = tid + it * 256;
            int kk = e / CPR, nb = (e % CPR) * 8;
            size_t src = (size_t)(k0 + kk) * ldb + nb;
            uint32_t doff = (uint32_t)(kk * NTP + nb) * 2;
            cp16(db + doff, BbH + src);
            if (BSPL) cp16(db + BPL * 2 + doff, BbL + src);
        }
    };

    float acc[2][NJ][4];
#pragma unroll
    for (int mi = 0; mi < 2; mi++)
#pragma unroll
        for (int nj = 0; nj < NJ; nj++)
#pragma unroll
            for (int q = 0; q < 4; q++) acc[mi][nj][q] = 0.0f;

    loadAB(0, 0); cp_commit();
    cp_wait0();
    __syncthreads();

    int arow = (lane & 15);
    int acol = (lane & 16) >> 1;                 // 0 or 8
    int bln = ((lane >> 4) << 3);                // trans: n offset 0/8

    for (int c = 0; c < NC; c++) {
        int s = c & 1;
        if (c + 1 < NC) { loadAB((c + 1) << 5, s ^ 1); cp_commit(); }
        uint32_t sa = (uint32_t)__cvta_generic_to_shared(sm + s * STG);
        uint32_t sb = sa + ANP * APL2 * 2;
#pragma unroll
        for (int kk = 0; kk < 32; kk += 16) {
            uint32_t ah[2][4], al[2][4];
#pragma unroll
            for (int mi = 0; mi < 2; mi++) {
                int r = wy * 32 + mi * 16 + arow;
                uint32_t ad = sa + (uint32_t)(r * ASTR2 + kk + acol) * 2;
                LDSM4(ah[mi], ad);
                if (ASPL) LDSM4(al[mi], ad + APL2 * 2);
            }
#pragma unroll
            for (int njp = 0; njp < NJ / 2; njp++) {
                int n16 = wx * (NT / 2) + njp * 16;
                uint32_t bd = sb +
                    (uint32_t)((kk + arow) * NTP + n16 + bln) * 2;
                uint32_t bf[4], blf[4];
                LDSM4T(bf, bd);
                if (BSPL) LDSM4T(blf, bd + BPL * 2);
#pragma unroll
                for (int mi = 0; mi < 2; mi++) {
                    mmaf16(acc[mi][2 * njp + 0], ah[mi], bf + 0);
                    mmaf16(acc[mi][2 * njp + 1], ah[mi], bf + 2);
                    if (ASPL) {
                        mmaf16(acc[mi][2 * njp + 0], al[mi], bf + 0);
                        mmaf16(acc[mi][2 * njp + 1], al[mi], bf + 2);
                    }
                    if (BSPL) {
                        mmaf16(acc[mi][2 * njp + 0], ah[mi], blf + 0);
                        mmaf16(acc[mi][2 * njp + 1], ah[mi], blf + 2);
                    }
                }
            }
        }
        if (c + 1 < NC) cp_wait0();
        __syncthreads();
    }

#pragma unroll
    for (int mi = 0; mi < 2; mi++) {
#pragma unroll
        for (int nj = 0; nj < NJ; nj++) {
            int r = m0 + wy * 32 + mi * 16 + (lane >> 2);
            int ncol = n0 + wx * (NT / 2) + nj * 8 + ((lane & 3) << 1);
            if (COUT == 0) {
                *(float2*)&C[(size_t)r * ldc + ncol] =
                    make_float2(acc[mi][nj][0], acc[mi][nj][1]);
                *(float2*)&C[(size_t)(r + 8) * ldc + ncol] =
                    make_float2(acc[mi][nj][2], acc[mi][nj][3]);
            } else {
#pragma unroll
                for (int hh = 0; hh < 2; hh++) {
                    f16 h0, l0, h1, l1;
                    split1(acc[mi][nj][2 * hh + 0], h0, l0);
                    split1(acc[mi][nj][2 * hh + 1], h1, l1);
                    f162 vh; vh.x = h0; vh.y = h1;
                    f162 vl; vl.x = l0; vl.y = l1;
                    size_t o = (size_t)(r + 8 * hh) * ldc + ncol;
                    *(f162*)(CH + o) = vh;
                    *(f162*)(CL + o) = vl;
                }
            }
        }
    }
}

// ---------------- merged score GEMM: z<32 -> AC (Q@K^T), z>=32 -> BD --------
#define SSTR 72
#define SPL  (128 * SSTR)

__global__ __launch_bounds__(256, 2)
void score_f16(const f16* __restrict__ qH, const f16* __restrict__ qL,
               const f16* __restrict__ rp,
               f16* __restrict__ AC, f16* __restrict__ BD) {
    int z = blockIdx.z;
    int mode = (z >= BB * NH) ? 1 : 0;
    int bh = mode ? (z - BB * NH) : z;
    int b = bh >> 4, h = bh & 15;
    int i0 = blockIdx.y * 128, j0 = blockIdx.x * 256;
    bool act[2];
    if (mode == 0) {
        act[0] = (j0 - i0) < 1152;
        act[1] = (j0 + 128 - i0) < 1152;
        if (!act[0]) return;
    } else {
        act[0] = (i0 + j0) > 768;
        act[1] = (i0 + j0 + 128) > 768;
        if (!act[1]) return;
    }
    int tid = threadIdx.x, lane = tid & 31, wid = tid >> 5;
    int wy = wid & 3, wx = wid >> 2;

    f16* sm = (f16*)dynsm;
    {
        const f16* AbH = qH + (size_t)(b * KL + MEML + i0) * D3 + h * DK;
        const f16* AbL = qL + (size_t)(b * KL + MEML + i0) * D3 + h * DK;
        uint32_t dh = (uint32_t)__cvta_generic_to_shared(sm);
#pragma unroll
        for (int it = 0; it < 4; it++) {
            int e = tid + it * 256;
            int row = e >> 3, ch = (e & 7) << 3;
            size_t src = (size_t)row * D3 + ch;
            uint32_t doff = (uint32_t)(row * SSTR + ch) * 2;
            cp16(dh + doff, AbH + src);
            cp16(dh + SPL * 2 + doff, AbL + src);
        }
    }
#pragma unroll
    for (int jt = 0; jt < 2; jt++) {
        if (!act[jt]) continue;
        int j1 = j0 + jt * 128;
        const f16* Bb;
        size_t ldrow;
        if (mode == 0) { Bb = qH + (size_t)(b * KL + j1) * D3 + DM + h * DK; ldrow = D3; }
        else           { Bb = rp + (size_t)j1 * DM + h * DK; ldrow = DM; }
        uint32_t dh = (uint32_t)__cvta_generic_to_shared(sm + (2 + jt) * SPL);
#pragma unroll
        for (int it = 0; it < 4; it++) {
            int e = tid + it * 256;
            int row = e >> 3, ch = (e & 7) << 3;
            cp16(dh + (uint32_t)(row * SSTR + ch) * 2, Bb + (size_t)row * ldrow + ch);
        }
    }
    cp_commit();
    cp_wait0();
    __syncthreads();

    int arow = (lane & 15);
    int acol = (lane & 16) >> 1;
    int brow = (lane & 7) + ((lane & 16) >> 1);
    int bcol = (lane & 8);
    uint32_t sa = (uint32_t)__cvta_generic_to_shared(sm);

    f16* Cb = (mode ? BD : AC) + (size_t)bh * QL * KL;
#pragma unroll
    for (int jt = 0; jt < 2; jt++) {
        if (!act[jt]) continue;
        uint32_t sb = sa + (2 + jt) * SPL * 2;
        float acc[2][8][4];
#pragma unroll
        for (int mi = 0; mi < 2; mi++)
#pragma unroll
            for (int nj = 0; nj < 8; nj++)
#pragma unroll
                for (int q = 0; q < 4; q++) acc[mi][nj][q] = 0.0f;
#pragma unroll
        for (int kk = 0; kk < 64; kk += 16) {
            uint32_t ah[2][4], al[2][4];
#pragma unroll
            for (int mi = 0; mi < 2; mi++) {
                int r = wy * 32 + mi * 16 + arow;
                uint32_t ad = sa + (uint32_t)(r * SSTR + kk + acol) * 2;
                LDSM4(ah[mi], ad);
                LDSM4(al[mi], ad + SPL * 2);
            }
#pragma unroll
            for (int njp = 0; njp < 4; njp++) {
                int n = wx * 64 + njp * 16 + brow;
                uint32_t bd = sb + (uint32_t)(n * SSTR + kk + bcol) * 2;
                uint32_t bf[4];
                LDSM4(bf, bd);
#pragma unroll
                for (int mi = 0; mi < 2; mi++) {
                    mmaf16(acc[mi][2 * njp + 0], ah[mi], bf + 0);
                    mmaf16(acc[mi][2 * njp + 1], ah[mi], bf + 2);
                    mmaf16(acc[mi][2 * njp + 0], al[mi], bf + 0);
                    mmaf16(acc[mi][2 * njp + 1], al[mi], bf + 2);
                }
            }
        }
        int j1 = j0 + jt * 128;
#pragma unroll
        for (int mi = 0; mi < 2; mi++) {
#pragma unroll
            for (int nj = 0; nj < 8; nj++) {
                int r = i0 + wy * 32 + mi * 16 + (lane >> 2);
                int ncol = j1 + wx * 64 + nj * 8 + ((lane & 3) << 1);
                *(f162*)&Cb[(size_t)r * KL + ncol] =
                    __floats2half2_rn(acc[mi][nj][0] * 0.125f,
                                      acc[mi][nj][1] * 0.125f);
                *(f162*)&Cb[(size_t)(r + 8) * KL + ncol] =
                    __floats2half2_rn(acc[mi][nj][2] * 0.125f,
                                      acc[mi][nj][3] * 0.125f);
            }
        }
    }
}

// ---------------- bias kernels (pre-scaled by 0.125) ----------------
__global__ void bias_u_kernel(const f16* __restrict__ kH,
                              const f16* __restrict__ kL,
                              const float* __restrict__ u,
                              float* __restrict__ bU) {
    int idx = blockIdx.x * 256 + threadIdx.x;
    int bh = idx >> 11, j = idx & 2047;
    int b = bh >> 4, h = bh & 15;
    const f16* ph = kH + (size_t)(b * KL + j) * D3 + DM + h * DK;
    const f16* pl = kL + (size_t)(b * KL + j) * D3 + DM + h * DK;
    const float* uu = u + h * DK;
    float s = 0.0f;
#pragma unroll
    for (int d = 0; d < DK; d++)
        s += (__half2float(ph[d]) + __half2float(pl[d])) * uu[d];
    bU[idx] = s * 0.125f;
}
__global__ void bias_v_kernel(const f16* __restrict__ rpH,
                              const f16* __restrict__ rpL,
                              const float* __restrict__ v,
                              float* __restrict__ bV) {
    int idx = blockIdx.x * 256 + threadIdx.x;
    int h = idx >> 11, p = idx & 2047;
    const f16* ph = rpH + (size_t)p * DM + h * DK;
    const f16* pl = rpL + (size_t)p * DM + h * DK;
    const float* vv = v + h * DK;
    float s = 0.0f;
#pragma unroll
    for (int d = 0; d < DK; d++)
        s += (__half2float(ph[d]) + __half2float(pl[d])) * vv[d];
    bV[idx] = s * 0.125f;
}

// ---------------- fused shift+bias+mask+softmax -> fp16 weights -------------
__global__ __launch_bounds__(256)
void fused_softmax3(const f16* __restrict__ AC, const f16* __restrict__ U,
                    const float* __restrict__ bU, const float* __restrict__ bV,
                    f16* __restrict__ WT) {
    int rid = blockIdx.x;
    int bh = rid >> 10, h = bh & 15, i = rid & 1023;
    const f16* p = AC + (size_t)rid * KL;
    const f16* q = U + (size_t)rid * KL + (QL - 1 - i);   // NOTE: odd offset — scalar loads only
    const float* bu = bU + bh * KL;
    const float* bv = bV + h * KL + (QL - 1 - i);
    int jmax = i + MEML;
    int tile_end = (i & ~127) + 128 + MEML;
    int tid = threadIdx.x;
    __shared__ float red[256];
    float x[8];
    float mx = -INFINITY;
#pragma unroll
    for (int t = 0; t < 4; t++) {
        int j = 2 * (tid + t * 256);
        float x0 = -INFINITY, x1 = -INFINITY;
        if (j < jmax) {                 // full pair valid
            f162 pv = *(const f162*)(p + j);
            float2 buv = *(const float2*)(bu + j);
            x0 = __half2float(pv.x) + buv.x + __half2float(q[j]) + bv[j];
            x1 = __half2float(pv.y) + buv.y + __half2float(q[j + 1]) + bv[j + 1];
        } else if (j == jmax) {         // edge: first element only
            x0 = __half2float(p[j]) + bu[j] + __half2float(q[j]) + bv[j];
        }
        x[2 * t + 0] = x0;
        x[2 * t + 1] = x1;
        mx = fmaxf(mx, fmaxf(x0, x1));
    }
    red[tid] = mx;
    __syncthreads();
    for (int s = 128; s > 0; s >>= 1) {
        if (tid < s) red[tid] = fmaxf(red[tid], red[tid + s]);
        __syncthreads();
    }
    mx = red[0];
    __syncthreads();
    float sum = 0.0f;
#pragma unroll
    for (int t = 0; t < 8; t++) {
        x[t] = __expf(x[t] - mx);
        sum += x[t];
    }
    red[tid] = sum;
    __syncthreads();
    for (int s = 128; s > 0; s >>= 1) {
        if (tid < s) red[tid] += red[tid + s];
        __syncthreads();
    }
    float inv = 1.0f / red[0];
    f16* w = WT + (size_t)rid * KL;
#pragma unroll
    for (int t = 0; t < 4; t++) {
        int j = 2 * (tid + t * 256);
        if (j < tile_end)
            *(f162*)(w + j) = __floats2half2_rn(x[2 * t] * inv, x[2 * t + 1] * inv);
    }
}

// ---------------------------------------------------------------------------
extern "C" void kernel_launch(void* const* d_in, const int* in_sizes, int n_in,
                              void* d_out, int out_size) {
    const float* inputs     = (const float*)d_in[0];
    const float* inputs_mem = (const float*)d_in[1];
    const float* r          = (const float*)d_in[2];
    const float* W          = (const float*)d_in[3];
    const float* W_r        = (const float*)d_in[4];
    const float* W_o        = (const float*)d_in[5];
    const float* u          = (const float*)d_in[6];
    const float* v          = (const float*)d_in[7];
    float* out = (float*)d_out;

    f16 *catH, *catL, *W1, *Wr1, *Wo1, *rsH, *rsL;
    f16 *qkvH, *qkvL, *rpH, *rpL, *attnH, *attnL, *wt, *scores, *bdu;
    float *biasU, *biasV;
    cudaGetSymbolAddress((void**)&catH, g_catH);  cudaGetSymbolAddress((void**)&catL, g_catL);
    cudaGetSymbolAddress((void**)&W1, g_W1);
    cudaGetSymbolAddress((void**)&Wr1, g_Wr1);
    cudaGetSymbolAddress((void**)&Wo1, g_Wo1);
    cudaGetSymbolAddress((void**)&rsH, g_rsH);    cudaGetSymbolAddress((void**)&rsL, g_rsL);
    cudaGetSymbolAddress((void**)&qkvH, g_qkvH);  cudaGetSymbolAddress((void**)&qkvL, g_qkvL);
    cudaGetSymbolAddress((void**)&rpH, g_rpH);    cudaGetSymbolAddress((void**)&rpL, g_rpL);
    cudaGetSymbolAddress((void**)&attnH, g_attnH);cudaGetSymbolAddress((void**)&attnL, g_attnL);
    cudaGetSymbolAddress((void**)&wt, g_wt);
    cudaGetSymbolAddress((void**)&scores, g_scores);
    cudaGetSymbolAddress((void**)&bdu, g_bdu);
    cudaGetSymbolAddress((void**)&biasU, g_biasU);
    cudaGetSymbolAddress((void**)&biasV, g_biasV);

    // smem sizes (bytes): stage = ANP*APL2 + BNP*32*(NT+8), 2 stages, fp16
    const int SM_A128 = (2 * APL2 + 32 * 136) * 2 * 2;   // 58368
    const int SM_AT   = (APL2 + 2 * 32 * 72) * 2 * 2;    // 38912
    const int SMSC    = 4 * SPL * 2;                     // 73728
    cudaFuncSetAttribute(gemm_f16<128, 1, 0, 0, 1>, cudaFuncAttributeMaxDynamicSharedMemorySize, SM_A128);
    cudaFuncSetAttribute(gemm_f16<128, 1, 0, 2, 1>, cudaFuncAttributeMaxDynamicSharedMemorySize, SM_A128);
    cudaFuncSetAttribute(gemm_f16<128, 1, 0, 0, 0>, cudaFuncAttributeMaxDynamicSharedMemorySize, SM_A128);
    cudaFuncSetAttribute(gemm_f16<64, 0, 1, 1, 1>,  cudaFuncAttributeMaxDynamicSharedMemorySize, SM_AT);
    cudaFuncSetAttribute(score_f16, cudaFuncAttributeMaxDynamicSharedMemorySize, SMSC);

    // 0. ingest
    split_single<<<DM * D3 / 2 / 256, 256>>>(W, W1, DM * D3 / 2);
    split_single<<<DM * DM / 2 / 256, 256>>>(W_r, Wr1, DM * DM / 2);
    split_single<<<DM * DM / 2 / 256, 256>>>(W_o, Wo1, DM * DM / 2);
    split_pair<<<KL * DM / 2 / 256, 256>>>(r, rsH, rsL, KL * DM / 2);
    build_cat_split<<<BB * KL * DM / 2 / 256, 256>>>(inputs, inputs_mem, catH, catL);
    // 1a. KV part of qkv: all 4096 rows x cols [DM, 3DM)
    gemm_f16<128, 1, 0, 0, 1><<<dim3(2 * DM / 128, BB * KL / 128), 256, SM_A128>>>(
        catH, catL, W1 + DM, nullptr, nullptr, qkvH + DM, qkvL + DM, DM, DM, D3, D3);
    // 1b. Q part: query rows only x cols [0, DM)
    gemm_f16<128, 1, 0, 2, 1><<<dim3(DM / 128, BB * QL / 128), 256, SM_A128>>>(
        catH, catL, W1, nullptr, nullptr, qkvH, qkvL, DM, DM, D3, D3);
    // 2. rproj = r @ W_r -> planes
    gemm_f16<128, 1, 0, 0, 1><<<dim3(DM / 128, KL / 128), 256, SM_A128>>>(
        rsH, rsL, Wr1, nullptr, nullptr, rpH, rpL, DM, DM, DM, DM);
    // 3. biases (pre-scaled)
    bias_u_kernel<<<BB * NH * KL / 256, 256>>>(qkvH, qkvL, u, biasU);
    bias_v_kernel<<<NH * KL / 256, 256>>>(rpH, rpL, v, biasV);
    // 4. merged score GEMMs: z<32 AC, z>=32 BD  (fp16 out, pre-scaled)
    score_f16<<<dim3(KL / 256, QL / 128, 2 * BB * NH), 256, SMSC>>>(
        qkvH, qkvL, rpH, scores, bdu);
    // 5. fused shift+bias+mask+softmax -> fp16 weights
    fused_softmax3<<<BB * NH * QL, 256>>>(scores, bdu, biasU, biasV, wt);
    // 6. attn = weights @ V  (A single, B split trans) -> planes, K clamped
    gemm_f16<64, 0, 1, 1, 1><<<dim3(1, QL / 128, BB * NH), 256, SM_AT>>>(
        wt, nullptr, qkvH + 2 * DM, qkvL + 2 * DM, nullptr, attnH, attnL,
        KL, KL, D3, DM);
    // 7. out = attn @ W_o (A split, B single, fp32 out)
    gemm_f16<128, 1, 0, 0, 0><<<dim3(DM / 128, BB * QL / 128), 256, SM_A128>>>(
        attnH, attnL, Wo1, nullptr, out, nullptr, nullptr, DM, DM, DM, DM);
}

// round 11
// speedup vs baseline: 3.2232x; 1.0239x over previous
#include <cuda_runtime.h>
#include <cuda_fp16.h>
#include <math.h>
#include <stdint.h>

#define BB    2
#define QL    1024
#define MEML  1024
#define KL    2048
#define DM    1024
#define NH    16
#define DK    64
#define D3    3072

typedef __half  f16;
typedef __half2 f162;

// ---------------- scratch (device globals, no allocation) ----------------
__device__ f16 g_catH[BB * KL * DM], g_catL[BB * KL * DM];
__device__ f16 g_W1[DM * D3];
__device__ f16 g_Wr1[DM * DM];
__device__ f16 g_Wo1[DM * DM];
__device__ f16 g_rsH[KL * DM], g_rsL[KL * DM];
__device__ f16 g_qkvH[BB * KL * D3], g_qkvL[BB * KL * D3];
__device__ f16 g_rpH[KL * DM], g_rpL[KL * DM];
__device__ f16 g_attnH[BB * QL * DM], g_attnL[BB * QL * DM];
__device__ f16 g_scores[(size_t)BB * NH * QL * KL];   // AC * 0.125, fp16
__device__ f16 g_bdu[(size_t)BB * NH * QL * KL];      // Q@R^T * 0.125, fp16
__device__ f16 g_wt[(size_t)BB * NH * QL * KL];       // softmax weights, fp16
__device__ float g_biasU[BB * NH * KL];
__device__ float g_biasV[NH * KL];

// ---------------- helpers ----------------
__device__ __forceinline__ void split1(float x, f16& h, f16& l) {
    h = __float2half_rn(x);
    l = __float2half_rn(x - __half2float(h));
}
__device__ __forceinline__ void cp16(uint32_t dst, const void* src) {
    asm volatile("cp.async.cg.shared.global [%0], [%1], 16;\n" :: "r"(dst), "l"(src));
}
__device__ __forceinline__ void cp_commit() {
    asm volatile("cp.async.commit_group;\n");
}
__device__ __forceinline__ void cp_wait0() {
    asm volatile("cp.async.wait_group 0;\n");
}
__device__ __forceinline__ void cp_wait1() {
    asm volatile("cp.async.wait_group 1;\n");
}
__device__ __forceinline__ void mmaf16(float* d, const uint32_t* a,
                                       const uint32_t* b) {
    asm volatile(
        "mma.sync.aligned.m16n8k16.row.col.f32.f16.f16.f32 "
        "{%0,%1,%2,%3}, {%4,%5,%6,%7}, {%8,%9}, {%0,%1,%2,%3};"
        : "+f"(d[0]), "+f"(d[1]), "+f"(d[2]), "+f"(d[3])
        : "r"(a[0]), "r"(a[1]), "r"(a[2]), "r"(a[3]), "r"(b[0]), "r"(b[1]));
}
#define LDSM4(R, addr)                                                        \
    asm volatile("ldmatrix.sync.aligned.m8n8.x4.shared.b16 {%0,%1,%2,%3}, [%4];" \
                 : "=r"((R)[0]), "=r"((R)[1]), "=r"((R)[2]), "=r"((R)[3])     \
                 : "r"(addr))
#define LDSM4T(R, addr)                                                       \
    asm volatile("ldmatrix.sync.aligned.m8n8.x4.trans.shared.b16 {%0,%1,%2,%3}, [%4];" \
                 : "=r"((R)[0]), "=r"((R)[1]), "=r"((R)[2]), "=r"((R)[3])     \
                 : "r"(addr))

extern __shared__ __align__(16) char dynsm[];

// ---------------- ingest kernels ----------------
__global__ void split_single(const float* __restrict__ src,
                             f16* __restrict__ H, int n2) {
    int i = blockIdx.x * 256 + threadIdx.x;
    if (i >= n2) return;
    float2 v = *(const float2*)(src + 2 * (size_t)i);
    *(f162*)(H + 2 * (size_t)i) = __floats2half2_rn(v.x, v.y);
}
__global__ void split_pair(const float* __restrict__ src,
                           f16* __restrict__ H, f16* __restrict__ L, int n2) {
    int i = blockIdx.x * 256 + threadIdx.x;
    if (i >= n2) return;
    float2 v = *(const float2*)(src + 2 * (size_t)i);
    f16 h0, l0, h1, l1;
    split1(v.x, h0, l0); split1(v.y, h1, l1);
    f162 vh; vh.x = h0; vh.y = h1;
    f162 vl; vl.x = l0; vl.y = l1;
    *(f162*)(H + 2 * (size_t)i) = vh;
    *(f162*)(L + 2 * (size_t)i) = vl;
}
__global__ void build_cat_split(const float* __restrict__ inp,
                                const float* __restrict__ mem,
                                f16* __restrict__ H, f16* __restrict__ L) {
    int idx = blockIdx.x * 256 + threadIdx.x;
    int per_b = KL * (DM / 2);
    int b = idx / per_b;
    int rem = idx - b * per_b;
    int t = rem / (DM / 2);
    int c = rem - t * (DM / 2);
    const float2* s;
    if (t < MEML) s = (const float2*)(mem + ((size_t)b * MEML + t) * DM) + c;
    else          s = (const float2*)(inp + ((size_t)b * QL + (t - MEML)) * DM) + c;
    float2 v = *s;
    f16 h0, l0, h1, l1;
    split1(v.x, h0, l0); split1(v.y, h1, l1);
    f162 vh; vh.x = h0; vh.y = h1;
    f162 vl; vl.x = l0; vl.y = l1;
    size_t o = ((size_t)b * KL + t) * DM + 2 * c;
    *(f162*)(H + o) = vh;
    *(f162*)(L + o) = vl;
}

// ---------------- unified fp16 GEMM (trans-B, 3-stage cp.async pipeline) ----
// A [m][k] (split if ASPL), B natural [k][n] (split if BSPL), ldmatrix.trans
// for B fragments. BM=128, BN=NT, BK=32, 256 thr (8 warps 4x2), 3 smem stages.
// MODE 1: per-(b,h) weights@V, K clamped past mask.
// MODE 2: Q-part of qkv: rows remapped to query rows only.
#define ASTR2 40
#define APL2  (128 * ASTR2)

template <int NT, int ASPL, int BSPL, int MODE, int COUT>
__global__ __launch_bounds__(256, 2)
void gemm_f16(const f16* __restrict__ AH, const f16* __restrict__ AL,
              const f16* __restrict__ BH, const f16* __restrict__ BL,
              float* __restrict__ C, f16* __restrict__ CH, f16* __restrict__ CL,
              int K, int lda, int ldb, int ldc) {
    constexpr int NTP = NT + 8;          // padded n-stride (16B-aligned rows)
    constexpr int BPL = 32 * NTP;        // B plane (halves) per stage
    constexpr int ANP = ASPL ? 2 : 1;
    constexpr int BNP = BSPL ? 2 : 1;
    constexpr int STG = ANP * APL2 + BNP * BPL;
    constexpr int NJ = NT / 16;
    int tid = threadIdx.x, lane = tid & 31, wid = tid >> 5;
    int wy = wid & 3, wx = wid >> 2;
    int m0, n0 = blockIdx.x * NT;

    if (MODE == 2) {
        int by = blockIdx.y, b = by >> 3;
        m0 = b * KL + MEML + (by & 7) * 128;     // query rows only
    } else {
        m0 = blockIdx.y * 128;
    }
    if (MODE == 1) {
        int z = blockIdx.z, b = z >> 4, h = z & 15;
        AH += (size_t)z * QL * KL;
        BH += (size_t)b * KL * D3 + (size_t)h * DK;
        BL += (size_t)b * KL * D3 + (size_t)h * DK;
        CH += (size_t)b * QL * DM + (size_t)h * DK;
        CL += (size_t)b * QL * DM + (size_t)h * DK;
    }
    const f16* AbH = AH + (size_t)m0 * lda;
    const f16* AbL = ASPL ? (AL + (size_t)m0 * lda) : nullptr;
    const f16* BbH = BH + n0;
    const f16* BbL = BSPL ? (BL + n0) : nullptr;

    int Klim = K;
    if (MODE == 1) { int km = (blockIdx.y * 128) + 128 + MEML; Klim = K < km ? K : km; }
    int NC = Klim >> 5;

    f16* sm = (f16*)dynsm;

    auto loadAB = [&](int k0, int s) {
        f16* base = sm + s * STG;
        uint32_t da = (uint32_t)__cvta_generic_to_shared(base);
        uint32_t db = da + ANP * APL2 * 2;
        // A: 128x32, 512 16B-chunks
#pragma unroll
        for (int it = 0; it < 2; it++) {
            int e = tid + it * 256;
            int row = e >> 2, ch = (e & 3) << 3;
            size_t src = (size_t)row * lda + k0 + ch;
            uint32_t doff = (uint32_t)(row * ASTR2 + ch) * 2;
            cp16(da + doff, AbH + src);
            if (ASPL) cp16(da + APL2 * 2 + doff, AbL + src);
        }
        // B: 32 x NT natural layout, NT/8 chunks per row
        constexpr int CPR = NT / 8;
        constexpr int ITB = (32 * CPR) / 256;
#pragma unroll
        for (int it = 0; it < ITB; it++) {
            int e = tid + it * 256;
            int kk = e / CPR, nb = (e % CPR) * 8;
            size_t src = (size_t)(k0 + kk) * ldb + nb;
            uint32_t doff = (uint32_t)(kk * NTP + nb) * 2;
            cp16(db + doff, BbH + src);
            if (BSPL) cp16(db + BPL * 2 + doff, BbL + src);
        }
    };

    float acc[2][NJ][4];
#pragma unroll
    for (int mi = 0; mi < 2; mi++)
#pragma unroll
        for (int nj = 0; nj < NJ; nj++)
#pragma unroll
            for (int q = 0; q < 4; q++) acc[mi][nj][q] = 0.0f;

    // 3-stage pipeline: preload chunks 0,1
    loadAB(0, 0); cp_commit();
    if (NC > 1) { loadAB(32, 1); cp_commit(); }

    int arow = (lane & 15);
    int acol = (lane & 16) >> 1;                 // 0 or 8
    int bln = ((lane >> 4) << 3);                // trans: n offset 0/8

    for (int c = 0; c < NC; c++) {
        if (c + 1 < NC) cp_wait1(); else cp_wait0();
        __syncthreads();
        if (c + 2 < NC) { loadAB((c + 2) << 5, (c + 2) % 3); cp_commit(); }
        int s = c % 3;
        uint32_t sa = (uint32_t)__cvta_generic_to_shared(sm + s * STG);
        uint32_t sb = sa + ANP * APL2 * 2;
#pragma unroll
        for (int kk = 0; kk < 32; kk += 16) {
            uint32_t ah[2][4], al[2][4];
#pragma unroll
            for (int mi = 0; mi < 2; mi++) {
                int r = wy * 32 + mi * 16 + arow;
                uint32_t ad = sa + (uint32_t)(r * ASTR2 + kk + acol) * 2;
                LDSM4(ah[mi], ad);
                if (ASPL) LDSM4(al[mi], ad + APL2 * 2);
            }
#pragma unroll
            for (int njp = 0; njp < NJ / 2; njp++) {
                int n16 = wx * (NT / 2) + njp * 16;
                uint32_t bd = sb +
                    (uint32_t)((kk + arow) * NTP + n16 + bln) * 2;
                uint32_t bf[4], blf[4];
                LDSM4T(bf, bd);
                if (BSPL) LDSM4T(blf, bd + BPL * 2);
#pragma unroll
                for (int mi = 0; mi < 2; mi++) {
                    mmaf16(acc[mi][2 * njp + 0], ah[mi], bf + 0);
                    mmaf16(acc[mi][2 * njp + 1], ah[mi], bf + 2);
                    if (ASPL) {
                        mmaf16(acc[mi][2 * njp + 0], al[mi], bf + 0);
                        mmaf16(acc[mi][2 * njp + 1], al[mi], bf + 2);
                    }
                    if (BSPL) {
                        mmaf16(acc[mi][2 * njp + 0], ah[mi], blf + 0);
                        mmaf16(acc[mi][2 * njp + 1], ah[mi], blf + 2);
                    }
                }
            }
        }
    }

#pragma unroll
    for (int mi = 0; mi < 2; mi++) {
#pragma unroll
        for (int nj = 0; nj < NJ; nj++) {
            int r = m0 + wy * 32 + mi * 16 + (lane >> 2);
            int ncol = n0 + wx * (NT / 2) + nj * 8 + ((lane & 3) << 1);
            if (COUT == 0) {
                *(float2*)&C[(size_t)r * ldc + ncol] =
                    make_float2(acc[mi][nj][0], acc[mi][nj][1]);
                *(float2*)&C[(size_t)(r + 8) * ldc + ncol] =
                    make_float2(acc[mi][nj][2], acc[mi][nj][3]);
            } else {
#pragma unroll
                for (int hh = 0; hh < 2; hh++) {
                    f16 h0, l0, h1, l1;
                    split1(acc[mi][nj][2 * hh + 0], h0, l0);
                    split1(acc[mi][nj][2 * hh + 1], h1, l1);
                    f162 vh; vh.x = h0; vh.y = h1;
                    f162 vl; vl.x = l0; vl.y = l1;
                    size_t o = (size_t)(r + 8 * hh) * ldc + ncol;
                    *(f162*)(CH + o) = vh;
                    *(f162*)(CL + o) = vl;
                }
            }
        }
    }
}

// ---------------- merged score GEMM: z<32 -> AC (Q@K^T), z>=32 -> BD --------
#define SSTR 72
#define SPL  (128 * SSTR)

__global__ __launch_bounds__(256, 2)
void score_f16(const f16* __restrict__ qH, const f16* __restrict__ qL,
               const f16* __restrict__ rp,
               f16* __restrict__ AC, f16* __restrict__ BD) {
    int z = blockIdx.z;
    int mode = (z >= BB * NH) ? 1 : 0;
    int bh = mode ? (z - BB * NH) : z;
    int b = bh >> 4, h = bh & 15;
    int i0 = blockIdx.y * 128, j0 = blockIdx.x * 256;
    bool act[2];
    if (mode == 0) {
        act[0] = (j0 - i0) < 1152;
        act[1] = (j0 + 128 - i0) < 1152;
        if (!act[0]) return;
    } else {
        act[0] = (i0 + j0) > 768;
        act[1] = (i0 + j0 + 128) > 768;
        if (!act[1]) return;
    }
    int tid = threadIdx.x, lane = tid & 31, wid = tid >> 5;
    int wy = wid & 3, wx = wid >> 2;

    f16* sm = (f16*)dynsm;
    {
        const f16* AbH = qH + (size_t)(b * KL + MEML + i0) * D3 + h * DK;
        const f16* AbL = qL + (size_t)(b * KL + MEML + i0) * D3 + h * DK;
        uint32_t dh = (uint32_t)__cvta_generic_to_shared(sm);
#pragma unroll
        for (int it = 0; it < 4; it++) {
            int e = tid + it * 256;
            int row = e >> 3, ch = (e & 7) << 3;
            size_t src = (size_t)row * D3 + ch;
            uint32_t doff = (uint32_t)(row * SSTR + ch) * 2;
            cp16(dh + doff, AbH + src);
            cp16(dh + SPL * 2 + doff, AbL + src);
        }
    }
#pragma unroll
    for (int jt = 0; jt < 2; jt++) {
        if (!act[jt]) continue;
        int j1 = j0 + jt * 128;
        const f16* Bb;
        size_t ldrow;
        if (mode == 0) { Bb = qH + (size_t)(b * KL + j1) * D3 + DM + h * DK; ldrow = D3; }
        else           { Bb = rp + (size_t)j1 * DM + h * DK; ldrow = DM; }
        uint32_t dh = (uint32_t)__cvta_generic_to_shared(sm + (2 + jt) * SPL);
#pragma unroll
        for (int it = 0; it < 4; it++) {
            int e = tid + it * 256;
            int row = e >> 3, ch = (e & 7) << 3;
            cp16(dh + (uint32_t)(row * SSTR + ch) * 2, Bb + (size_t)row * ldrow + ch);
        }
    }
    cp_commit();
    cp_wait0();
    __syncthreads();

    int arow = (lane & 15);
    int acol = (lane & 16) >> 1;
    int brow = (lane & 7) + ((lane & 16) >> 1);
    int bcol = (lane & 8);
    uint32_t sa = (uint32_t)__cvta_generic_to_shared(sm);

    f16* Cb = (mode ? BD : AC) + (size_t)bh * QL * KL;
#pragma unroll
    for (int jt = 0; jt < 2; jt++) {
        if (!act[jt]) continue;
        uint32_t sb = sa + (2 + jt) * SPL * 2;
        float acc[2][8][4];
#pragma unroll
        for (int mi = 0; mi < 2; mi++)
#pragma unroll
            for (int nj = 0; nj < 8; nj++)
#pragma unroll
                for (int q = 0; q < 4; q++) acc[mi][nj][q] = 0.0f;
#pragma unroll
        for (int kk = 0; kk < 64; kk += 16) {
            uint32_t ah[2][4], al[2][4];
#pragma unroll
            for (int mi = 0; mi < 2; mi++) {
                int r = wy * 32 + mi * 16 + arow;
                uint32_t ad = sa + (uint32_t)(r * SSTR + kk + acol) * 2;
                LDSM4(ah[mi], ad);
                LDSM4(al[mi], ad + SPL * 2);
            }
#pragma unroll
            for (int njp = 0; njp < 4; njp++) {
                int n = wx * 64 + njp * 16 + brow;
                uint32_t bd = sb + (uint32_t)(n * SSTR + kk + bcol) * 2;
                uint32_t bf[4];
                LDSM4(bf, bd);
#pragma unroll
                for (int mi = 0; mi < 2; mi++) {
                    mmaf16(acc[mi][2 * njp + 0], ah[mi], bf + 0);
                    mmaf16(acc[mi][2 * njp + 1], ah[mi], bf + 2);
                    mmaf16(acc[mi][2 * njp + 0], al[mi], bf + 0);
                    mmaf16(acc[mi][2 * njp + 1], al[mi], bf + 2);
                }
            }
        }
        int j1 = j0 + jt * 128;
#pragma unroll
        for (int mi = 0; mi < 2; mi++) {
#pragma unroll
            for (int nj = 0; nj < 8; nj++) {
                int r = i0 + wy * 32 + mi * 16 + (lane >> 2);
                int ncol = j1 + wx * 64 + nj * 8 + ((lane & 3) << 1);
                *(f162*)&Cb[(size_t)r * KL + ncol] =
                    __floats2half2_rn(acc[mi][nj][0] * 0.125f,
                                      acc[mi][nj][1] * 0.125f);
                *(f162*)&Cb[(size_t)(r + 8) * KL + ncol] =
                    __floats2half2_rn(acc[mi][nj][2] * 0.125f,
                                      acc[mi][nj][3] * 0.125f);
            }
        }
    }
}

// ---------------- bias kernels (pre-scaled by 0.125) ----------------
__global__ void bias_u_kernel(const f16* __restrict__ kH,
                              const f16* __restrict__ kL,
                              const float* __restrict__ u,
                              float* __restrict__ bU) {
    int idx = blockIdx.x * 256 + threadIdx.x;
    int bh = idx >> 11, j = idx & 2047;
    int b = bh >> 4, h = bh & 15;
    const f16* ph = kH + (size_t)(b * KL + j) * D3 + DM + h * DK;
    const f16* pl = kL + (size_t)(b * KL + j) * D3 + DM + h * DK;
    const float* uu = u + h * DK;
    float s = 0.0f;
#pragma unroll
    for (int d = 0; d < DK; d++)
        s += (__half2float(ph[d]) + __half2float(pl[d])) * uu[d];
    bU[idx] = s * 0.125f;
}
__global__ void bias_v_kernel(const f16* __restrict__ rpH,
                              const f16* __restrict__ rpL,
                              const float* __restrict__ v,
                              float* __restrict__ bV) {
    int idx = blockIdx.x * 256 + threadIdx.x;
    int h = idx >> 11, p = idx & 2047;
    const f16* ph = rpH + (size_t)p * DM + h * DK;
    const f16* pl = rpL + (size_t)p * DM + h * DK;
    const float* vv = v + h * DK;
    float s = 0.0f;
#pragma unroll
    for (int d = 0; d < DK; d++)
        s += (__half2float(ph[d]) + __half2float(pl[d])) * vv[d];
    bV[idx] = s * 0.125f;
}

// ---------------- fused shift+bias+mask+softmax -> fp16 weights -------------
__global__ __launch_bounds__(256)
void fused_softmax3(const f16* __restrict__ AC, const f16* __restrict__ U,
                    const float* __restrict__ bU, const float* __restrict__ bV,
                    f16* __restrict__ WT) {
    int rid = blockIdx.x;
    int bh = rid >> 10, h = bh & 15, i = rid & 1023;
    const f16* p = AC + (size_t)rid * KL;
    const f16* q = U + (size_t)rid * KL + (QL - 1 - i);   // odd offset — scalar loads only
    const float* bu = bU + bh * KL;
    const float* bv = bV + h * KL + (QL - 1 - i);
    int jmax = i + MEML;
    int tile_end = (i & ~127) + 128 + MEML;
    int tid = threadIdx.x;
    __shared__ float red[256];
    float x[8];
    float mx = -INFINITY;
#pragma unroll
    for (int t = 0; t < 4; t++) {
        int j = 2 * (tid + t * 256);
        float x0 = -INFINITY, x1 = -INFINITY;
        if (j < jmax) {                 // full pair valid
            f162 pv = *(const f162*)(p + j);
            float2 buv = *(const float2*)(bu + j);
            x0 = __half2float(pv.x) + buv.x + __half2float(q[j]) + bv[j];
            x1 = __half2float(pv.y) + buv.y + __half2float(q[j + 1]) + bv[j + 1];
        } else if (j == jmax) {         // edge: first element only
            x0 = __half2float(p[j]) + bu[j] + __half2float(q[j]) + bv[j];
        }
        x[2 * t + 0] = x0;
        x[2 * t + 1] = x1;
        mx = fmaxf(mx, fmaxf(x0, x1));
    }
    red[tid] = mx;
    __syncthreads();
    for (int s = 128; s > 0; s >>= 1) {
        if (tid < s) red[tid] = fmaxf(red[tid], red[tid + s]);
        __syncthreads();
    }
    mx = red[0];
    __syncthreads();
    float sum = 0.0f;
#pragma unroll
    for (int t = 0; t < 8; t++) {
        x[t] = __expf(x[t] - mx);
        sum += x[t];
    }
    red[tid] = sum;
    __syncthreads();
    for (int s = 128; s > 0; s >>= 1) {
        if (tid < s) red[tid] += red[tid + s];
        __syncthreads();
    }
    float inv = 1.0f / red[0];
    f16* w = WT + (size_t)rid * KL;
#pragma unroll
    for (int t = 0; t < 4; t++) {
        int j = 2 * (tid + t * 256);
        if (j < tile_end)
            *(f162*)(w + j) = __floats2half2_rn(x[2 * t] * inv, x[2 * t + 1] * inv);
    }
}

// ---------------------------------------------------------------------------
extern "C" void kernel_launch(void* const* d_in, const int* in_sizes, int n_in,
                              void* d_out, int out_size) {
    const float* inputs     = (const float*)d_in[0];
    const float* inputs_mem = (const float*)d_in[1];
    const float* r          = (const float*)d_in[2];
    const float* W          = (const float*)d_in[3];
    const float* W_r        = (const float*)d_in[4];
    const float* W_o        = (const float*)d_in[5];
    const float* u          = (const float*)d_in[6];
    const float* v          = (const float*)d_in[7];
    float* out = (float*)d_out;

    f16 *catH, *catL, *W1, *Wr1, *Wo1, *rsH, *rsL;
    f16 *qkvH, *qkvL, *rpH, *rpL, *attnH, *attnL, *wt, *scores, *bdu;
    float *biasU, *biasV;
    cudaGetSymbolAddress((void**)&catH, g_catH);  cudaGetSymbolAddress((void**)&catL, g_catL);
    cudaGetSymbolAddress((void**)&W1, g_W1);
    cudaGetSymbolAddress((void**)&Wr1, g_Wr1);
    cudaGetSymbolAddress((void**)&Wo1, g_Wo1);
    cudaGetSymbolAddress((void**)&rsH, g_rsH);    cudaGetSymbolAddress((void**)&rsL, g_rsL);
    cudaGetSymbolAddress((void**)&qkvH, g_qkvH);  cudaGetSymbolAddress((void**)&qkvL, g_qkvL);
    cudaGetSymbolAddress((void**)&rpH, g_rpH);    cudaGetSymbolAddress((void**)&rpL, g_rpL);
    cudaGetSymbolAddress((void**)&attnH, g_attnH);cudaGetSymbolAddress((void**)&attnL, g_attnL);
    cudaGetSymbolAddress((void**)&wt, g_wt);
    cudaGetSymbolAddress((void**)&scores, g_scores);
    cudaGetSymbolAddress((void**)&bdu, g_bdu);
    cudaGetSymbolAddress((void**)&biasU, g_biasU);
    cudaGetSymbolAddress((void**)&biasV, g_biasV);

    // smem sizes (bytes): stage = ANP*APL2 + BNP*32*(NT+8), 3 stages, fp16
    const int SM_A128 = (2 * APL2 + 32 * 136) * 3 * 2;   // 87552
    const int SM_AT   = (APL2 + 2 * 32 * 72) * 3 * 2;    // 58368
    const int SMSC    = 4 * SPL * 2;                     // 73728
    cudaFuncSetAttribute(gemm_f16<128, 1, 0, 0, 1>, cudaFuncAttributeMaxDynamicSharedMemorySize, SM_A128);
    cudaFuncSetAttribute(gemm_f16<128, 1, 0, 2, 1>, cudaFuncAttributeMaxDynamicSharedMemorySize, SM_A128);
    cudaFuncSetAttribute(gemm_f16<128, 1, 0, 0, 0>, cudaFuncAttributeMaxDynamicSharedMemorySize, SM_A128);
    cudaFuncSetAttribute(gemm_f16<64, 0, 1, 1, 1>,  cudaFuncAttributeMaxDynamicSharedMemorySize, SM_AT);
    cudaFuncSetAttribute(score_f16, cudaFuncAttributeMaxDynamicSharedMemorySize, SMSC);

    // 0. ingest
    split_single<<<DM * D3 / 2 / 256, 256>>>(W, W1, DM * D3 / 2);
    split_single<<<DM * DM / 2 / 256, 256>>>(W_r, Wr1, DM * DM / 2);
    split_single<<<DM * DM / 2 / 256, 256>>>(W_o, Wo1, DM * DM / 2);
    split_pair<<<KL * DM / 2 / 256, 256>>>(r, rsH, rsL, KL * DM / 2);
    build_cat_split<<<BB * KL * DM / 2 / 256, 256>>>(inputs, inputs_mem, catH, catL);
    // 1a. KV part of qkv: all 4096 rows x cols [DM, 3DM)
    gemm_f16<128, 1, 0, 0, 1><<<dim3(2 * DM / 128, BB * KL / 128), 256, SM_A128>>>(
        catH, catL, W1 + DM, nullptr, nullptr, qkvH + DM, qkvL + DM, DM, DM, D3, D3);
    // 1b. Q part: query rows only x cols [0, DM)
    gemm_f16<128, 1, 0, 2, 1><<<dim3(DM / 128, BB * QL / 128), 256, SM_A128>>>(
        catH, catL, W1, nullptr, nullptr, qkvH, qkvL, DM, DM, D3, D3);
    // 2. rproj = r @ W_r -> planes
    gemm_f16<128, 1, 0, 0, 1><<<dim3(DM / 128, KL / 128), 256, SM_A128>>>(
        rsH, rsL, Wr1, nullptr, nullptr, rpH, rpL, DM, DM, DM, DM);
    // 3. biases (pre-scaled)
    bias_u_kernel<<<BB * NH * KL / 256, 256>>>(qkvH, qkvL, u, biasU);
    bias_v_kernel<<<NH * KL / 256, 256>>>(rpH, rpL, v, biasV);
    // 4. merged score GEMMs: z<32 AC, z>=32 BD  (fp16 out, pre-scaled)
    score_f16<<<dim3(KL / 256, QL / 128, 2 * BB * NH), 256, SMSC>>>(
        qkvH, qkvL, rpH, scores, bdu);
    // 5. fused shift+bias+mask+softmax -> fp16 weights
    fused_softmax3<<<BB * NH * QL, 256>>>(scores, bdu, biasU, biasV, wt);
    // 6. attn = weights @ V  (A single, B split trans) -> planes, K clamped
    gemm_f16<64, 0, 1, 1, 1><<<dim3(1, QL / 128, BB * NH), 256, SM_AT>>>(
        wt, nullptr, qkvH + 2 * DM, qkvL + 2 * DM, nullptr, attnH, attnL,
        KL, KL, D3, DM);
    // 7. out = attn @ W_o (A split, B single, fp32 out)
    gemm_f16<128, 1, 0, 0, 0><<<dim3(DM / 128, BB * QL / 128), 256, SM_A128>>>(
        attnH, attnL, Wo1, nullptr, out, nullptr, nullptr, DM, DM, DM, DM);
}

// round 12
// speedup vs baseline: 3.4335x; 1.0653x over previous
#include <cuda_runtime.h>
#include <cuda_fp16.h>
#include <math.h>
#include <stdint.h>

#define BB    2
#define QL    1024
#define MEML  1024
#define KL    2048
#define DM    1024
#define NH    16
#define DK    64
#define D3    3072

typedef __half  f16;
typedef __half2 f162;

// ---------------- scratch (device globals, no allocation) ----------------
__device__ f16 g_catH[BB * KL * DM], g_catL[BB * KL * DM];
__device__ f16 g_W1[DM * D3];
__device__ f16 g_Wr1[DM * DM];
__device__ f16 g_Wo1[DM * DM];
__device__ f16 g_rsH[KL * DM], g_rsL[KL * DM];
__device__ f16 g_qkvH[BB * KL * D3], g_qkvL[BB * KL * D3];
__device__ f16 g_rpH[KL * DM], g_rpL[KL * DM];
__device__ f16 g_attnH[BB * QL * DM], g_attnL[BB * QL * DM];
__device__ f16 g_scores[(size_t)BB * NH * QL * KL];   // AC * 0.125, fp16
__device__ f16 g_bdu[(size_t)BB * NH * QL * KL];      // Q@R^T * 0.125, fp16
__device__ f16 g_wt[(size_t)BB * NH * QL * KL];       // softmax weights, fp16
__device__ float g_biasU[BB * NH * KL];
__device__ float g_biasV[NH * KL];

// ---------------- helpers ----------------
__device__ __forceinline__ void split1(float x, f16& h, f16& l) {
    h = __float2half_rn(x);
    l = __float2half_rn(x - __half2float(h));
}
__device__ __forceinline__ void cp16(uint32_t dst, const void* src) {
    asm volatile("cp.async.cg.shared.global [%0], [%1], 16;\n" :: "r"(dst), "l"(src));
}
__device__ __forceinline__ void cp_commit() {
    asm volatile("cp.async.commit_group;\n");
}
__device__ __forceinline__ void cp_wait0() {
    asm volatile("cp.async.wait_group 0;\n");
}
__device__ __forceinline__ void cp_wait1() {
    asm volatile("cp.async.wait_group 1;\n");
}
__device__ __forceinline__ void mmaf16(float* d, const uint32_t* a,
                                       const uint32_t* b) {
    asm volatile(
        "mma.sync.aligned.m16n8k16.row.col.f32.f16.f16.f32 "
        "{%0,%1,%2,%3}, {%4,%5,%6,%7}, {%8,%9}, {%0,%1,%2,%3};"
        : "+f"(d[0]), "+f"(d[1]), "+f"(d[2]), "+f"(d[3])
        : "r"(a[0]), "r"(a[1]), "r"(a[2]), "r"(a[3]), "r"(b[0]), "r"(b[1]));
}
#define LDSM4(R, addr)                                                        \
    asm volatile("ldmatrix.sync.aligned.m8n8.x4.shared.b16 {%0,%1,%2,%3}, [%4];" \
                 : "=r"((R)[0]), "=r"((R)[1]), "=r"((R)[2]), "=r"((R)[3])     \
                 : "r"(addr))
#define LDSM4T(R, addr)                                                       \
    asm volatile("ldmatrix.sync.aligned.m8n8.x4.trans.shared.b16 {%0,%1,%2,%3}, [%4];" \
                 : "=r"((R)[0]), "=r"((R)[1]), "=r"((R)[2]), "=r"((R)[3])     \
                 : "r"(addr))

extern __shared__ __align__(16) char dynsm[];

// ---------------- ingest kernels ----------------
__global__ void split_single(const float* __restrict__ src,
                             f16* __restrict__ H, int n2) {
    int i = blockIdx.x * 256 + threadIdx.x;
    if (i >= n2) return;
    float2 v = *(const float2*)(src + 2 * (size_t)i);
    *(f162*)(H + 2 * (size_t)i) = __floats2half2_rn(v.x, v.y);
}
__global__ void split_pair(const float* __restrict__ src,
                           f16* __restrict__ H, f16* __restrict__ L, int n2) {
    int i = blockIdx.x * 256 + threadIdx.x;
    if (i >= n2) return;
    float2 v = *(const float2*)(src + 2 * (size_t)i);
    f16 h0, l0, h1, l1;
    split1(v.x, h0, l0); split1(v.y, h1, l1);
    f162 vh; vh.x = h0; vh.y = h1;
    f162 vl; vl.x = l0; vl.y = l1;
    *(f162*)(H + 2 * (size_t)i) = vh;
    *(f162*)(L + 2 * (size_t)i) = vl;
}
__global__ void build_cat_split(const float* __restrict__ inp,
                                const float* __restrict__ mem,
                                f16* __restrict__ H, f16* __restrict__ L) {
    int idx = blockIdx.x * 256 + threadIdx.x;
    int per_b = KL * (DM / 2);
    int b = idx / per_b;
    int rem = idx - b * per_b;
    int t = rem / (DM / 2);
    int c = rem - t * (DM / 2);
    const float2* s;
    if (t < MEML) s = (const float2*)(mem + ((size_t)b * MEML + t) * DM) + c;
    else          s = (const float2*)(inp + ((size_t)b * QL + (t - MEML)) * DM) + c;
    float2 v = *s;
    f16 h0, l0, h1, l1;
    split1(v.x, h0, l0); split1(v.y, h1, l1);
    f162 vh; vh.x = h0; vh.y = h1;
    f162 vl; vl.x = l0; vl.y = l1;
    size_t o = ((size_t)b * KL + t) * DM + 2 * c;
    *(f162*)(H + o) = vh;
    *(f162*)(L + o) = vl;
}

// ---------------- unified fp16 GEMM (trans-B, 3-stage cp.async pipeline) ----
#define ASTR2 40
#define APL2  (128 * ASTR2)

template <int NT, int ASPL, int BSPL, int MODE, int COUT>
__global__ __launch_bounds__(256, 2)
void gemm_f16(const f16* __restrict__ AH, const f16* __restrict__ AL,
              const f16* __restrict__ BH, const f16* __restrict__ BL,
              float* __restrict__ C, f16* __restrict__ CH, f16* __restrict__ CL,
              int K, int lda, int ldb, int ldc) {
    constexpr int NTP = NT + 8;
    constexpr int BPL = 32 * NTP;
    constexpr int ANP = ASPL ? 2 : 1;
    constexpr int BNP = BSPL ? 2 : 1;
    constexpr int STG = ANP * APL2 + BNP * BPL;
    constexpr int NJ = NT / 16;
    int tid = threadIdx.x, lane = tid & 31, wid = tid >> 5;
    int wy = wid & 3, wx = wid >> 2;
    int m0, n0 = blockIdx.x * NT;

    if (MODE == 2) {
        int by = blockIdx.y, b = by >> 3;
        m0 = b * KL + MEML + (by & 7) * 128;     // query rows only
    } else {
        m0 = blockIdx.y * 128;
    }
    if (MODE == 1) {
        int z = blockIdx.z, b = z >> 4, h = z & 15;
        AH += (size_t)z * QL * KL;
        BH += (size_t)b * KL * D3 + (size_t)h * DK;
        if (BSPL) BL += (size_t)b * KL * D3 + (size_t)h * DK;
        CH += (size_t)b * QL * DM + (size_t)h * DK;
        CL += (size_t)b * QL * DM + (size_t)h * DK;
    }
    const f16* AbH = AH + (size_t)m0 * lda;
    const f16* AbL = ASPL ? (AL + (size_t)m0 * lda) : nullptr;
    const f16* BbH = BH + n0;
    const f16* BbL = BSPL ? (BL + n0) : nullptr;

    int Klim = K;
    if (MODE == 1) { int km = (blockIdx.y * 128) + 128 + MEML; Klim = K < km ? K : km; }
    int NC = Klim >> 5;

    f16* sm = (f16*)dynsm;

    auto loadAB = [&](int k0, int s) {
        f16* base = sm + s * STG;
        uint32_t da = (uint32_t)__cvta_generic_to_shared(base);
        uint32_t db = da + ANP * APL2 * 2;
#pragma unroll
        for (int it = 0; it < 2; it++) {
            int e = tid + it * 256;
            int row = e >> 2, ch = (e & 3) << 3;
            size_t src = (size_t)row * lda + k0 + ch;
            uint32_t doff = (uint32_t)(row * ASTR2 + ch) * 2;
            cp16(da + doff, AbH + src);
            if (ASPL) cp16(da + APL2 * 2 + doff, AbL + src);
        }
        constexpr int CPR = NT / 8;
        constexpr int ITB = (32 * CPR) / 256;
#pragma unroll
        for (int it = 0; it < ITB; it++) {
            int e = tid + it * 256;
            int kk = e / CPR, nb = (e % CPR) * 8;
            size_t src = (size_t)(k0 + kk) * ldb + nb;
            uint32_t doff = (uint32_t)(kk * NTP + nb) * 2;
            cp16(db + doff, BbH + src);
            if (BSPL) cp16(db + BPL * 2 + doff, BbL + src);
        }
    };

    float acc[2][NJ][4];
#pragma unroll
    for (int mi = 0; mi < 2; mi++)
#pragma unroll
        for (int nj = 0; nj < NJ; nj++)
#pragma unroll
            for (int q = 0; q < 4; q++) acc[mi][nj][q] = 0.0f;

    loadAB(0, 0); cp_commit();
    if (NC > 1) { loadAB(32, 1); cp_commit(); }

    int arow = (lane & 15);
    int acol = (lane & 16) >> 1;
    int bln = ((lane >> 4) << 3);

    for (int c = 0; c < NC; c++) {
        if (c + 1 < NC) cp_wait1(); else cp_wait0();
        __syncthreads();
        if (c + 2 < NC) { loadAB((c + 2) << 5, (c + 2) % 3); cp_commit(); }
        int s = c % 3;
        uint32_t sa = (uint32_t)__cvta_generic_to_shared(sm + s * STG);
        uint32_t sb = sa + ANP * APL2 * 2;
#pragma unroll
        for (int kk = 0; kk < 32; kk += 16) {
            uint32_t ah[2][4], al[2][4];
#pragma unroll
            for (int mi = 0; mi < 2; mi++) {
                int r = wy * 32 + mi * 16 + arow;
                uint32_t ad = sa + (uint32_t)(r * ASTR2 + kk + acol) * 2;
                LDSM4(ah[mi], ad);
                if (ASPL) LDSM4(al[mi], ad + APL2 * 2);
            }
#pragma unroll
            for (int njp = 0; njp < NJ / 2; njp++) {
                int n16 = wx * (NT / 2) + njp * 16;
                uint32_t bd = sb +
                    (uint32_t)((kk + arow) * NTP + n16 + bln) * 2;
                uint32_t bf[4], blf[4];
                LDSM4T(bf, bd);
                if (BSPL) LDSM4T(blf, bd + BPL * 2);
#pragma unroll
                for (int mi = 0; mi < 2; mi++) {
                    mmaf16(acc[mi][2 * njp + 0], ah[mi], bf + 0);
                    mmaf16(acc[mi][2 * njp + 1], ah[mi], bf + 2);
                    if (ASPL) {
                        mmaf16(acc[mi][2 * njp + 0], al[mi], bf + 0);
                        mmaf16(acc[mi][2 * njp + 1], al[mi], bf + 2);
                    }
                    if (BSPL) {
                        mmaf16(acc[mi][2 * njp + 0], ah[mi], blf + 0);
                        mmaf16(acc[mi][2 * njp + 1], ah[mi], blf + 2);
                    }
                }
            }
        }
    }

#pragma unroll
    for (int mi = 0; mi < 2; mi++) {
#pragma unroll
        for (int nj = 0; nj < NJ; nj++) {
            int r = m0 + wy * 32 + mi * 16 + (lane >> 2);
            int ncol = n0 + wx * (NT / 2) + nj * 8 + ((lane & 3) << 1);
            if (COUT == 0) {
                *(float2*)&C[(size_t)r * ldc + ncol] =
                    make_float2(acc[mi][nj][0], acc[mi][nj][1]);
                *(float2*)&C[(size_t)(r + 8) * ldc + ncol] =
                    make_float2(acc[mi][nj][2], acc[mi][nj][3]);
            } else {
#pragma unroll
                for (int hh = 0; hh < 2; hh++) {
                    f16 h0, l0, h1, l1;
                    split1(acc[mi][nj][2 * hh + 0], h0, l0);
                    split1(acc[mi][nj][2 * hh + 1], h1, l1);
                    f162 vh; vh.x = h0; vh.y = h1;
                    f162 vl; vl.x = l0; vl.y = l1;
                    size_t o = (size_t)(r + 8 * hh) * ldc + ncol;
                    *(f162*)(CH + o) = vh;
                    *(f162*)(CL + o) = vl;
                }
            }
        }
    }
}

// ---------------- merged score GEMM (single-plane Q): z<32 AC, z>=32 BD ----
#define SSTR 72
#define SPL  (128 * SSTR)

__global__ __launch_bounds__(256, 2)
void score_f16(const f16* __restrict__ qH, const f16* __restrict__ rp,
               f16* __restrict__ AC, f16* __restrict__ BD) {
    int z = blockIdx.z;
    int mode = (z >= BB * NH) ? 1 : 0;
    int bh = mode ? (z - BB * NH) : z;
    int b = bh >> 4, h = bh & 15;
    int i0 = blockIdx.y * 128, j0 = blockIdx.x * 256;
    bool act[2];
    if (mode == 0) {
        act[0] = (j0 - i0) < 1152;
        act[1] = (j0 + 128 - i0) < 1152;
        if (!act[0]) return;
    } else {
        act[0] = (i0 + j0) > 768;
        act[1] = (i0 + j0 + 128) > 768;
        if (!act[1]) return;
    }
    int tid = threadIdx.x, lane = tid & 31, wid = tid >> 5;
    int wy = wid & 3, wx = wid >> 2;

    f16* sm = (f16*)dynsm;
    {
        const f16* AbH = qH + (size_t)(b * KL + MEML + i0) * D3 + h * DK;
        uint32_t dh = (uint32_t)__cvta_generic_to_shared(sm);
#pragma unroll
        for (int it = 0; it < 4; it++) {
            int e = tid + it * 256;
            int row = e >> 3, ch = (e & 7) << 3;
            cp16(dh + (uint32_t)(row * SSTR + ch) * 2,
                 AbH + (size_t)row * D3 + ch);
        }
    }
#pragma unroll
    for (int jt = 0; jt < 2; jt++) {
        if (!act[jt]) continue;
        int j1 = j0 + jt * 128;
        const f16* Bb;
        size_t ldrow;
        if (mode == 0) { Bb = qH + (size_t)(b * KL + j1) * D3 + DM + h * DK; ldrow = D3; }
        else           { Bb = rp + (size_t)j1 * DM + h * DK; ldrow = DM; }
        uint32_t dh = (uint32_t)__cvta_generic_to_shared(sm + (1 + jt) * SPL);
#pragma unroll
        for (int it = 0; it < 4; it++) {
            int e = tid + it * 256;
            int row = e >> 3, ch = (e & 7) << 3;
            cp16(dh + (uint32_t)(row * SSTR + ch) * 2, Bb + (size_t)row * ldrow + ch);
        }
    }
    cp_commit();
    cp_wait0();
    __syncthreads();

    int arow = (lane & 15);
    int acol = (lane & 16) >> 1;
    int brow = (lane & 7) + ((lane & 16) >> 1);
    int bcol = (lane & 8);
    uint32_t sa = (uint32_t)__cvta_generic_to_shared(sm);

    f16* Cb = (mode ? BD : AC) + (size_t)bh * QL * KL;
#pragma unroll
    for (int jt = 0; jt < 2; jt++) {
        if (!act[jt]) continue;
        uint32_t sb = sa + (1 + jt) * SPL * 2;
        float acc[2][8][4];
#pragma unroll
        for (int mi = 0; mi < 2; mi++)
#pragma unroll
            for (int nj = 0; nj < 8; nj++)
#pragma unroll
                for (int q = 0; q < 4; q++) acc[mi][nj][q] = 0.0f;
#pragma unroll
        for (int kk = 0; kk < 64; kk += 16) {
            uint32_t ah[2][4];
#pragma unroll
            for (int mi = 0; mi < 2; mi++) {
                int r = wy * 32 + mi * 16 + arow;
                uint32_t ad = sa + (uint32_t)(r * SSTR + kk + acol) * 2;
                LDSM4(ah[mi], ad);
            }
#pragma unroll
            for (int njp = 0; njp < 4; njp++) {
                int n = wx * 64 + njp * 16 + brow;
                uint32_t bd = sb + (uint32_t)(n * SSTR + kk + bcol) * 2;
                uint32_t bf[4];
                LDSM4(bf, bd);
#pragma unroll
                for (int mi = 0; mi < 2; mi++) {
                    mmaf16(acc[mi][2 * njp + 0], ah[mi], bf + 0);
                    mmaf16(acc[mi][2 * njp + 1], ah[mi], bf + 2);
                }
            }
        }
        int j1 = j0 + jt * 128;
#pragma unroll
        for (int mi = 0; mi < 2; mi++) {
#pragma unroll
            for (int nj = 0; nj < 8; nj++) {
                int r = i0 + wy * 32 + mi * 16 + (lane >> 2);
                int ncol = j1 + wx * 64 + nj * 8 + ((lane & 3) << 1);
                *(f162*)&Cb[(size_t)r * KL + ncol] =
                    __floats2half2_rn(acc[mi][nj][0] * 0.125f,
                                      acc[mi][nj][1] * 0.125f);
                *(f162*)&Cb[(size_t)(r + 8) * KL + ncol] =
                    __floats2half2_rn(acc[mi][nj][2] * 0.125f,
                                      acc[mi][nj][3] * 0.125f);
            }
        }
    }
}

// ---------------- bias kernels (pre-scaled by 0.125) ----------------
__global__ void bias_u_kernel(const f16* __restrict__ kH,
                              const f16* __restrict__ kL,
                              const float* __restrict__ u,
                              float* __restrict__ bU) {
    int idx = blockIdx.x * 256 + threadIdx.x;
    int bh = idx >> 11, j = idx & 2047;
    int b = bh >> 4, h = bh & 15;
    const f16* ph = kH + (size_t)(b * KL + j) * D3 + DM + h * DK;
    const f16* pl = kL + (size_t)(b * KL + j) * D3 + DM + h * DK;
    const float* uu = u + h * DK;
    float s = 0.0f;
#pragma unroll
    for (int d = 0; d < DK; d++)
        s += (__half2float(ph[d]) + __half2float(pl[d])) * uu[d];
    bU[idx] = s * 0.125f;
}
__global__ void bias_v_kernel(const f16* __restrict__ rpH,
                              const f16* __restrict__ rpL,
                              const float* __restrict__ v,
                              float* __restrict__ bV) {
    int idx = blockIdx.x * 256 + threadIdx.x;
    int h = idx >> 11, p = idx & 2047;
    const f16* ph = rpH + (size_t)p * DM + h * DK;
    const f16* pl = rpL + (size_t)p * DM + h * DK;
    const float* vv = v + h * DK;
    float s = 0.0f;
#pragma unroll
    for (int d = 0; d < DK; d++)
        s += (__half2float(ph[d]) + __half2float(pl[d])) * vv[d];
    bV[idx] = s * 0.125f;
}

// ---------------- fused shift+bias+mask+softmax -> fp16 weights -------------
__global__ __launch_bounds__(256)
void fused_softmax3(const f16* __restrict__ AC, const f16* __restrict__ U,
                    const float* __restrict__ bU, const float* __restrict__ bV,
                    f16* __restrict__ WT) {
    int rid = blockIdx.x;
    int bh = rid >> 10, h = bh & 15, i = rid & 1023;
    const f16* p = AC + (size_t)rid * KL;
    const f16* q = U + (size_t)rid * KL + (QL - 1 - i);   // odd offset — scalar loads only
    const float* bu = bU + bh * KL;
    const float* bv = bV + h * KL + (QL - 1 - i);
    int jmax = i + MEML;
    int tile_end = (i & ~127) + 128 + MEML;
    int tid = threadIdx.x;
    __shared__ float red[256];
    float x[8];
    float mx = -INFINITY;
#pragma unroll
    for (int t = 0; t < 4; t++) {
        int j = 2 * (tid + t * 256);
        float x0 = -INFINITY, x1 = -INFINITY;
        if (j < jmax) {
            f162 pv = *(const f162*)(p + j);
            float2 buv = *(const float2*)(bu + j);
            x0 = __half2float(pv.x) + buv.x + __half2float(q[j]) + bv[j];
            x1 = __half2float(pv.y) + buv.y + __half2float(q[j + 1]) + bv[j + 1];
        } else if (j == jmax) {
            x0 = __half2float(p[j]) + bu[j] + __half2float(q[j]) + bv[j];
        }
        x[2 * t + 0] = x0;
        x[2 * t + 1] = x1;
        mx = fmaxf(mx, fmaxf(x0, x1));
    }
    red[tid] = mx;
    __syncthreads();
    for (int s = 128; s > 0; s >>= 1) {
        if (tid < s) red[tid] = fmaxf(red[tid], red[tid + s]);
        __syncthreads();
    }
    mx = red[0];
    __syncthreads();
    float sum = 0.0f;
#pragma unroll
    for (int t = 0; t < 8; t++) {
        x[t] = __expf(x[t] - mx);
        sum += x[t];
    }
    red[tid] = sum;
    __syncthreads();
    for (int s = 128; s > 0; s >>= 1) {
        if (tid < s) red[tid] += red[tid + s];
        __syncthreads();
    }
    float inv = 1.0f / red[0];
    f16* w = WT + (size_t)rid * KL;
#pragma unroll
    for (int t = 0; t < 4; t++) {
        int j = 2 * (tid + t * 256);
        if (j < tile_end)
            *(f162*)(w + j) = __floats2half2_rn(x[2 * t] * inv, x[2 * t + 1] * inv);
    }
}

// ---------------------------------------------------------------------------
extern "C" void kernel_launch(void* const* d_in, const int* in_sizes, int n_in,
                              void* d_out, int out_size) {
    const float* inputs     = (const float*)d_in[0];
    const float* inputs_mem = (const float*)d_in[1];
    const float* r          = (const float*)d_in[2];
    const float* W          = (const float*)d_in[3];
    const float* W_r        = (const float*)d_in[4];
    const float* W_o        = (const float*)d_in[5];
    const float* u          = (const float*)d_in[6];
    const float* v          = (const float*)d_in[7];
    float* out = (float*)d_out;

    f16 *catH, *catL, *W1, *Wr1, *Wo1, *rsH, *rsL;
    f16 *qkvH, *qkvL, *rpH, *rpL, *attnH, *attnL, *wt, *scores, *bdu;
    float *biasU, *biasV;
    cudaGetSymbolAddress((void**)&catH, g_catH);  cudaGetSymbolAddress((void**)&catL, g_catL);
    cudaGetSymbolAddress((void**)&W1, g_W1);
    cudaGetSymbolAddress((void**)&Wr1, g_Wr1);
    cudaGetSymbolAddress((void**)&Wo1, g_Wo1);
    cudaGetSymbolAddress((void**)&rsH, g_rsH);    cudaGetSymbolAddress((void**)&rsL, g_rsL);
    cudaGetSymbolAddress((void**)&qkvH, g_qkvH);  cudaGetSymbolAddress((void**)&qkvL, g_qkvL);
    cudaGetSymbolAddress((void**)&rpH, g_rpH);    cudaGetSymbolAddress((void**)&rpL, g_rpL);
    cudaGetSymbolAddress((void**)&attnH, g_attnH);cudaGetSymbolAddress((void**)&attnL, g_attnL);
    cudaGetSymbolAddress((void**)&wt, g_wt);
    cudaGetSymbolAddress((void**)&scores, g_scores);
    cudaGetSymbolAddress((void**)&bdu, g_bdu);
    cudaGetSymbolAddress((void**)&biasU, g_biasU);
    cudaGetSymbolAddress((void**)&biasV, g_biasV);

    // smem sizes (bytes)
    const int SM_A128 = (2 * APL2 + 32 * 136) * 3 * 2;   // 87552 (A-split, B-single, NT=128)
    const int SM_V    = (APL2 + 32 * 72) * 3 * 2;        // 44544 (both single, NT=64)
    const int SMSC    = 3 * SPL * 2;                     // 55296 (single-plane score)
    cudaFuncSetAttribute(gemm_f16<128, 1, 0, 0, 1>, cudaFuncAttributeMaxDynamicSharedMemorySize, SM_A128);
    cudaFuncSetAttribute(gemm_f16<128, 1, 0, 2, 1>, cudaFuncAttributeMaxDynamicSharedMemorySize, SM_A128);
    cudaFuncSetAttribute(gemm_f16<128, 1, 0, 0, 0>, cudaFuncAttributeMaxDynamicSharedMemorySize, SM_A128);
    cudaFuncSetAttribute(gemm_f16<64, 0, 0, 1, 1>,  cudaFuncAttributeMaxDynamicSharedMemorySize, SM_V);
    cudaFuncSetAttribute(score_f16, cudaFuncAttributeMaxDynamicSharedMemorySize, SMSC);

    // 0. ingest
    split_single<<<DM * D3 / 2 / 256, 256>>>(W, W1, DM * D3 / 2);
    split_single<<<DM * DM / 2 / 256, 256>>>(W_r, Wr1, DM * DM / 2);
    split_single<<<DM * DM / 2 / 256, 256>>>(W_o, Wo1, DM * DM / 2);
    split_pair<<<KL * DM / 2 / 256, 256>>>(r, rsH, rsL, KL * DM / 2);
    build_cat_split<<<BB * KL * DM / 2 / 256, 256>>>(inputs, inputs_mem, catH, catL);
    // 1a. KV part of qkv: all 4096 rows x cols [DM, 3DM)
    gemm_f16<128, 1, 0, 0, 1><<<dim3(2 * DM / 128, BB * KL / 128), 256, SM_A128>>>(
        catH, catL, W1 + DM, nullptr, nullptr, qkvH + DM, qkvL + DM, DM, DM, D3, D3);
    // 1b. Q part: query rows only x cols [0, DM)
    gemm_f16<128, 1, 0, 2, 1><<<dim3(DM / 128, BB * QL / 128), 256, SM_A128>>>(
        catH, catL, W1, nullptr, nullptr, qkvH, qkvL, DM, DM, D3, D3);
    // 2. rproj = r @ W_r -> planes
    gemm_f16<128, 1, 0, 0, 1><<<dim3(DM / 128, KL / 128), 256, SM_A128>>>(
        rsH, rsL, Wr1, nullptr, nullptr, rpH, rpL, DM, DM, DM, DM);
    // 3. biases (pre-scaled)
    bias_u_kernel<<<BB * NH * KL / 256, 256>>>(qkvH, qkvL, u, biasU);
    bias_v_kernel<<<NH * KL / 256, 256>>>(rpH, rpL, v, biasV);
    // 4. merged score GEMMs (single-plane Q): z<32 AC, z>=32 BD
    score_f16<<<dim3(KL / 256, QL / 128, 2 * BB * NH), 256, SMSC>>>(
        qkvH, rpH, scores, bdu);
    // 5. fused shift+bias+mask+softmax -> fp16 weights
    fused_softmax3<<<BB * NH * QL, 256>>>(scores, bdu, biasU, biasV, wt);
    // 6. attn = weights @ V  (both single) -> planes, K clamped
    gemm_f16<64, 0, 0, 1, 1><<<dim3(1, QL / 128, BB * NH), 256, SM_V>>>(
        wt, nullptr, qkvH + 2 * DM, nullptr, nullptr, attnH, attnL,
        KL, KL, D3, DM);
    // 7. out = attn @ W_o (A split, B single, fp32 out)
    gemm_f16<128, 1, 0, 0, 0><<<dim3(DM / 128, BB * QL / 128), 256, SM_A128>>>(
        attnH, attnL, Wo1, nullptr, out, nullptr, nullptr, DM, DM, DM, DM);
}

// round 13
// speedup vs baseline: 3.5201x; 1.0252x over previous
#include <cuda_runtime.h>
#include <cuda_fp16.h>
#include <math.h>
#include <stdint.h>

#define BB    2
#define QL    1024
#define MEML  1024
#define KL    2048
#define DM    1024
#define NH    16
#define DK    64
#define D3    3072

typedef __half  f16;
typedef __half2 f162;

// ---------------- scratch (device globals, no allocation) ----------------
__device__ f16 g_catH[BB * KL * DM], g_catL[BB * KL * DM];
__device__ f16 g_W1[DM * D3];
__device__ f16 g_Wr1[DM * DM];
__device__ f16 g_Wo1[DM * DM];
__device__ f16 g_rsH[KL * DM], g_rsL[KL * DM];
__device__ f16 g_qkvH[BB * KL * D3], g_qkvL[BB * KL * D3];
__device__ f16 g_rpH[KL * DM], g_rpL[KL * DM];
__device__ f16 g_attnH[BB * QL * DM], g_attnL[BB * QL * DM];
__device__ f16 g_scores[(size_t)BB * NH * QL * KL];
__device__ f16 g_bdu[(size_t)BB * NH * QL * KL];
__device__ f16 g_wt[(size_t)BB * NH * QL * KL];
__device__ float g_biasU[BB * NH * KL];
__device__ float g_biasV[NH * KL];

// ---------------- helpers ----------------
__device__ __forceinline__ void split1(float x, f16& h, f16& l) {
    h = __float2half_rn(x);
    l = __float2half_rn(x - __half2float(h));
}
__device__ __forceinline__ void cp16(uint32_t dst, const void* src) {
    asm volatile("cp.async.cg.shared.global [%0], [%1], 16;\n" :: "r"(dst), "l"(src));
}
__device__ __forceinline__ void cp_commit() {
    asm volatile("cp.async.commit_group;\n");
}
__device__ __forceinline__ void cp_wait0() {
    asm volatile("cp.async.wait_group 0;\n");
}
__device__ __forceinline__ void cp_wait1() {
    asm volatile("cp.async.wait_group 1;\n");
}
__device__ __forceinline__ void mmaf16(float* d, const uint32_t* a,
                                       const uint32_t* b) {
    asm volatile(
        "mma.sync.aligned.m16n8k16.row.col.f32.f16.f16.f32 "
        "{%0,%1,%2,%3}, {%4,%5,%6,%7}, {%8,%9}, {%0,%1,%2,%3};"
        : "+f"(d[0]), "+f"(d[1]), "+f"(d[2]), "+f"(d[3])
        : "r"(a[0]), "r"(a[1]), "r"(a[2]), "r"(a[3]), "r"(b[0]), "r"(b[1]));
}
#define LDSM4(R, addr)                                                        \
    asm volatile("ldmatrix.sync.aligned.m8n8.x4.shared.b16 {%0,%1,%2,%3}, [%4];" \
                 : "=r"((R)[0]), "=r"((R)[1]), "=r"((R)[2]), "=r"((R)[3])     \
                 : "r"(addr))
#define LDSM4T(R, addr)                                                       \
    asm volatile("ldmatrix.sync.aligned.m8n8.x4.trans.shared.b16 {%0,%1,%2,%3}, [%4];" \
                 : "=r"((R)[0]), "=r"((R)[1]), "=r"((R)[2]), "=r"((R)[3])     \
                 : "r"(addr))

extern __shared__ __align__(16) char dynsm[];

// ---------------- ingest kernels ----------------
__global__ void split_single(const float* __restrict__ src,
                             f16* __restrict__ H, int n2) {
    int i = blockIdx.x * 256 + threadIdx.x;
    if (i >= n2) return;
    float2 v = *(const float2*)(src + 2 * (size_t)i);
    *(f162*)(H + 2 * (size_t)i) = __floats2half2_rn(v.x, v.y);
}
__global__ void split_pair(const float* __restrict__ src,
                           f16* __restrict__ H, f16* __restrict__ L, int n2) {
    int i = blockIdx.x * 256 + threadIdx.x;
    if (i >= n2) return;
    float2 v = *(const float2*)(src + 2 * (size_t)i);
    f16 h0, l0, h1, l1;
    split1(v.x, h0, l0); split1(v.y, h1, l1);
    f162 vh; vh.x = h0; vh.y = h1;
    f162 vl; vl.x = l0; vl.y = l1;
    *(f162*)(H + 2 * (size_t)i) = vh;
    *(f162*)(L + 2 * (size_t)i) = vl;
}
__global__ void build_cat_split(const float* __restrict__ inp,
                                const float* __restrict__ mem,
                                f16* __restrict__ H, f16* __restrict__ L) {
    int idx = blockIdx.x * 256 + threadIdx.x;
    int per_b = KL * (DM / 2);
    int b = idx / per_b;
    int rem = idx - b * per_b;
    int t = rem / (DM / 2);
    int c = rem - t * (DM / 2);
    const float2* s;
    if (t < MEML) s = (const float2*)(mem + ((size_t)b * MEML + t) * DM) + c;
    else          s = (const float2*)(inp + ((size_t)b * QL + (t - MEML)) * DM) + c;
    float2 v = *s;
    f16 h0, l0, h1, l1;
    split1(v.x, h0, l0); split1(v.y, h1, l1);
    f162 vh; vh.x = h0; vh.y = h1;
    f162 vl; vl.x = l0; vl.y = l1;
    size_t o = ((size_t)b * KL + t) * DM + 2 * c;
    *(f162*)(H + o) = vh;
    *(f162*)(L + o) = vl;
}

// ---------------- GEMM body (trans-B, 3-stage cp.async pipeline) ------------
// All pointers pre-offset to tile base. Epilogue uses local r in [0,128),
// ncol in [0,NT). C strides ldc apply to the pre-offset base.
#define ASTR2 40
#define APL2  (128 * ASTR2)

template <int NT, int ASPL, int BSPL, int COUT>
__device__ __forceinline__ void gemm_body(
    const f16* __restrict__ AbH, const f16* __restrict__ AbL,
    const f16* __restrict__ BbH, const f16* __restrict__ BbL,
    float* __restrict__ Cf, f16* __restrict__ CH, f16* __restrict__ CL,
    int NC, int lda, int ldb, int ldc) {
    constexpr int NTP = NT + 8;
    constexpr int BPL = 32 * NTP;
    constexpr int ANP = ASPL ? 2 : 1;
    constexpr int BNP = BSPL ? 2 : 1;
    constexpr int STG = ANP * APL2 + BNP * BPL;
    constexpr int NJ = NT / 16;
    int tid = threadIdx.x, lane = tid & 31, wid = tid >> 5;
    int wy = wid & 3, wx = wid >> 2;

    f16* sm = (f16*)dynsm;

    auto loadAB = [&](int k0, int s) {
        f16* base = sm + s * STG;
        uint32_t da = (uint32_t)__cvta_generic_to_shared(base);
        uint32_t db = da + ANP * APL2 * 2;
#pragma unroll
        for (int it = 0; it < 2; it++) {
            int e = tid + it * 256;
            int row = e >> 2, ch = (e & 3) << 3;
            size_t src = (size_t)row * lda + k0 + ch;
            uint32_t doff = (uint32_t)(row * ASTR2 + ch) * 2;
            cp16(da + doff, AbH + src);
            if (ASPL) cp16(da + APL2 * 2 + doff, AbL + src);
        }
        constexpr int CPR = NT / 8;
        constexpr int ITB = (32 * CPR) / 256;
#pragma unroll
        for (int it = 0; it < ITB; it++) {
            int e = tid + it * 256;
            int kk = e / CPR, nb = (e % CPR) * 8;
            size_t src = (size_t)(k0 + kk) * ldb + nb;
            uint32_t doff = (uint32_t)(kk * NTP + nb) * 2;
            cp16(db + doff, BbH + src);
            if (BSPL) cp16(db + BPL * 2 + doff, BbL + src);
        }
    };

    float acc[2][NJ][4];
#pragma unroll
    for (int mi = 0; mi < 2; mi++)
#pragma unroll
        for (int nj = 0; nj < NJ; nj++)
#pragma unroll
            for (int q = 0; q < 4; q++) acc[mi][nj][q] = 0.0f;

    loadAB(0, 0); cp_commit();
    if (NC > 1) { loadAB(32, 1); cp_commit(); }

    int arow = (lane & 15);
    int acol = (lane & 16) >> 1;
    int bln = ((lane >> 4) << 3);

    for (int c = 0; c < NC; c++) {
        if (c + 1 < NC) cp_wait1(); else cp_wait0();
        __syncthreads();
        if (c + 2 < NC) { loadAB((c + 2) << 5, (c + 2) % 3); cp_commit(); }
        int s = c % 3;
        uint32_t sa = (uint32_t)__cvta_generic_to_shared(sm + s * STG);
        uint32_t sb = sa + ANP * APL2 * 2;
#pragma unroll
        for (int kk = 0; kk < 32; kk += 16) {
            uint32_t ah[2][4], al[2][4];
#pragma unroll
            for (int mi = 0; mi < 2; mi++) {
                int r = wy * 32 + mi * 16 + arow;
                uint32_t ad = sa + (uint32_t)(r * ASTR2 + kk + acol) * 2;
                LDSM4(ah[mi], ad);
                if (ASPL) LDSM4(al[mi], ad + APL2 * 2);
            }
#pragma unroll
            for (int njp = 0; njp < NJ / 2; njp++) {
                int n16 = wx * (NT / 2) + njp * 16;
                uint32_t bd = sb +
                    (uint32_t)((kk + arow) * NTP + n16 + bln) * 2;
                uint32_t bf[4], blf[4];
                LDSM4T(bf, bd);
                if (BSPL) LDSM4T(blf, bd + BPL * 2);
#pragma unroll
                for (int mi = 0; mi < 2; mi++) {
                    mmaf16(acc[mi][2 * njp + 0], ah[mi], bf + 0);
                    mmaf16(acc[mi][2 * njp + 1], ah[mi], bf + 2);
                    if (ASPL) {
                        mmaf16(acc[mi][2 * njp + 0], al[mi], bf + 0);
                        mmaf16(acc[mi][2 * njp + 1], al[mi], bf + 2);
                    }
                    if (BSPL) {
                        mmaf16(acc[mi][2 * njp + 0], ah[mi], blf + 0);
                        mmaf16(acc[mi][2 * njp + 1], ah[mi], blf + 2);
                    }
                }
            }
        }
    }

#pragma unroll
    for (int mi = 0; mi < 2; mi++) {
#pragma unroll
        for (int nj = 0; nj < NJ; nj++) {
            int r = wy * 32 + mi * 16 + (lane >> 2);
            int ncol = wx * (NT / 2) + nj * 8 + ((lane & 3) << 1);
            if (COUT == 0) {
                *(float2*)&Cf[(size_t)r * ldc + ncol] =
                    make_float2(acc[mi][nj][0], acc[mi][nj][1]);
                *(float2*)&Cf[(size_t)(r + 8) * ldc + ncol] =
                    make_float2(acc[mi][nj][2], acc[mi][nj][3]);
            } else {
#pragma unroll
                for (int hh = 0; hh < 2; hh++) {
                    f16 h0, l0, h1, l1;
                    split1(acc[mi][nj][2 * hh + 0], h0, l0);
                    split1(acc[mi][nj][2 * hh + 1], h1, l1);
                    f162 vh; vh.x = h0; vh.y = h1;
                    f162 vl; vl.x = l0; vl.y = l1;
                    size_t o = (size_t)(r + 8 * hh) * ldc + ncol;
                    *(f162*)(CH + o) = vh;
                    *(f162*)(CL + o) = vl;
                }
            }
        }
    }
}

// ---------------- merged projection launch: KV + Q + rproj (768 blocks) -----
__global__ __launch_bounds__(256, 2)
void proj_all(const f16* __restrict__ catH, const f16* __restrict__ catL,
              const f16* __restrict__ rsH, const f16* __restrict__ rsL,
              const f16* __restrict__ W1, const f16* __restrict__ Wr1,
              f16* __restrict__ qkvH, f16* __restrict__ qkvL,
              f16* __restrict__ rpH, f16* __restrict__ rpL) {
    int id = blockIdx.x;
    if (id < 512) {
        // KV: all 4096 cat rows x cols [DM, 3DM)
        int x = id & 15, y = id >> 4;
        size_t arow = (size_t)(y * 128);
        size_t cbase = arow * D3 + DM + x * 128;
        gemm_body<128, 1, 0, 1>(
            catH + arow * DM, catL + arow * DM,
            W1 + DM + x * 128, nullptr,
            nullptr, qkvH + cbase, qkvL + cbase,
            32, DM, D3, D3);
    } else if (id < 640) {
        // Q: query rows only x cols [0, DM)
        int t = id - 512;
        int x = t & 7, y = t >> 3;
        int b = y >> 3;
        size_t grow = (size_t)(b * KL + MEML + (y & 7) * 128);
        size_t cbase = grow * D3 + x * 128;
        gemm_body<128, 1, 0, 1>(
            catH + grow * DM, catL + grow * DM,
            W1 + x * 128, nullptr,
            nullptr, qkvH + cbase, qkvL + cbase,
            32, DM, D3, D3);
    } else {
        // rproj: 2048 r rows x 1024 cols
        int t = id - 640;
        int x = t & 7, y = t >> 3;
        size_t arow = (size_t)(y * 128);
        size_t cbase = arow * DM + x * 128;
        gemm_body<128, 1, 0, 1>(
            rsH + arow * DM, rsL + arow * DM,
            Wr1 + x * 128, nullptr,
            nullptr, rpH + cbase, rpL + cbase,
            32, DM, DM, DM);
    }
}

// ---------------- V GEMM: weights @ V per (b,h), K clamped ------------------
__global__ __launch_bounds__(256, 2)
void vgemm(const f16* __restrict__ wt, const f16* __restrict__ qkvH,
           f16* __restrict__ attnH, f16* __restrict__ attnL) {
    int z = blockIdx.z, b = z >> 4, h = z & 15;
    int m0 = blockIdx.y * 128;
    int km = m0 + 128 + MEML;
    int Klim = (KL < km) ? KL : km;
    const f16* Ab = wt + (size_t)z * QL * KL + (size_t)m0 * KL;
    const f16* Bb = qkvH + 2 * DM + (size_t)b * KL * D3 + (size_t)h * DK;
    size_t cbase = (size_t)b * QL * DM + (size_t)h * DK + (size_t)m0 * DM;
    gemm_body<64, 0, 0, 1>(Ab, nullptr, Bb, nullptr,
                           nullptr, attnH + cbase, attnL + cbase,
                           Klim >> 5, KL, D3, DM);
}

// ---------------- out GEMM: attn @ W_o (fp32 out) ---------------------------
__global__ __launch_bounds__(256, 2)
void outgemm(const f16* __restrict__ attnH, const f16* __restrict__ attnL,
             const f16* __restrict__ Wo1, float* __restrict__ out) {
    int m0 = blockIdx.y * 128, n0 = blockIdx.x * 128;
    gemm_body<128, 1, 0, 0>(
        attnH + (size_t)m0 * DM, attnL + (size_t)m0 * DM,
        Wo1 + n0, nullptr,
        out + (size_t)m0 * DM + n0, nullptr, nullptr,
        32, DM, DM, DM);
}

// ---------------- merged score GEMM (single-plane Q): z<32 AC, z>=32 BD ----
#define SSTR 72
#define SPL  (128 * SSTR)

__global__ __launch_bounds__(256, 2)
void score_f16(const f16* __restrict__ qH, const f16* __restrict__ rp,
               f16* __restrict__ AC, f16* __restrict__ BD) {
    int z = blockIdx.z;
    int mode = (z >= BB * NH) ? 1 : 0;
    int bh = mode ? (z - BB * NH) : z;
    int b = bh >> 4, h = bh & 15;
    int i0 = blockIdx.y * 128, j0 = blockIdx.x * 256;
    bool act[2];
    if (mode == 0) {
        act[0] = (j0 - i0) < 1152;
        act[1] = (j0 + 128 - i0) < 1152;
        if (!act[0]) return;
    } else {
        act[0] = (i0 + j0) > 768;
        act[1] = (i0 + j0 + 128) > 768;
        if (!act[1]) return;
    }
    int tid = threadIdx.x, lane = tid & 31, wid = tid >> 5;
    int wy = wid & 3, wx = wid >> 2;

    f16* sm = (f16*)dynsm;
    {
        const f16* AbH = qH + (size_t)(b * KL + MEML + i0) * D3 + h * DK;
        uint32_t dh = (uint32_t)__cvta_generic_to_shared(sm);
#pragma unroll
        for (int it = 0; it < 4; it++) {
            int e = tid + it * 256;
            int row = e >> 3, ch = (e & 7) << 3;
            cp16(dh + (uint32_t)(row * SSTR + ch) * 2,
                 AbH + (size_t)row * D3 + ch);
        }
    }
#pragma unroll
    for (int jt = 0; jt < 2; jt++) {
        if (!act[jt]) continue;
        int j1 = j0 + jt * 128;
        const f16* Bb;
        size_t ldrow;
        if (mode == 0) { Bb = qH + (size_t)(b * KL + j1) * D3 + DM + h * DK; ldrow = D3; }
        else           { Bb = rp + (size_t)j1 * DM + h * DK; ldrow = DM; }
        uint32_t dh = (uint32_t)__cvta_generic_to_shared(sm + (1 + jt) * SPL);
#pragma unroll
        for (int it = 0; it < 4; it++) {
            int e = tid + it * 256;
            int row = e >> 3, ch = (e & 7) << 3;
            cp16(dh + (uint32_t)(row * SSTR + ch) * 2, Bb + (size_t)row * ldrow + ch);
        }
    }
    cp_commit();
    cp_wait0();
    __syncthreads();

    int arow = (lane & 15);
    int acol = (lane & 16) >> 1;
    int brow = (lane & 7) + ((lane & 16) >> 1);
    int bcol = (lane & 8);
    uint32_t sa = (uint32_t)__cvta_generic_to_shared(sm);

    f16* Cb = (mode ? BD : AC) + (size_t)bh * QL * KL;
#pragma unroll
    for (int jt = 0; jt < 2; jt++) {
        if (!act[jt]) continue;
        uint32_t sb = sa + (1 + jt) * SPL * 2;
        float acc[2][8][4];
#pragma unroll
        for (int mi = 0; mi < 2; mi++)
#pragma unroll
            for (int nj = 0; nj < 8; nj++)
#pragma unroll
                for (int q = 0; q < 4; q++) acc[mi][nj][q] = 0.0f;
#pragma unroll
        for (int kk = 0; kk < 64; kk += 16) {
            uint32_t ah[2][4];
#pragma unroll
            for (int mi = 0; mi < 2; mi++) {
                int r = wy * 32 + mi * 16 + arow;
                uint32_t ad = sa + (uint32_t)(r * SSTR + kk + acol) * 2;
                LDSM4(ah[mi], ad);
            }
#pragma unroll
            for (int njp = 0; njp < 4; njp++) {
                int n = wx * 64 + njp * 16 + brow;
                uint32_t bd = sb + (uint32_t)(n * SSTR + kk + bcol) * 2;
                uint32_t bf[4];
                LDSM4(bf, bd);
#pragma unroll
                for (int mi = 0; mi < 2; mi++) {
                    mmaf16(acc[mi][2 * njp + 0], ah[mi], bf + 0);
                    mmaf16(acc[mi][2 * njp + 1], ah[mi], bf + 2);
                }
            }
        }
        int j1 = j0 + jt * 128;
#pragma unroll
        for (int mi = 0; mi < 2; mi++) {
#pragma unroll
            for (int nj = 0; nj < 8; nj++) {
                int r = i0 + wy * 32 + mi * 16 + (lane >> 2);
                int ncol = j1 + wx * 64 + nj * 8 + ((lane & 3) << 1);
                *(f162*)&Cb[(size_t)r * KL + ncol] =
                    __floats2half2_rn(acc[mi][nj][0] * 0.125f,
                                      acc[mi][nj][1] * 0.125f);
                *(f162*)&Cb[(size_t)(r + 8) * KL + ncol] =
                    __floats2half2_rn(acc[mi][nj][2] * 0.125f,
                                      acc[mi][nj][3] * 0.125f);
            }
        }
    }
}

// ---------------- bias kernels (pre-scaled by 0.125) ----------------
__global__ void bias_u_kernel(const f16* __restrict__ kH,
                              const f16* __restrict__ kL,
                              const float* __restrict__ u,
                              float* __restrict__ bU) {
    int idx = blockIdx.x * 256 + threadIdx.x;
    int bh = idx >> 11, j = idx & 2047;
    int b = bh >> 4, h = bh & 15;
    const f16* ph = kH + (size_t)(b * KL + j) * D3 + DM + h * DK;
    const f16* pl = kL + (size_t)(b * KL + j) * D3 + DM + h * DK;
    const float* uu = u + h * DK;
    float s = 0.0f;
#pragma unroll
    for (int d = 0; d < DK; d++)
        s += (__half2float(ph[d]) + __half2float(pl[d])) * uu[d];
    bU[idx] = s * 0.125f;
}
__global__ void bias_v_kernel(const f16* __restrict__ rpH,
                              const f16* __restrict__ rpL,
                              const float* __restrict__ v,
                              float* __restrict__ bV) {
    int idx = blockIdx.x * 256 + threadIdx.x;
    int h = idx >> 11, p = idx & 2047;
    const f16* ph = rpH + (size_t)p * DM + h * DK;
    const f16* pl = rpL + (size_t)p * DM + h * DK;
    const float* vv = v + h * DK;
    float s = 0.0f;
#pragma unroll
    for (int d = 0; d < DK; d++)
        s += (__half2float(ph[d]) + __half2float(pl[d])) * vv[d];
    bV[idx] = s * 0.125f;
}

// ---------------- fused shift+bias+mask+softmax -> fp16 weights -------------
__global__ __launch_bounds__(256)
void fused_softmax3(const f16* __restrict__ AC, const f16* __restrict__ U,
                    const float* __restrict__ bU, const float* __restrict__ bV,
                    f16* __restrict__ WT) {
    int rid = blockIdx.x;
    int bh = rid >> 10, h = bh & 15, i = rid & 1023;
    const f16* p = AC + (size_t)rid * KL;
    const f16* q = U + (size_t)rid * KL + (QL - 1 - i);   // odd offset — scalar loads only
    const float* bu = bU + bh * KL;
    const float* bv = bV + h * KL + (QL - 1 - i);
    int jmax = i + MEML;
    int tile_end = (i & ~127) + 128 + MEML;
    int tid = threadIdx.x;
    __shared__ float red[256];
    float x[8];
    float mx = -INFINITY;
#pragma unroll
    for (int t = 0; t < 4; t++) {
        int j = 2 * (tid + t * 256);
        float x0 = -INFINITY, x1 = -INFINITY;
        if (j < jmax) {
            f162 pv = *(const f162*)(p + j);
            float2 buv = *(const float2*)(bu + j);
            x0 = __half2float(pv.x) + buv.x + __half2float(q[j]) + bv[j];
            x1 = __half2float(pv.y) + buv.y + __half2float(q[j + 1]) + bv[j + 1];
        } else if (j == jmax) {
            x0 = __half2float(p[j]) + bu[j] + __half2float(q[j]) + bv[j];
        }
        x[2 * t + 0] = x0;
        x[2 * t + 1] = x1;
        mx = fmaxf(mx, fmaxf(x0, x1));
    }
    red[tid] = mx;
    __syncthreads();
    for (int s = 128; s > 0; s >>= 1) {
        if (tid < s) red[tid] = fmaxf(red[tid], red[tid + s]);
        __syncthreads();
    }
    mx = red[0];
    __syncthreads();
    float sum = 0.0f;
#pragma unroll
    for (int t = 0; t < 8; t++) {
        x[t] = __expf(x[t] - mx);
        sum += x[t];
    }
    red[tid] = sum;
    __syncthreads();
    for (int s = 128; s > 0; s >>= 1) {
        if (tid < s) red[tid] += red[tid + s];
        __syncthreads();
    }
    float inv = 1.0f / red[0];
    f16* w = WT + (size_t)rid * KL;
#pragma unroll
    for (int t = 0; t < 4; t++) {
        int j = 2 * (tid + t * 256);
        if (j < tile_end)
            *(f162*)(w + j) = __floats2half2_rn(x[2 * t] * inv, x[2 * t + 1] * inv);
    }
}

// ---------------------------------------------------------------------------
extern "C" void kernel_launch(void* const* d_in, const int* in_sizes, int n_in,
                              void* d_out, int out_size) {
    const float* inputs     = (const float*)d_in[0];
    const float* inputs_mem = (const float*)d_in[1];
    const float* r          = (const float*)d_in[2];
    const float* W          = (const float*)d_in[3];
    const float* W_r        = (const float*)d_in[4];
    const float* W_o        = (const float*)d_in[5];
    const float* u          = (const float*)d_in[6];
    const float* v          = (const float*)d_in[7];
    float* out = (float*)d_out;

    f16 *catH, *catL, *W1, *Wr1, *Wo1, *rsH, *rsL;
    f16 *qkvH, *qkvL, *rpH, *rpL, *attnH, *attnL, *wt, *scores, *bdu;
    float *biasU, *biasV;
    cudaGetSymbolAddress((void**)&catH, g_catH);  cudaGetSymbolAddress((void**)&catL, g_catL);
    cudaGetSymbolAddress((void**)&W1, g_W1);
    cudaGetSymbolAddress((void**)&Wr1, g_Wr1);
    cudaGetSymbolAddress((void**)&Wo1, g_Wo1);
    cudaGetSymbolAddress((void**)&rsH, g_rsH);    cudaGetSymbolAddress((void**)&rsL, g_rsL);
    cudaGetSymbolAddress((void**)&qkvH, g_qkvH);  cudaGetSymbolAddress((void**)&qkvL, g_qkvL);
    cudaGetSymbolAddress((void**)&rpH, g_rpH);    cudaGetSymbolAddress((void**)&rpL, g_rpL);
    cudaGetSymbolAddress((void**)&attnH, g_attnH);cudaGetSymbolAddress((void**)&attnL, g_attnL);
    cudaGetSymbolAddress((void**)&wt, g_wt);
    cudaGetSymbolAddress((void**)&scores, g_scores);
    cudaGetSymbolAddress((void**)&bdu, g_bdu);
    cudaGetSymbolAddress((void**)&biasU, g_biasU);
    cudaGetSymbolAddress((void**)&biasV, g_biasV);

    // smem sizes (bytes)
    const int SM_A128 = (2 * APL2 + 32 * 136) * 3 * 2;   // 87552 (A-split, B-single, NT=128)
    const int SM_V    = (APL2 + 32 * 72) * 3 * 2;        // 44544 (both single, NT=64)
    const int SMSC    = 3 * SPL * 2;                     // 55296
    cudaFuncSetAttribute(proj_all, cudaFuncAttributeMaxDynamicSharedMemorySize, SM_A128);
    cudaFuncSetAttribute(outgemm,  cudaFuncAttributeMaxDynamicSharedMemorySize, SM_A128);
    cudaFuncSetAttribute(vgemm,    cudaFuncAttributeMaxDynamicSharedMemorySize, SM_V);
    cudaFuncSetAttribute(score_f16, cudaFuncAttributeMaxDynamicSharedMemorySize, SMSC);

    // 0. ingest
    split_single<<<DM * D3 / 2 / 256, 256>>>(W, W1, DM * D3 / 2);
    split_single<<<DM * DM / 2 / 256, 256>>>(W_r, Wr1, DM * DM / 2);
    split_single<<<DM * DM / 2 / 256, 256>>>(W_o, Wo1, DM * DM / 2);
    split_pair<<<KL * DM / 2 / 256, 256>>>(r, rsH, rsL, KL * DM / 2);
    build_cat_split<<<BB * KL * DM / 2 / 256, 256>>>(inputs, inputs_mem, catH, catL);
    // 1. merged projections: KV (512 blocks) + Q (128) + rproj (128)
    proj_all<<<768, 256, SM_A128>>>(catH, catL, rsH, rsL, W1, Wr1,
                                    qkvH, qkvL, rpH, rpL);
    // 2. biases (pre-scaled)
    bias_u_kernel<<<BB * NH * KL / 256, 256>>>(qkvH, qkvL, u, biasU);
    bias_v_kernel<<<NH * KL / 256, 256>>>(rpH, rpL, v, biasV);
    // 3. merged score GEMMs (single-plane Q): z<32 AC, z>=32 BD
    score_f16<<<dim3(KL / 256, QL / 128, 2 * BB * NH), 256, SMSC>>>(
        qkvH, rpH, scores, bdu);
    // 4. fused shift+bias+mask+softmax -> fp16 weights
    fused_softmax3<<<BB * NH * QL, 256>>>(scores, bdu, biasU, biasV, wt);
    // 5. attn = weights @ V  (both single) -> planes, K clamped
    vgemm<<<dim3(1, QL / 128, BB * NH), 256, SM_V>>>(wt, qkvH, attnH, attnL);
    // 6. out = attn @ W_o (A split, B single, fp32 out)
    outgemm<<<dim3(DM / 128, BB * QL / 128), 256, SM_A128>>>(attnH, attnL, Wo1, out);
}

// round 14
// speedup vs baseline: 4.1330x; 1.1741x over previous
#include <cuda_runtime.h>
#include <cuda_fp16.h>
#include <math.h>
#include <stdint.h>

#define BB    2
#define QL    1024
#define MEML  1024
#define KL    2048
#define DM    1024
#define NH    16
#define DK    64
#define D3    3072

typedef __half  f16;
typedef __half2 f162;

// ---------------- scratch (device globals, no allocation) ----------------
__device__ f16 g_catH[BB * KL * DM];
__device__ f16 g_W1[DM * D3];
__device__ f16 g_Wr1[DM * DM];
__device__ f16 g_Wo1[DM * DM];
__device__ f16 g_rsH[KL * DM];
__device__ f16 g_qkvH[BB * KL * D3], g_qkvL[BB * KL * D3];
__device__ f16 g_rpH[KL * DM], g_rpL[KL * DM];
__device__ f16 g_attnH[BB * QL * DM], g_attnL[BB * QL * DM];
__device__ f16 g_scores[(size_t)BB * NH * QL * KL];
__device__ f16 g_bdu[(size_t)BB * NH * QL * KL];
__device__ f16 g_wt[(size_t)BB * NH * QL * KL];
__device__ float g_biasU[BB * NH * KL];
__device__ float g_biasV[NH * KL];

// ---------------- helpers ----------------
__device__ __forceinline__ void split1(float x, f16& h, f16& l) {
    h = __float2half_rn(x);
    l = __float2half_rn(x - __half2float(h));
}
__device__ __forceinline__ void cp16(uint32_t dst, const void* src) {
    asm volatile("cp.async.cg.shared.global [%0], [%1], 16;\n" :: "r"(dst), "l"(src));
}
__device__ __forceinline__ void cp_commit() {
    asm volatile("cp.async.commit_group;\n");
}
__device__ __forceinline__ void cp_wait0() {
    asm volatile("cp.async.wait_group 0;\n");
}
__device__ __forceinline__ void cp_wait1() {
    asm volatile("cp.async.wait_group 1;\n");
}
__device__ __forceinline__ void mmaf16(float* d, const uint32_t* a,
                                       const uint32_t* b) {
    asm volatile(
        "mma.sync.aligned.m16n8k16.row.col.f32.f16.f16.f32 "
        "{%0,%1,%2,%3}, {%4,%5,%6,%7}, {%8,%9}, {%0,%1,%2,%3};"
        : "+f"(d[0]), "+f"(d[1]), "+f"(d[2]), "+f"(d[3])
        : "r"(a[0]), "r"(a[1]), "r"(a[2]), "r"(a[3]), "r"(b[0]), "r"(b[1]));
}
#define LDSM4(R, addr)                                                        \
    asm volatile("ldmatrix.sync.aligned.m8n8.x4.shared.b16 {%0,%1,%2,%3}, [%4];" \
                 : "=r"((R)[0]), "=r"((R)[1]), "=r"((R)[2]), "=r"((R)[3])     \
                 : "r"(addr))
#define LDSM4T(R, addr)                                                       \
    asm volatile("ldmatrix.sync.aligned.m8n8.x4.trans.shared.b16 {%0,%1,%2,%3}, [%4];" \
                 : "=r"((R)[0]), "=r"((R)[1]), "=r"((R)[2]), "=r"((R)[3])     \
                 : "r"(addr))

extern __shared__ __align__(16) char dynsm[];

// ---------------- ingest kernels ----------------
__global__ void split_single(const float* __restrict__ src,
                             f16* __restrict__ H, int n2) {
    int i = blockIdx.x * 256 + threadIdx.x;
    if (i >= n2) return;
    float2 v = *(const float2*)(src + 2 * (size_t)i);
    *(f162*)(H + 2 * (size_t)i) = __floats2half2_rn(v.x, v.y);
}
__global__ void split_pair(const float* __restrict__ src,
                           f16* __restrict__ H, f16* __restrict__ L, int n2) {
    int i = blockIdx.x * 256 + threadIdx.x;
    if (i >= n2) return;
    float2 v = *(const float2*)(src + 2 * (size_t)i);
    f16 h0, l0, h1, l1;
    split1(v.x, h0, l0); split1(v.y, h1, l1);
    f162 vh; vh.x = h0; vh.y = h1;
    f162 vl; vl.x = l0; vl.y = l1;
    *(f162*)(H + 2 * (size_t)i) = vh;
    *(f162*)(L + 2 * (size_t)i) = vl;
}
__global__ void build_cat_single(const float* __restrict__ inp,
                                 const float* __restrict__ mem,
                                 f16* __restrict__ H) {
    int idx = blockIdx.x * 256 + threadIdx.x;
    int per_b = KL * (DM / 2);
    int b = idx / per_b;
    int rem = idx - b * per_b;
    int t = rem / (DM / 2);
    int c = rem - t * (DM / 2);
    const float2* s;
    if (t < MEML) s = (const float2*)(mem + ((size_t)b * MEML + t) * DM) + c;
    else          s = (const float2*)(inp + ((size_t)b * QL + (t - MEML)) * DM) + c;
    float2 v = *s;
    size_t o = ((size_t)b * KL + t) * DM + 2 * c;
    *(f162*)(H + o) = __floats2half2_rn(v.x, v.y);
}

// ---------------- GEMM body (trans-B, 3-stage cp.async pipeline) ------------
#define ASTR2 40
#define APL2  (128 * ASTR2)

template <int NT, int ASPL, int BSPL, int COUT>
__device__ __forceinline__ void gemm_body(
    const f16* __restrict__ AbH, const f16* __restrict__ AbL,
    const f16* __restrict__ BbH, const f16* __restrict__ BbL,
    float* __restrict__ Cf, f16* __restrict__ CH, f16* __restrict__ CL,
    int NC, int lda, int ldb, int ldc) {
    constexpr int NTP = NT + 8;
    constexpr int BPL = 32 * NTP;
    constexpr int ANP = ASPL ? 2 : 1;
    constexpr int BNP = BSPL ? 2 : 1;
    constexpr int STG = ANP * APL2 + BNP * BPL;
    constexpr int NJ = NT / 16;
    int tid = threadIdx.x, lane = tid & 31, wid = tid >> 5;
    int wy = wid & 3, wx = wid >> 2;

    f16* sm = (f16*)dynsm;

    auto loadAB = [&](int k0, int s) {
        f16* base = sm + s * STG;
        uint32_t da = (uint32_t)__cvta_generic_to_shared(base);
        uint32_t db = da + ANP * APL2 * 2;
#pragma unroll
        for (int it = 0; it < 2; it++) {
            int e = tid + it * 256;
            int row = e >> 2, ch = (e & 3) << 3;
            size_t src = (size_t)row * lda + k0 + ch;
            uint32_t doff = (uint32_t)(row * ASTR2 + ch) * 2;
            cp16(da + doff, AbH + src);
            if (ASPL) cp16(da + APL2 * 2 + doff, AbL + src);
        }
        constexpr int CPR = NT / 8;
        constexpr int ITB = (32 * CPR) / 256;
#pragma unroll
        for (int it = 0; it < ITB; it++) {
            int e = tid + it * 256;
            int kk = e / CPR, nb = (e % CPR) * 8;
            size_t src = (size_t)(k0 + kk) * ldb + nb;
            uint32_t doff = (uint32_t)(kk * NTP + nb) * 2;
            cp16(db + doff, BbH + src);
            if (BSPL) cp16(db + BPL * 2 + doff, BbL + src);
        }
    };

    float acc[2][NJ][4];
#pragma unroll
    for (int mi = 0; mi < 2; mi++)
#pragma unroll
        for (int nj = 0; nj < NJ; nj++)
#pragma unroll
            for (int q = 0; q < 4; q++) acc[mi][nj][q] = 0.0f;

    loadAB(0, 0); cp_commit();
    if (NC > 1) { loadAB(32, 1); cp_commit(); }

    int arow = (lane & 15);
    int acol = (lane & 16) >> 1;
    int bln = ((lane >> 4) << 3);

    for (int c = 0; c < NC; c++) {
        if (c + 1 < NC) cp_wait1(); else cp_wait0();
        __syncthreads();
        if (c + 2 < NC) { loadAB((c + 2) << 5, (c + 2) % 3); cp_commit(); }
        int s = c % 3;
        uint32_t sa = (uint32_t)__cvta_generic_to_shared(sm + s * STG);
        uint32_t sb = sa + ANP * APL2 * 2;
#pragma unroll
        for (int kk = 0; kk < 32; kk += 16) {
            uint32_t ah[2][4], al[2][4];
#pragma unroll
            for (int mi = 0; mi < 2; mi++) {
                int r = wy * 32 + mi * 16 + arow;
                uint32_t ad = sa + (uint32_t)(r * ASTR2 + kk + acol) * 2;
                LDSM4(ah[mi], ad);
                if (ASPL) LDSM4(al[mi], ad + APL2 * 2);
            }
#pragma unroll
            for (int njp = 0; njp < NJ / 2; njp++) {
                int n16 = wx * (NT / 2) + njp * 16;
                uint32_t bd = sb +
                    (uint32_t)((kk + arow) * NTP + n16 + bln) * 2;
                uint32_t bf[4], blf[4];
                LDSM4T(bf, bd);
                if (BSPL) LDSM4T(blf, bd + BPL * 2);
#pragma unroll
                for (int mi = 0; mi < 2; mi++) {
                    mmaf16(acc[mi][2 * njp + 0], ah[mi], bf + 0);
                    mmaf16(acc[mi][2 * njp + 1], ah[mi], bf + 2);
                    if (ASPL) {
                        mmaf16(acc[mi][2 * njp + 0], al[mi], bf + 0);
                        mmaf16(acc[mi][2 * njp + 1], al[mi], bf + 2);
                    }
                    if (BSPL) {
                        mmaf16(acc[mi][2 * njp + 0], ah[mi], blf + 0);
                        mmaf16(acc[mi][2 * njp + 1], ah[mi], blf + 2);
                    }
                }
            }
        }
    }

#pragma unroll
    for (int mi = 0; mi < 2; mi++) {
#pragma unroll
        for (int nj = 0; nj < NJ; nj++) {
            int r = wy * 32 + mi * 16 + (lane >> 2);
            int ncol = wx * (NT / 2) + nj * 8 + ((lane & 3) << 1);
            if (COUT == 0) {
                *(float2*)&Cf[(size_t)r * ldc + ncol] =
                    make_float2(acc[mi][nj][0], acc[mi][nj][1]);
                *(float2*)&Cf[(size_t)(r + 8) * ldc + ncol] =
                    make_float2(acc[mi][nj][2], acc[mi][nj][3]);
            } else {
#pragma unroll
                for (int hh = 0; hh < 2; hh++) {
                    f16 h0, l0, h1, l1;
                    split1(acc[mi][nj][2 * hh + 0], h0, l0);
                    split1(acc[mi][nj][2 * hh + 1], h1, l1);
                    f162 vh; vh.x = h0; vh.y = h1;
                    f162 vl; vl.x = l0; vl.y = l1;
                    size_t o = (size_t)(r + 8 * hh) * ldc + ncol;
                    *(f162*)(CH + o) = vh;
                    *(f162*)(CL + o) = vl;
                }
            }
        }
    }
}

// ---------------- merged projection launch (single-term A): 768 blocks ------
__global__ __launch_bounds__(256, 2)
void proj_all(const f16* __restrict__ catH, const f16* __restrict__ rsH,
              const f16* __restrict__ W1, const f16* __restrict__ Wr1,
              f16* __restrict__ qkvH, f16* __restrict__ qkvL,
              f16* __restrict__ rpH, f16* __restrict__ rpL) {
    int id = blockIdx.x;
    if (id < 512) {
        int x = id & 15, y = id >> 4;
        size_t arow = (size_t)(y * 128);
        size_t cbase = arow * D3 + DM + x * 128;
        gemm_body<128, 0, 0, 1>(
            catH + arow * DM, nullptr,
            W1 + DM + x * 128, nullptr,
            nullptr, qkvH + cbase, qkvL + cbase,
            32, DM, D3, D3);
    } else if (id < 640) {
        int t = id - 512;
        int x = t & 7, y = t >> 3;
        int b = y >> 3;
        size_t grow = (size_t)(b * KL + MEML + (y & 7) * 128);
        size_t cbase = grow * D3 + x * 128;
        gemm_body<128, 0, 0, 1>(
            catH + grow * DM, nullptr,
            W1 + x * 128, nullptr,
            nullptr, qkvH + cbase, qkvL + cbase,
            32, DM, D3, D3);
    } else {
        int t = id - 640;
        int x = t & 7, y = t >> 3;
        size_t arow = (size_t)(y * 128);
        size_t cbase = arow * DM + x * 128;
        gemm_body<128, 0, 0, 1>(
            rsH + arow * DM, nullptr,
            Wr1 + x * 128, nullptr,
            nullptr, rpH + cbase, rpL + cbase,
            32, DM, DM, DM);
    }
}

// ---------------- V GEMM: weights @ V per (b,h), K clamped ------------------
__global__ __launch_bounds__(256, 2)
void vgemm(const f16* __restrict__ wt, const f16* __restrict__ qkvH,
           f16* __restrict__ attnH, f16* __restrict__ attnL) {
    int z = blockIdx.z, b = z >> 4, h = z & 15;
    int m0 = blockIdx.y * 128;
    int km = m0 + 128 + MEML;
    int Klim = (KL < km) ? KL : km;
    const f16* Ab = wt + (size_t)z * QL * KL + (size_t)m0 * KL;
    const f16* Bb = qkvH + 2 * DM + (size_t)b * KL * D3 + (size_t)h * DK;
    size_t cbase = (size_t)b * QL * DM + (size_t)h * DK + (size_t)m0 * DM;
    gemm_body<64, 0, 0, 1>(Ab, nullptr, Bb, nullptr,
                           nullptr, attnH + cbase, attnL + cbase,
                           Klim >> 5, KL, D3, DM);
}

// ---------------- out GEMM: attn @ W_o (A-split, fp32 out) ------------------
__global__ __launch_bounds__(256, 2)
void outgemm(const f16* __restrict__ attnH, const f16* __restrict__ attnL,
             const f16* __restrict__ Wo1, float* __restrict__ out) {
    int m0 = blockIdx.y * 128, n0 = blockIdx.x * 128;
    gemm_body<128, 1, 0, 0>(
        attnH + (size_t)m0 * DM, attnL + (size_t)m0 * DM,
        Wo1 + n0, nullptr,
        out + (size_t)m0 * DM + n0, nullptr, nullptr,
        32, DM, DM, DM);
}

// ---------------- merged score GEMM (single-plane Q): z<32 AC, z>=32 BD ----
#define SSTR 72
#define SPL  (128 * SSTR)

__global__ __launch_bounds__(256, 2)
void score_f16(const f16* __restrict__ qH, const f16* __restrict__ rp,
               f16* __restrict__ AC, f16* __restrict__ BD) {
    int z = blockIdx.z;
    int mode = (z >= BB * NH) ? 1 : 0;
    int bh = mode ? (z - BB * NH) : z;
    int b = bh >> 4, h = bh & 15;
    int i0 = blockIdx.y * 128, j0 = blockIdx.x * 256;
    bool act[2];
    if (mode == 0) {
        act[0] = (j0 - i0) < 1152;
        act[1] = (j0 + 128 - i0) < 1152;
        if (!act[0]) return;
    } else {
        act[0] = (i0 + j0) > 768;
        act[1] = (i0 + j0 + 128) > 768;
        if (!act[1]) return;
    }
    int tid = threadIdx.x, lane = tid & 31, wid = tid >> 5;
    int wy = wid & 3, wx = wid >> 2;

    f16* sm = (f16*)dynsm;
    {
        const f16* AbH = qH + (size_t)(b * KL + MEML + i0) * D3 + h * DK;
        uint32_t dh = (uint32_t)__cvta_generic_to_shared(sm);
#pragma unroll
        for (int it = 0; it < 4; it++) {
            int e = tid + it * 256;
            int row = e >> 3, ch = (e & 7) << 3;
            cp16(dh + (uint32_t)(row * SSTR + ch) * 2,
                 AbH + (size_t)row * D3 + ch);
        }
    }
#pragma unroll
    for (int jt = 0; jt < 2; jt++) {
        if (!act[jt]) continue;
        int j1 = j0 + jt * 128;
        const f16* Bb;
        size_t ldrow;
        if (mode == 0) { Bb = qH + (size_t)(b * KL + j1) * D3 + DM + h * DK; ldrow = D3; }
        else           { Bb = rp + (size_t)j1 * DM + h * DK; ldrow = DM; }
        uint32_t dh = (uint32_t)__cvta_generic_to_shared(sm + (1 + jt) * SPL);
#pragma unroll
        for (int it = 0; it < 4; it++) {
            int e = tid + it * 256;
            int row = e >> 3, ch = (e & 7) << 3;
            cp16(dh + (uint32_t)(row * SSTR + ch) * 2, Bb + (size_t)row * ldrow + ch);
        }
    }
    cp_commit();
    cp_wait0();
    __syncthreads();

    int arow = (lane & 15);
    int acol = (lane & 16) >> 1;
    int brow = (lane & 7) + ((lane & 16) >> 1);
    int bcol = (lane & 8);
    uint32_t sa = (uint32_t)__cvta_generic_to_shared(sm);

    f16* Cb = (mode ? BD : AC) + (size_t)bh * QL * KL;
#pragma unroll
    for (int jt = 0; jt < 2; jt++) {
        if (!act[jt]) continue;
        uint32_t sb = sa + (1 + jt) * SPL * 2;
        float acc[2][8][4];
#pragma unroll
        for (int mi = 0; mi < 2; mi++)
#pragma unroll
            for (int nj = 0; nj < 8; nj++)
#pragma unroll
                for (int q = 0; q < 4; q++) acc[mi][nj][q] = 0.0f;
#pragma unroll
        for (int kk = 0; kk < 64; kk += 16) {
            uint32_t ah[2][4];
#pragma unroll
            for (int mi = 0; mi < 2; mi++) {
                int r = wy * 32 + mi * 16 + arow;
                uint32_t ad = sa + (uint32_t)(r * SSTR + kk + acol) * 2;
                LDSM4(ah[mi], ad);
            }
#pragma unroll
            for (int njp = 0; njp < 4; njp++) {
                int n = wx * 64 + njp * 16 + brow;
                uint32_t bd = sb + (uint32_t)(n * SSTR + kk + bcol) * 2;
                uint32_t bf[4];
                LDSM4(bf, bd);
#pragma unroll
                for (int mi = 0; mi < 2; mi++) {
                    mmaf16(acc[mi][2 * njp + 0], ah[mi], bf + 0);
                    mmaf16(acc[mi][2 * njp + 1], ah[mi], bf + 2);
                }
            }
        }
        int j1 = j0 + jt * 128;
#pragma unroll
        for (int mi = 0; mi < 2; mi++) {
#pragma unroll
            for (int nj = 0; nj < 8; nj++) {
                int r = i0 + wy * 32 + mi * 16 + (lane >> 2);
                int ncol = j1 + wx * 64 + nj * 8 + ((lane & 3) << 1);
                *(f162*)&Cb[(size_t)r * KL + ncol] =
                    __floats2half2_rn(acc[mi][nj][0] * 0.125f,
                                      acc[mi][nj][1] * 0.125f);
                *(f162*)&Cb[(size_t)(r + 8) * KL + ncol] =
                    __floats2half2_rn(acc[mi][nj][2] * 0.125f,
                                      acc[mi][nj][3] * 0.125f);
            }
        }
    }
}

// ---------------- bias kernels (pre-scaled by 0.125) ----------------
__global__ void bias_u_kernel(const f16* __restrict__ kH,
                              const f16* __restrict__ kL,
                              const float* __restrict__ u,
                              float* __restrict__ bU) {
    int idx = blockIdx.x * 256 + threadIdx.x;
    int bh = idx >> 11, j = idx & 2047;
    int b = bh >> 4, h = bh & 15;
    const f16* ph = kH + (size_t)(b * KL + j) * D3 + DM + h * DK;
    const f16* pl = kL + (size_t)(b * KL + j) * D3 + DM + h * DK;
    const float* uu = u + h * DK;
    float s = 0.0f;
#pragma unroll
    for (int d = 0; d < DK; d++)
        s += (__half2float(ph[d]) + __half2float(pl[d])) * uu[d];
    bU[idx] = s * 0.125f;
}
__global__ void bias_v_kernel(const f16* __restrict__ rpH,
                              const f16* __restrict__ rpL,
                              const float* __restrict__ v,
                              float* __restrict__ bV) {
    int idx = blockIdx.x * 256 + threadIdx.x;
    int h = idx >> 11, p = idx & 2047;
    const f16* ph = rpH + (size_t)p * DM + h * DK;
    const f16* pl = rpL + (size_t)p * DM + h * DK;
    const float* vv = v + h * DK;
    float s = 0.0f;
#pragma unroll
    for (int d = 0; d < DK; d++)
        s += (__half2float(ph[d]) + __half2float(pl[d])) * vv[d];
    bV[idx] = s * 0.125f;
}

// ---------------- fused shift+bias+mask+softmax -> fp16 weights -------------
__global__ __launch_bounds__(256)
void fused_softmax3(const f16* __restrict__ AC, const f16* __restrict__ U,
                    const float* __restrict__ bU, const float* __restrict__ bV,
                    f16* __restrict__ WT) {
    int rid = blockIdx.x;
    int bh = rid >> 10, h = bh & 15, i = rid & 1023;
    const f16* p = AC + (size_t)rid * KL;
    const f16* q = U + (size_t)rid * KL + (QL - 1 - i);   // odd offset — scalar loads only
    const float* bu = bU + bh * KL;
    const float* bv = bV + h * KL + (QL - 1 - i);
    int jmax = i + MEML;
    int tile_end = (i & ~127) + 128 + MEML;
    int tid = threadIdx.x;
    __shared__ float red[256];
    float x[8];
    float mx = -INFINITY;
#pragma unroll
    for (int t = 0; t < 4; t++) {
        int j = 2 * (tid + t * 256);
        float x0 = -INFINITY, x1 = -INFINITY;
        if (j < jmax) {
            f162 pv = *(const f162*)(p + j);
            float2 buv = *(const float2*)(bu + j);
            x0 = __half2float(pv.x) + buv.x + __half2float(q[j]) + bv[j];
            x1 = __half2float(pv.y) + buv.y + __half2float(q[j + 1]) + bv[j + 1];
        } else if (j == jmax) {
            x0 = __half2float(p[j]) + bu[j] + __half2float(q[j]) + bv[j];
        }
        x[2 * t + 0] = x0;
        x[2 * t + 1] = x1;
        mx = fmaxf(mx, fmaxf(x0, x1));
    }
    red[tid] = mx;
    __syncthreads();
    for (int s = 128; s > 0; s >>= 1) {
        if (tid < s) red[tid] = fmaxf(red[tid], red[tid + s]);
        __syncthreads();
    }
    mx = red[0];
    __syncthreads();
    float sum = 0.0f;
#pragma unroll
    for (int t = 0; t < 8; t++) {
        x[t] = __expf(x[t] - mx);
        sum += x[t];
    }
    red[tid] = sum;
    __syncthreads();
    for (int s = 128; s > 0; s >>= 1) {
        if (tid < s) red[tid] += red[tid + s];
        __syncthreads();
    }
    float inv = 1.0f / red[0];
    f16* w = WT + (size_t)rid * KL;
#pragma unroll
    for (int t = 0; t < 4; t++) {
        int j = 2 * (tid + t * 256);
        if (j < tile_end)
            *(f162*)(w + j) = __floats2half2_rn(x[2 * t] * inv, x[2 * t + 1] * inv);
    }
}

// ---------------------------------------------------------------------------
extern "C" void kernel_launch(void* const* d_in, const int* in_sizes, int n_in,
                              void* d_out, int out_size) {
    const float* inputs     = (const float*)d_in[0];
    const float* inputs_mem = (const float*)d_in[1];
    const float* r          = (const float*)d_in[2];
    const float* W          = (const float*)d_in[3];
    const float* W_r        = (const float*)d_in[4];
    const float* W_o        = (const float*)d_in[5];
    const float* u          = (const float*)d_in[6];
    const float* v          = (const float*)d_in[7];
    float* out = (float*)d_out;

    f16 *catH, *W1, *Wr1, *Wo1, *rsH;
    f16 *qkvH, *qkvL, *rpH, *rpL, *attnH, *attnL, *wt, *scores, *bdu;
    float *biasU, *biasV;
    cudaGetSymbolAddress((void**)&catH, g_catH);
    cudaGetSymbolAddress((void**)&W1, g_W1);
    cudaGetSymbolAddress((void**)&Wr1, g_Wr1);
    cudaGetSymbolAddress((void**)&Wo1, g_Wo1);
    cudaGetSymbolAddress((void**)&rsH, g_rsH);
    cudaGetSymbolAddress((void**)&qkvH, g_qkvH);  cudaGetSymbolAddress((void**)&qkvL, g_qkvL);
    cudaGetSymbolAddress((void**)&rpH, g_rpH);    cudaGetSymbolAddress((void**)&rpL, g_rpL);
    cudaGetSymbolAddress((void**)&attnH, g_attnH);cudaGetSymbolAddress((void**)&attnL, g_attnL);
    cudaGetSymbolAddress((void**)&wt, g_wt);
    cudaGetSymbolAddress((void**)&scores, g_scores);
    cudaGetSymbolAddress((void**)&bdu, g_bdu);
    cudaGetSymbolAddress((void**)&biasU, g_biasU);
    cudaGetSymbolAddress((void**)&biasV, g_biasV);

    // smem sizes (bytes)
    const int SM_PROJ = (APL2 + 32 * 136) * 3 * 2;       // 56832 (single A, NT=128)
    const int SM_OUT  = (2 * APL2 + 32 * 136) * 3 * 2;   // 87552 (A-split, NT=128)
    const int SM_V    = (APL2 + 32 * 72) * 3 * 2;        // 44544 (single, NT=64)
    const int SMSC    = 3 * SPL * 2;                     // 55296
    cudaFuncSetAttribute(proj_all, cudaFuncAttributeMaxDynamicSharedMemorySize, SM_PROJ);
    cudaFuncSetAttribute(outgemm,  cudaFuncAttributeMaxDynamicSharedMemorySize, SM_OUT);
    cudaFuncSetAttribute(vgemm,    cudaFuncAttributeMaxDynamicSharedMemorySize, SM_V);
    cudaFuncSetAttribute(score_f16, cudaFuncAttributeMaxDynamicSharedMemorySize, SMSC);

    // 0. ingest (single-fp16 cat/r/W; attn planes still split downstream)
    split_single<<<DM * D3 / 2 / 256, 256>>>(W, W1, DM * D3 / 2);
    split_single<<<DM * DM / 2 / 256, 256>>>(W_r, Wr1, DM * DM / 2);
    split_single<<<DM * DM / 2 / 256, 256>>>(W_o, Wo1, DM * DM / 2);
    split_single<<<KL * DM / 2 / 256, 256>>>(r, rsH, KL * DM / 2);
    build_cat_single<<<BB * KL * DM / 2 / 256, 256>>>(inputs, inputs_mem, catH);
    // 1. merged projections: KV (512 blocks) + Q (128) + rproj (128)
    proj_all<<<768, 256, SM_PROJ>>>(catH, rsH, W1, Wr1, qkvH, qkvL, rpH, rpL);
    // 2. biases (pre-scaled)
    bias_u_kernel<<<BB * NH * KL / 256, 256>>>(qkvH, qkvL, u, biasU);
    bias_v_kernel<<<NH * KL / 256, 256>>>(rpH, rpL, v, biasV);
    // 3. merged score GEMMs (single-plane Q): z<32 AC, z>=32 BD
    score_f16<<<dim3(KL / 256, QL / 128, 2 * BB * NH), 256, SMSC>>>(
        qkvH, rpH, scores, bdu);
    // 4. fused shift+bias+mask+softmax -> fp16 weights
    fused_softmax3<<<BB * NH * QL, 256>>>(scores, bdu, biasU, biasV, wt);
    // 5. attn = weights @ V  (both single) -> planes, K clamped
    vgemm<<<dim3(1, QL / 128, BB * NH), 256, SM_V>>>(wt, qkvH, attnH, attnL);
    // 6. out = attn @ W_o (A split, B single, fp32 out)
    outgemm<<<dim3(DM / 128, BB * QL / 128), 256, SM_OUT>>>(attnH, attnL, Wo1, out);
}

// round 16
// speedup vs baseline: 4.5896x; 1.1105x over previous
#include <cuda_runtime.h>
#include <cuda_fp16.h>
#include <math.h>
#include <stdint.h>

#define BB    2
#define QL    1024
#define MEML  1024
#define KL    2048
#define DM    1024
#define NH    16
#define DK    64
#define D3    3072

typedef __half  f16;
typedef __half2 f162;

// ---------------- scratch (device globals, no allocation) ----------------
__device__ f16 g_catH[BB * KL * DM];
__device__ f16 g_W1[DM * D3];
__device__ f16 g_Wr1[DM * DM];
__device__ f16 g_Wo1[DM * DM];
__device__ f16 g_rsH[KL * DM];
__device__ f16 g_qkvH[BB * KL * D3];
__device__ f16 g_rpH[KL * DM];
__device__ f16 g_attnH[BB * QL * DM], g_attnL[BB * QL * DM];
__device__ f16 g_scores[(size_t)BB * NH * QL * KL];
__device__ f16 g_bdu[(size_t)BB * NH * QL * KL];
__device__ f16 g_wt[(size_t)BB * NH * QL * KL];
__device__ float g_biasU[BB * NH * KL];
__device__ float g_biasV[NH * KL];

// ---------------- helpers ----------------
__device__ __forceinline__ void split1(float x, f16& h, f16& l) {
    h = __float2half_rn(x);
    l = __float2half_rn(x - __half2float(h));
}
__device__ __forceinline__ void cp16(uint32_t dst, const void* src) {
    asm volatile("cp.async.cg.shared.global [%0], [%1], 16;\n" :: "r"(dst), "l"(src));
}
__device__ __forceinline__ void cp_commit() {
    asm volatile("cp.async.commit_group;\n");
}
__device__ __forceinline__ void cp_wait0() {
    asm volatile("cp.async.wait_group 0;\n");
}
__device__ __forceinline__ void cp_wait1() {
    asm volatile("cp.async.wait_group 1;\n");
}
__device__ __forceinline__ void mmaf16(float* d, const uint32_t* a,
                                       const uint32_t* b) {
    asm volatile(
        "mma.sync.aligned.m16n8k16.row.col.f32.f16.f16.f32 "
        "{%0,%1,%2,%3}, {%4,%5,%6,%7}, {%8,%9}, {%0,%1,%2,%3};"
        : "+f"(d[0]), "+f"(d[1]), "+f"(d[2]), "+f"(d[3])
        : "r"(a[0]), "r"(a[1]), "r"(a[2]), "r"(a[3]), "r"(b[0]), "r"(b[1]));
}
#define LDSM4(R, addr)                                                        \
    asm volatile("ldmatrix.sync.aligned.m8n8.x4.shared.b16 {%0,%1,%2,%3}, [%4];" \
                 : "=r"((R)[0]), "=r"((R)[1]), "=r"((R)[2]), "=r"((R)[3])     \
                 : "r"(addr))
#define LDSM4T(R, addr)                                                       \
    asm volatile("ldmatrix.sync.aligned.m8n8.x4.trans.shared.b16 {%0,%1,%2,%3}, [%4];" \
                 : "=r"((R)[0]), "=r"((R)[1]), "=r"((R)[2]), "=r"((R)[3])     \
                 : "r"(addr))

extern __shared__ __align__(16) char dynsm[];

// ---------------- merged ingest: W | Wr | Wo | r | cat ----------------
#define NB_W   6144
#define NB_WR  2048
#define NB_WO  2048
#define NB_R   4096
#define NB_CAT 8192     // BB*KL*DM/2 float2 units / 256 threads

__global__ void ingest_all(const float* __restrict__ W,
                           const float* __restrict__ W_r,
                           const float* __restrict__ W_o,
                           const float* __restrict__ r,
                           const float* __restrict__ inp,
                           const float* __restrict__ mem,
                           f16* __restrict__ W1, f16* __restrict__ Wr1,
                           f16* __restrict__ Wo1, f16* __restrict__ rsH,
                           f16* __restrict__ catH) {
    int id = blockIdx.x;
    if (id < NB_W) {
        int i = id * 256 + threadIdx.x;
        float2 v = *(const float2*)(W + 2 * (size_t)i);
        *(f162*)(W1 + 2 * (size_t)i) = __floats2half2_rn(v.x, v.y);
    } else if (id < NB_W + NB_WR) {
        int i = (id - NB_W) * 256 + threadIdx.x;
        float2 v = *(const float2*)(W_r + 2 * (size_t)i);
        *(f162*)(Wr1 + 2 * (size_t)i) = __floats2half2_rn(v.x, v.y);
    } else if (id < NB_W + NB_WR + NB_WO) {
        int i = (id - NB_W - NB_WR) * 256 + threadIdx.x;
        float2 v = *(const float2*)(W_o + 2 * (size_t)i);
        *(f162*)(Wo1 + 2 * (size_t)i) = __floats2half2_rn(v.x, v.y);
    } else if (id < NB_W + NB_WR + NB_WO + NB_R) {
        int i = (id - NB_W - NB_WR - NB_WO) * 256 + threadIdx.x;
        float2 v = *(const float2*)(r + 2 * (size_t)i);
        *(f162*)(rsH + 2 * (size_t)i) = __floats2half2_rn(v.x, v.y);
    } else {
        int idx = (id - NB_W - NB_WR - NB_WO - NB_R) * 256 + threadIdx.x;
        int per_b = KL * (DM / 2);
        int b = idx / per_b;
        int rem = idx - b * per_b;
        int t = rem / (DM / 2);
        int c = rem - t * (DM / 2);
        const float2* s;
        if (t < MEML) s = (const float2*)(mem + ((size_t)b * MEML + t) * DM) + c;
        else          s = (const float2*)(inp + ((size_t)b * QL + (t - MEML)) * DM) + c;
        float2 v = *s;
        size_t o = ((size_t)b * KL + t) * DM + 2 * c;
        *(f162*)(catH + o) = __floats2half2_rn(v.x, v.y);
    }
}

// ---------------- GEMM body (trans-B, 3-stage cp.async pipeline) ------------
// COUT: 0 = fp32 C, 1 = fp16 hi/lo planes, 2 = fp16 single plane
#define ASTR2 40
#define APL2  (128 * ASTR2)

template <int NT, int ASPL, int BSPL, int COUT>
__device__ __forceinline__ void gemm_body(
    const f16* __restrict__ AbH, const f16* __restrict__ AbL,
    const f16* __restrict__ BbH, const f16* __restrict__ BbL,
    float* __restrict__ Cf, f16* __restrict__ CH, f16* __restrict__ CL,
    int NC, int lda, int ldb, int ldc) {
    constexpr int NTP = NT + 8;
    constexpr int BPL = 32 * NTP;
    constexpr int ANP = ASPL ? 2 : 1;
    constexpr int BNP = BSPL ? 2 : 1;
    constexpr int STG = ANP * APL2 + BNP * BPL;
    constexpr int NJ = NT / 16;
    int tid = threadIdx.x, lane = tid & 31, wid = tid >> 5;
    int wy = wid & 3, wx = wid >> 2;

    f16* sm = (f16*)dynsm;

    auto loadAB = [&](int k0, int s) {
        f16* base = sm + s * STG;
        uint32_t da = (uint32_t)__cvta_generic_to_shared(base);
        uint32_t db = da + ANP * APL2 * 2;
#pragma unroll
        for (int it = 0; it < 2; it++) {
            int e = tid + it * 256;
            int row = e >> 2, ch = (e & 3) << 3;
            size_t src = (size_t)row * lda + k0 + ch;
            uint32_t doff = (uint32_t)(row * ASTR2 + ch) * 2;
            cp16(da + doff, AbH + src);
            if (ASPL) cp16(da + APL2 * 2 + doff, AbL + src);
        }
        constexpr int CPR = NT / 8;
        constexpr int ITB = (32 * CPR) / 256;
#pragma unroll
        for (int it = 0; it < ITB; it++) {
            int e = tid + it * 256;
            int kk = e / CPR, nb = (e % CPR) * 8;
            size_t src = (size_t)(k0 + kk) * ldb + nb;
            uint32_t doff = (uint32_t)(kk * NTP + nb) * 2;
            cp16(db + doff, BbH + src);
            if (BSPL) cp16(db + BPL * 2 + doff, BbL + src);
        }
    };

    float acc[2][NJ][4];
#pragma unroll
    for (int mi = 0; mi < 2; mi++)
#pragma unroll
        for (int nj = 0; nj < NJ; nj++)
#pragma unroll
            for (int q = 0; q < 4; q++) acc[mi][nj][q] = 0.0f;

    loadAB(0, 0); cp_commit();
    if (NC > 1) { loadAB(32, 1); cp_commit(); }

    int arow = (lane & 15);
    int acol = (lane & 16) >> 1;
    int bln = ((lane >> 4) << 3);

    for (int c = 0; c < NC; c++) {
        if (c + 1 < NC) cp_wait1(); else cp_wait0();
        __syncthreads();
        if (c + 2 < NC) { loadAB((c + 2) << 5, (c + 2) % 3); cp_commit(); }
        int s = c % 3;
        uint32_t sa = (uint32_t)__cvta_generic_to_shared(sm + s * STG);
        uint32_t sb = sa + ANP * APL2 * 2;
#pragma unroll
        for (int kk = 0; kk < 32; kk += 16) {
            uint32_t ah[2][4], al[2][4];
#pragma unroll
            for (int mi = 0; mi < 2; mi++) {
                int r = wy * 32 + mi * 16 + arow;
                uint32_t ad = sa + (uint32_t)(r * ASTR2 + kk + acol) * 2;
                LDSM4(ah[mi], ad);
                if (ASPL) LDSM4(al[mi], ad + APL2 * 2);
            }
#pragma unroll
            for (int njp = 0; njp < NJ / 2; njp++) {
                int n16 = wx * (NT / 2) + njp * 16;
                uint32_t bd = sb +
                    (uint32_t)((kk + arow) * NTP + n16 + bln) * 2;
                uint32_t bf[4], blf[4];
                LDSM4T(bf, bd);
                if (BSPL) LDSM4T(blf, bd + BPL * 2);
#pragma unroll
                for (int mi = 0; mi < 2; mi++) {
                    mmaf16(acc[mi][2 * njp + 0], ah[mi], bf + 0);
                    mmaf16(acc[mi][2 * njp + 1], ah[mi], bf + 2);
                    if (ASPL) {
                        mmaf16(acc[mi][2 * njp + 0], al[mi], bf + 0);
                        mmaf16(acc[mi][2 * njp + 1], al[mi], bf + 2);
                    }
                    if (BSPL) {
                        mmaf16(acc[mi][2 * njp + 0], ah[mi], blf + 0);
                        mmaf16(acc[mi][2 * njp + 1], ah[mi], blf + 2);
                    }
                }
            }
        }
    }

#pragma unroll
    for (int mi = 0; mi < 2; mi++) {
#pragma unroll
        for (int nj = 0; nj < NJ; nj++) {
            int r = wy * 32 + mi * 16 + (lane >> 2);
            int ncol = wx * (NT / 2) + nj * 8 + ((lane & 3) << 1);
            if (COUT == 0) {
                *(float2*)&Cf[(size_t)r * ldc + ncol] =
                    make_float2(acc[mi][nj][0], acc[mi][nj][1]);
                *(float2*)&Cf[(size_t)(r + 8) * ldc + ncol] =
                    make_float2(acc[mi][nj][2], acc[mi][nj][3]);
            } else if (COUT == 1) {
#pragma unroll
                for (int hh = 0; hh < 2; hh++) {
                    f16 h0, l0, h1, l1;
                    split1(acc[mi][nj][2 * hh + 0], h0, l0);
                    split1(acc[mi][nj][2 * hh + 1], h1, l1);
                    f162 vh; vh.x = h0; vh.y = h1;
                    f162 vl; vl.x = l0; vl.y = l1;
                    size_t o = (size_t)(r + 8 * hh) * ldc + ncol;
                    *(f162*)(CH + o) = vh;
                    *(f162*)(CL + o) = vl;
                }
            } else {
                *(f162*)(CH + (size_t)r * ldc + ncol) =
                    __floats2half2_rn(acc[mi][nj][0], acc[mi][nj][1]);
                *(f162*)(CH + (size_t)(r + 8) * ldc + ncol) =
                    __floats2half2_rn(acc[mi][nj][2], acc[mi][nj][3]);
            }
        }
    }
}

// ---------------- merged projection launch (single in/out): 768 blocks ------
__global__ __launch_bounds__(256, 2)
void proj_all(const f16* __restrict__ catH, const f16* __restrict__ rsH,
              const f16* __restrict__ W1, const f16* __restrict__ Wr1,
              f16* __restrict__ qkvH, f16* __restrict__ rpH) {
    int id = blockIdx.x;
    if (id < 512) {
        int x = id & 15, y = id >> 4;
        size_t arow = (size_t)(y * 128);
        size_t cbase = arow * D3 + DM + x * 128;
        gemm_body<128, 0, 0, 2>(
            catH + arow * DM, nullptr, W1 + DM + x * 128, nullptr,
            nullptr, qkvH + cbase, nullptr, 32, DM, D3, D3);
    } else if (id < 640) {
        int t = id - 512;
        int x = t & 7, y = t >> 3;
        int b = y >> 3;
        size_t grow = (size_t)(b * KL + MEML + (y & 7) * 128);
        size_t cbase = grow * D3 + x * 128;
        gemm_body<128, 0, 0, 2>(
            catH + grow * DM, nullptr, W1 + x * 128, nullptr,
            nullptr, qkvH + cbase, nullptr, 32, DM, D3, D3);
    } else {
        int t = id - 640;
        int x = t & 7, y = t >> 3;
        size_t arow = (size_t)(y * 128);
        size_t cbase = arow * DM + x * 128;
        gemm_body<128, 0, 0, 2>(
            rsH + arow * DM, nullptr, Wr1 + x * 128, nullptr,
            nullptr, rpH + cbase, nullptr, 32, DM, DM, DM);
    }
}

// ---------------- V GEMM: weights @ V per (b,h), K clamped ------------------
__global__ __launch_bounds__(256, 2)
void vgemm(const f16* __restrict__ wt, const f16* __restrict__ qkvH,
           f16* __restrict__ attnH, f16* __restrict__ attnL) {
    int z = blockIdx.z, b = z >> 4, h = z & 15;
    int m0 = blockIdx.y * 128;
    int km = m0 + 128 + MEML;
    int Klim = (KL < km) ? KL : km;
    const f16* Ab = wt + (size_t)z * QL * KL + (size_t)m0 * KL;
    const f16* Bb = qkvH + 2 * DM + (size_t)b * KL * D3 + (size_t)h * DK;
    size_t cbase = (size_t)b * QL * DM + (size_t)h * DK + (size_t)m0 * DM;
    gemm_body<64, 0, 0, 1>(Ab, nullptr, Bb, nullptr,
                           nullptr, attnH + cbase, attnL + cbase,
                           Klim >> 5, KL, D3, DM);
}

// ---------------- out GEMM: attn @ W_o (A-split, fp32 out) ------------------
__global__ __launch_bounds__(256, 2)
void outgemm(const f16* __restrict__ attnH, const f16* __restrict__ attnL,
             const f16* __restrict__ Wo1, float* __restrict__ out) {
    int m0 = blockIdx.y * 128, n0 = blockIdx.x * 128;
    gemm_body<128, 1, 0, 0>(
        attnH + (size_t)m0 * DM, attnL + (size_t)m0 * DM,
        Wo1 + n0, nullptr,
        out + (size_t)m0 * DM + n0, nullptr, nullptr,
        32, DM, DM, DM);
}

// ---------------- merged score GEMM + bias add: z<32 AC, z>=32 BD -----------
#define SSTR 72
#define SPL  (128 * SSTR)

__global__ __launch_bounds__(256, 2)
void score_f16(const f16* __restrict__ qH, const f16* __restrict__ rp,
               const float* __restrict__ bU, const float* __restrict__ bV,
               f16* __restrict__ AC, f16* __restrict__ BD) {
    int z = blockIdx.z;
    int mode = (z >= BB * NH) ? 1 : 0;
    int bh = mode ? (z - BB * NH) : z;
    int b = bh >> 4, h = bh & 15;
    int i0 = blockIdx.y * 128, j0 = blockIdx.x * 256;
    bool act[2];
    if (mode == 0) {
        act[0] = (j0 - i0) < 1152;
        act[1] = (j0 + 128 - i0) < 1152;
        if (!act[0]) return;
    } else {
        act[0] = (i0 + j0) > 768;
        act[1] = (i0 + j0 + 128) > 768;
        if (!act[1]) return;
    }
    int tid = threadIdx.x, lane = tid & 31, wid = tid >> 5;
    int wy = wid & 3, wx = wid >> 2;

    const float* bias = mode ? (bV + h * KL) : (bU + bh * KL);

    f16* sm = (f16*)dynsm;
    {
        const f16* AbH = qH + (size_t)(b * KL + MEML + i0) * D3 + h * DK;
        uint32_t dh = (uint32_t)__cvta_generic_to_shared(sm);
#pragma unroll
        for (int it = 0; it < 4; it++) {
            int e = tid + it * 256;
            int row = e >> 3, ch = (e & 7) << 3;
            cp16(dh + (uint32_t)(row * SSTR + ch) * 2,
                 AbH + (size_t)row * D3 + ch);
        }
    }
#pragma unroll
    for (int jt = 0; jt < 2; jt++) {
        if (!act[jt]) continue;
        int j1 = j0 + jt * 128;
        const f16* Bb;
        size_t ldrow;
        if (mode == 0) { Bb = qH + (size_t)(b * KL + j1) * D3 + DM + h * DK; ldrow = D3; }
        else           { Bb = rp + (size_t)j1 * DM + h * DK; ldrow = DM; }
        uint32_t dh = (uint32_t)__cvta_generic_to_shared(sm + (1 + jt) * SPL);
#pragma unroll
        for (int it = 0; it < 4; it++) {
            int e = tid + it * 256;
            int row = e >> 3, ch = (e & 7) << 3;
            cp16(dh + (uint32_t)(row * SSTR + ch) * 2, Bb + (size_t)row * ldrow + ch);
        }
    }
    cp_commit();
    cp_wait0();
    __syncthreads();

    int arow = (lane & 15);
    int acol = (lane & 16) >> 1;
    int brow = (lane & 7) + ((lane & 16) >> 1);
    int bcol = (lane & 8);
    uint32_t sa = (uint32_t)__cvta_generic_to_shared(sm);

    f16* Cb = (mode ? BD : AC) + (size_t)bh * QL * KL;
#pragma unroll
    for (int jt = 0; jt < 2; jt++) {
        if (!act[jt]) continue;
        uint32_t sb = sa + (1 + jt) * SPL * 2;
        float acc[2][8][4];
#pragma unroll
        for (int mi = 0; mi < 2; mi++)
#pragma unroll
            for (int nj = 0; nj < 8; nj++)
#pragma unroll
                for (int q = 0; q < 4; q++) acc[mi][nj][q] = 0.0f;
#pragma unroll
        for (int kk = 0; kk < 64; kk += 16) {
            uint32_t ah[2][4];
#pragma unroll
            for (int mi = 0; mi < 2; mi++) {
                int r = wy * 32 + mi * 16 + arow;
                uint32_t ad = sa + (uint32_t)(r * SSTR + kk + acol) * 2;
                LDSM4(ah[mi], ad);
            }
#pragma unroll
            for (int njp = 0; njp < 4; njp++) {
                int n = wx * 64 + njp * 16 + brow;
                uint32_t bd = sb + (uint32_t)(n * SSTR + kk + bcol) * 2;
                uint32_t bf[4];
                LDSM4(bf, bd);
#pragma unroll
                for (int mi = 0; mi < 2; mi++) {
                    mmaf16(acc[mi][2 * njp + 0], ah[mi], bf + 0);
                    mmaf16(acc[mi][2 * njp + 1], ah[mi], bf + 2);
                }
            }
        }
        int j1 = j0 + jt * 128;
#pragma unroll
        for (int mi = 0; mi < 2; mi++) {
#pragma unroll
            for (int nj = 0; nj < 8; nj++) {
                int r = i0 + wy * 32 + mi * 16 + (lane >> 2);
                int ncol = j1 + wx * 64 + nj * 8 + ((lane & 3) << 1);
                float2 bb0 = *(const float2*)(bias + ncol);
                *(f162*)&Cb[(size_t)r * KL + ncol] =
                    __floats2half2_rn(acc[mi][nj][0] * 0.125f + bb0.x,
                                      acc[mi][nj][1] * 0.125f + bb0.y);
                *(f162*)&Cb[(size_t)(r + 8) * KL + ncol] =
                    __floats2half2_rn(acc[mi][nj][2] * 0.125f + bb0.x,
                                      acc[mi][nj][3] * 0.125f + bb0.y);
            }
        }
    }
}

// ---------------- bias kernels (pre-scaled by 0.125, single-plane in) -------
__global__ void bias_u_kernel(const f16* __restrict__ kH,
                              const float* __restrict__ u,
                              float* __restrict__ bU) {
    int idx = blockIdx.x * 256 + threadIdx.x;
    int bh = idx >> 11, j = idx & 2047;
    int b = bh >> 4, h = bh & 15;
    const f16* ph = kH + (size_t)(b * KL + j) * D3 + DM + h * DK;
    const float* uu = u + h * DK;
    float s = 0.0f;
#pragma unroll
    for (int d = 0; d < DK; d++)
        s += __half2float(ph[d]) * uu[d];
    bU[idx] = s * 0.125f;
}
__global__ void bias_v_kernel(const f16* __restrict__ rpH,
                              const float* __restrict__ v,
                              float* __restrict__ bV) {
    int idx = blockIdx.x * 256 + threadIdx.x;
    int h = idx >> 11, p = idx & 2047;
    const f16* ph = rpH + (size_t)p * DM + h * DK;
    const float* vv = v + h * DK;
    float s = 0.0f;
#pragma unroll
    for (int d = 0; d < DK; d++)
        s += __half2float(ph[d]) * vv[d];
    bV[idx] = s * 0.125f;
}

// ---------------- fused shift+mask+softmax -> fp16 weights ------------------
__global__ __launch_bounds__(256)
void fused_softmax3(const f16* __restrict__ AC, const f16* __restrict__ U,
                    f16* __restrict__ WT) {
    int rid = blockIdx.x;
    int i = rid & 1023;
    const f16* p = AC + (size_t)rid * KL;
    const f16* q = U + (size_t)rid * KL + (QL - 1 - i);   // odd offset — scalar loads only
    int jmax = i + MEML;
    int tile_end = (i & ~127) + 128 + MEML;
    int tid = threadIdx.x;
    __shared__ float red[256];
    float x[8];
    float mx = -INFINITY;
#pragma unroll
    for (int t = 0; t < 4; t++) {
        int j = 2 * (tid + t * 256);
        float x0 = -INFINITY, x1 = -INFINITY;
        if (j < jmax) {
            f162 pv = *(const f162*)(p + j);
            x0 = __half2float(pv.x) + __half2float(q[j]);
            x1 = __half2float(pv.y) + __half2float(q[j + 1]);
        } else if (j == jmax) {
            x0 = __half2float(p[j]) + __half2float(q[j]);
        }
        x[2 * t + 0] = x0;
        x[2 * t + 1] = x1;
        mx = fmaxf(mx, fmaxf(x0, x1));
    }
    red[tid] = mx;
    __syncthreads();
    for (int s = 128; s > 0; s >>= 1) {
        if (tid < s) red[tid] = fmaxf(red[tid], red[tid + s]);
        __syncthreads();
    }
    mx = red[0];
    __syncthreads();
    float sum = 0.0f;
#pragma unroll
    for (int t = 0; t < 8; t++) {
        x[t] = __expf(x[t] - mx);
        sum += x[t];
    }
    red[tid] = sum;
    __syncthreads();
    for (int s = 128; s > 0; s >>= 1) {
        if (tid < s) red[tid] += red[tid + s];
        __syncthreads();
    }
    float inv = 1.0f / red[0];
    f16* w = WT + (size_t)rid * KL;
#pragma unroll
    for (int t = 0; t < 4; t++) {
        int j = 2 * (tid + t * 256);
        if (j < tile_end)
            *(f162*)(w + j) = __floats2half2_rn(x[2 * t] * inv, x[2 * t + 1] * inv);
    }
}

// ---------------------------------------------------------------------------
extern "C" void kernel_launch(void* const* d_in, const int* in_sizes, int n_in,
                              void* d_out, int out_size) {
    const float* inputs     = (const float*)d_in[0];
    const float* inputs_mem = (const float*)d_in[1];
    const float* r          = (const float*)d_in[2];
    const float* W          = (const float*)d_in[3];
    const float* W_r        = (const float*)d_in[4];
    const float* W_o        = (const float*)d_in[5];
    const float* u          = (const float*)d_in[6];
    const float* v          = (const float*)d_in[7];
    float* out = (float*)d_out;

    f16 *catH, *W1, *Wr1, *Wo1, *rsH;
    f16 *qkvH, *rpH, *attnH, *attnL, *wt, *scores, *bdu;
    float *biasU, *biasV;
    cudaGetSymbolAddress((void**)&catH, g_catH);
    cudaGetSymbolAddress((void**)&W1, g_W1);
    cudaGetSymbolAddress((void**)&Wr1, g_Wr1);
    cudaGetSymbolAddress((void**)&Wo1, g_Wo1);
    cudaGetSymbolAddress((void**)&rsH, g_rsH);
    cudaGetSymbolAddress((void**)&qkvH, g_qkvH);
    cudaGetSymbolAddress((void**)&rpH, g_rpH);
    cudaGetSymbolAddress((void**)&attnH, g_attnH);cudaGetSymbolAddress((void**)&attnL, g_attnL);
    cudaGetSymbolAddress((void**)&wt, g_wt);
    cudaGetSymbolAddress((void**)&scores, g_scores);
    cudaGetSymbolAddress((void**)&bdu, g_bdu);
    cudaGetSymbolAddress((void**)&biasU, g_biasU);
    cudaGetSymbolAddress((void**)&biasV, g_biasV);

    // smem sizes (bytes)
    const int SM_PROJ = (APL2 + 32 * 136) * 3 * 2;       // 56832
    const int SM_OUT  = (2 * APL2 + 32 * 136) * 3 * 2;   // 87552
    const int SM_V    = (APL2 + 32 * 72) * 3 * 2;        // 44544
    const int SMSC    = 3 * SPL * 2;                     // 55296
    cudaFuncSetAttribute(proj_all, cudaFuncAttributeMaxDynamicSharedMemorySize, SM_PROJ);
    cudaFuncSetAttribute(outgemm,  cudaFuncAttributeMaxDynamicSharedMemorySize, SM_OUT);
    cudaFuncSetAttribute(vgemm,    cudaFuncAttributeMaxDynamicSharedMemorySize, SM_V);
    cudaFuncSetAttribute(score_f16, cudaFuncAttributeMaxDynamicSharedMemorySize, SMSC);

    // 0. merged ingest
    ingest_all<<<NB_W + NB_WR + NB_WO + NB_R + NB_CAT, 256>>>(
        W, W_r, W_o, r, inputs, inputs_mem, W1, Wr1, Wo1, rsH, catH);
    // 1. merged projections (single-plane out): KV + Q + rproj
    proj_all<<<768, 256, SM_PROJ>>>(catH, rsH, W1, Wr1, qkvH, rpH);
    // 2. biases (pre-scaled)
    bias_u_kernel<<<BB * NH * KL / 256, 256>>>(qkvH, u, biasU);
    bias_v_kernel<<<NH * KL / 256, 256>>>(rpH, v, biasV);
    // 3. merged score GEMMs + bias add: z<32 AC, z>=32 BD
    score_f16<<<dim3(KL / 256, QL / 128, 2 * BB * NH), 256, SMSC>>>(
        qkvH, rpH, biasU, biasV, scores, bdu);
    // 4. fused shift+mask+softmax -> fp16 weights
    fused_softmax3<<<BB * NH * QL, 256>>>(scores, bdu, wt);
    // 5. attn = weights @ V -> planes, K clamped
    vgemm<<<dim3(1, QL / 128, BB * NH), 256, SM_V>>>(wt, qkvH, attnH, attnL);
    // 6. out = attn @ W_o (A split, fp32 out)
    outgemm<<<dim3(DM / 128, BB * QL / 128), 256, SM_OUT>>>(attnH, attnL, Wo1, out);
}

// round 17
// speedup vs baseline: 4.8785x; 1.0630x over previous
#include <cuda_runtime.h>
#include <cuda_fp16.h>
#include <math.h>
#include <stdint.h>

#define BB    2
#define QL    1024
#define MEML  1024
#define KL    2048
#define DM    1024
#define NH    16
#define DK    64
#define D3    3072

typedef __half  f16;
typedef __half2 f162;

// ---------------- scratch (device globals, no allocation) ----------------
__device__ f16 g_catH[BB * KL * DM];
__device__ f16 g_W1[DM * D3];
__device__ f16 g_Wr1[DM * DM];
__device__ f16 g_Wo1[DM * DM];
__device__ f16 g_rsH[KL * DM];
__device__ f16 g_qkvH[BB * KL * D3];
__device__ f16 g_rpH[KL * DM];
__device__ f16 g_attnH[BB * QL * DM], g_attnL[BB * QL * DM];
__device__ f16 g_scores[(size_t)BB * NH * QL * KL];
__device__ f16 g_bdu[(size_t)BB * NH * QL * KL];
__device__ f16 g_wt[(size_t)BB * NH * QL * KL];
__device__ float g_biasU[BB * NH * KL];
__device__ float g_biasV[NH * KL];

// ---------------- helpers ----------------
__device__ __forceinline__ void split1(float x, f16& h, f16& l) {
    h = __float2half_rn(x);
    l = __float2half_rn(x - __half2float(h));
}
__device__ __forceinline__ void cp16(uint32_t dst, const void* src) {
    asm volatile("cp.async.cg.shared.global [%0], [%1], 16;\n" :: "r"(dst), "l"(src));
}
__device__ __forceinline__ void cp_commit() {
    asm volatile("cp.async.commit_group;\n");
}
__device__ __forceinline__ void cp_wait0() {
    asm volatile("cp.async.wait_group 0;\n");
}
__device__ __forceinline__ void cp_wait1() {
    asm volatile("cp.async.wait_group 1;\n");
}
__device__ __forceinline__ void mmaf16(float* d, const uint32_t* a,
                                       const uint32_t* b) {
    asm volatile(
        "mma.sync.aligned.m16n8k16.row.col.f32.f16.f16.f32 "
        "{%0,%1,%2,%3}, {%4,%5,%6,%7}, {%8,%9}, {%0,%1,%2,%3};"
        : "+f"(d[0]), "+f"(d[1]), "+f"(d[2]), "+f"(d[3])
        : "r"(a[0]), "r"(a[1]), "r"(a[2]), "r"(a[3]), "r"(b[0]), "r"(b[1]));
}
#define LDSM4(R, addr)                                                        \
    asm volatile("ldmatrix.sync.aligned.m8n8.x4.shared.b16 {%0,%1,%2,%3}, [%4];" \
                 : "=r"((R)[0]), "=r"((R)[1]), "=r"((R)[2]), "=r"((R)[3])     \
                 : "r"(addr))
#define LDSM4T(R, addr)                                                       \
    asm volatile("ldmatrix.sync.aligned.m8n8.x4.trans.shared.b16 {%0,%1,%2,%3}, [%4];" \
                 : "=r"((R)[0]), "=r"((R)[1]), "=r"((R)[2]), "=r"((R)[3])     \
                 : "r"(addr))

extern __shared__ __align__(16) char dynsm[];

// ---------------- merged ingest: W | Wr | Wo | r | cat ----------------
#define NB_W   6144
#define NB_WR  2048
#define NB_WO  2048
#define NB_R   4096
#define NB_CAT 8192     // BB*KL*DM/2 float2 units / 256 threads

__global__ void ingest_all(const float* __restrict__ W,
                           const float* __restrict__ W_r,
                           const float* __restrict__ W_o,
                           const float* __restrict__ r,
                           const float* __restrict__ inp,
                           const float* __restrict__ mem,
                           f16* __restrict__ W1, f16* __restrict__ Wr1,
                           f16* __restrict__ Wo1, f16* __restrict__ rsH,
                           f16* __restrict__ catH) {
    int id = blockIdx.x;
    if (id < NB_W) {
        int i = id * 256 + threadIdx.x;
        float2 v = *(const float2*)(W + 2 * (size_t)i);
        *(f162*)(W1 + 2 * (size_t)i) = __floats2half2_rn(v.x, v.y);
    } else if (id < NB_W + NB_WR) {
        int i = (id - NB_W) * 256 + threadIdx.x;
        float2 v = *(const float2*)(W_r + 2 * (size_t)i);
        *(f162*)(Wr1 + 2 * (size_t)i) = __floats2half2_rn(v.x, v.y);
    } else if (id < NB_W + NB_WR + NB_WO) {
        int i = (id - NB_W - NB_WR) * 256 + threadIdx.x;
        float2 v = *(const float2*)(W_o + 2 * (size_t)i);
        *(f162*)(Wo1 + 2 * (size_t)i) = __floats2half2_rn(v.x, v.y);
    } else if (id < NB_W + NB_WR + NB_WO + NB_R) {
        int i = (id - NB_W - NB_WR - NB_WO) * 256 + threadIdx.x;
        float2 v = *(const float2*)(r + 2 * (size_t)i);
        *(f162*)(rsH + 2 * (size_t)i) = __floats2half2_rn(v.x, v.y);
    } else {
        int idx = (id - NB_W - NB_WR - NB_WO - NB_R) * 256 + threadIdx.x;
        int per_b = KL * (DM / 2);
        int b = idx / per_b;
        int rem = idx - b * per_b;
        int t = rem / (DM / 2);
        int c = rem - t * (DM / 2);
        const float2* s;
        if (t < MEML) s = (const float2*)(mem + ((size_t)b * MEML + t) * DM) + c;
        else          s = (const float2*)(inp + ((size_t)b * QL + (t - MEML)) * DM) + c;
        float2 v = *s;
        size_t o = ((size_t)b * KL + t) * DM + 2 * c;
        *(f162*)(catH + o) = __floats2half2_rn(v.x, v.y);
    }
}

// ---------------- GEMM body (trans-B, 3-stage cp.async pipeline) ------------
// COUT: 0 = fp32 C, 1 = fp16 hi/lo planes, 2 = fp16 single plane
#define ASTR2 40
#define APL2  (128 * ASTR2)

template <int NT, int ASPL, int BSPL, int COUT>
__device__ __forceinline__ void gemm_body(
    const f16* __restrict__ AbH, const f16* __restrict__ AbL,
    const f16* __restrict__ BbH, const f16* __restrict__ BbL,
    float* __restrict__ Cf, f16* __restrict__ CH, f16* __restrict__ CL,
    int NC, int lda, int ldb, int ldc) {
    constexpr int NTP = NT + 8;
    constexpr int BPL = 32 * NTP;
    constexpr int ANP = ASPL ? 2 : 1;
    constexpr int BNP = BSPL ? 2 : 1;
    constexpr int STG = ANP * APL2 + BNP * BPL;
    constexpr int NJ = NT / 16;
    int tid = threadIdx.x, lane = tid & 31, wid = tid >> 5;
    int wy = wid & 3, wx = wid >> 2;

    f16* sm = (f16*)dynsm;

    auto loadAB = [&](int k0, int s) {
        f16* base = sm + s * STG;
        uint32_t da = (uint32_t)__cvta_generic_to_shared(base);
        uint32_t db = da + ANP * APL2 * 2;
#pragma unroll
        for (int it = 0; it < 2; it++) {
            int e = tid + it * 256;
            int row = e >> 2, ch = (e & 3) << 3;
            size_t src = (size_t)row * lda + k0 + ch;
            uint32_t doff = (uint32_t)(row * ASTR2 + ch) * 2;
            cp16(da + doff, AbH + src);
            if (ASPL) cp16(da + APL2 * 2 + doff, AbL + src);
        }
        constexpr int CPR = NT / 8;
        constexpr int ITB = (32 * CPR) / 256;
#pragma unroll
        for (int it = 0; it < ITB; it++) {
            int e = tid + it * 256;
            int kk = e / CPR, nb = (e % CPR) * 8;
            size_t src = (size_t)(k0 + kk) * ldb + nb;
            uint32_t doff = (uint32_t)(kk * NTP + nb) * 2;
            cp16(db + doff, BbH + src);
            if (BSPL) cp16(db + BPL * 2 + doff, BbL + src);
        }
    };

    float acc[2][NJ][4];
#pragma unroll
    for (int mi = 0; mi < 2; mi++)
#pragma unroll
        for (int nj = 0; nj < NJ; nj++)
#pragma unroll
            for (int q = 0; q < 4; q++) acc[mi][nj][q] = 0.0f;

    loadAB(0, 0); cp_commit();
    if (NC > 1) { loadAB(32, 1); cp_commit(); }

    int arow = (lane & 15);
    int acol = (lane & 16) >> 1;
    int bln = ((lane >> 4) << 3);

    for (int c = 0; c < NC; c++) {
        if (c + 1 < NC) cp_wait1(); else cp_wait0();
        __syncthreads();
        if (c + 2 < NC) { loadAB((c + 2) << 5, (c + 2) % 3); cp_commit(); }
        int s = c % 3;
        uint32_t sa = (uint32_t)__cvta_generic_to_shared(sm + s * STG);
        uint32_t sb = sa + ANP * APL2 * 2;
#pragma unroll
        for (int kk = 0; kk < 32; kk += 16) {
            uint32_t ah[2][4], al[2][4];
#pragma unroll
            for (int mi = 0; mi < 2; mi++) {
                int r = wy * 32 + mi * 16 + arow;
                uint32_t ad = sa + (uint32_t)(r * ASTR2 + kk + acol) * 2;
                LDSM4(ah[mi], ad);
                if (ASPL) LDSM4(al[mi], ad + APL2 * 2);
            }
#pragma unroll
            for (int njp = 0; njp < NJ / 2; njp++) {
                int n16 = wx * (NT / 2) + njp * 16;
                uint32_t bd = sb +
                    (uint32_t)((kk + arow) * NTP + n16 + bln) * 2;
                uint32_t bf[4], blf[4];
                LDSM4T(bf, bd);
                if (BSPL) LDSM4T(blf, bd + BPL * 2);
#pragma unroll
                for (int mi = 0; mi < 2; mi++) {
                    mmaf16(acc[mi][2 * njp + 0], ah[mi], bf + 0);
                    mmaf16(acc[mi][2 * njp + 1], ah[mi], bf + 2);
                    if (ASPL) {
                        mmaf16(acc[mi][2 * njp + 0], al[mi], bf + 0);
                        mmaf16(acc[mi][2 * njp + 1], al[mi], bf + 2);
                    }
                    if (BSPL) {
                        mmaf16(acc[mi][2 * njp + 0], ah[mi], blf + 0);
                        mmaf16(acc[mi][2 * njp + 1], ah[mi], blf + 2);
                    }
                }
            }
        }
    }

#pragma unroll
    for (int mi = 0; mi < 2; mi++) {
#pragma unroll
        for (int nj = 0; nj < NJ; nj++) {
            int r = wy * 32 + mi * 16 + (lane >> 2);
            int ncol = wx * (NT / 2) + nj * 8 + ((lane & 3) << 1);
            if (COUT == 0) {
                *(float2*)&Cf[(size_t)r * ldc + ncol] =
                    make_float2(acc[mi][nj][0], acc[mi][nj][1]);
                *(float2*)&Cf[(size_t)(r + 8) * ldc + ncol] =
                    make_float2(acc[mi][nj][2], acc[mi][nj][3]);
            } else if (COUT == 1) {
#pragma unroll
                for (int hh = 0; hh < 2; hh++) {
                    f16 h0, l0, h1, l1;
                    split1(acc[mi][nj][2 * hh + 0], h0, l0);
                    split1(acc[mi][nj][2 * hh + 1], h1, l1);
                    f162 vh; vh.x = h0; vh.y = h1;
                    f162 vl; vl.x = l0; vl.y = l1;
                    size_t o = (size_t)(r + 8 * hh) * ldc + ncol;
                    *(f162*)(CH + o) = vh;
                    *(f162*)(CL + o) = vl;
                }
            } else {
                *(f162*)(CH + (size_t)r * ldc + ncol) =
                    __floats2half2_rn(acc[mi][nj][0], acc[mi][nj][1]);
                *(f162*)(CH + (size_t)(r + 8) * ldc + ncol) =
                    __floats2half2_rn(acc[mi][nj][2], acc[mi][nj][3]);
            }
        }
    }
}

// ---------------- merged projection launch (single in/out): 768 blocks ------
__global__ __launch_bounds__(256, 2)
void proj_all(const f16* __restrict__ catH, const f16* __restrict__ rsH,
              const f16* __restrict__ W1, const f16* __restrict__ Wr1,
              f16* __restrict__ qkvH, f16* __restrict__ rpH) {
    int id = blockIdx.x;
    if (id < 512) {
        int x = id & 15, y = id >> 4;
        size_t arow = (size_t)(y * 128);
        size_t cbase = arow * D3 + DM + x * 128;
        gemm_body<128, 0, 0, 2>(
            catH + arow * DM, nullptr, W1 + DM + x * 128, nullptr,
            nullptr, qkvH + cbase, nullptr, 32, DM, D3, D3);
    } else if (id < 640) {
        int t = id - 512;
        int x = t & 7, y = t >> 3;
        int b = y >> 3;
        size_t grow = (size_t)(b * KL + MEML + (y & 7) * 128);
        size_t cbase = grow * D3 + x * 128;
        gemm_body<128, 0, 0, 2>(
            catH + grow * DM, nullptr, W1 + x * 128, nullptr,
            nullptr, qkvH + cbase, nullptr, 32, DM, D3, D3);
    } else {
        int t = id - 640;
        int x = t & 7, y = t >> 3;
        size_t arow = (size_t)(y * 128);
        size_t cbase = arow * DM + x * 128;
        gemm_body<128, 0, 0, 2>(
            rsH + arow * DM, nullptr, Wr1 + x * 128, nullptr,
            nullptr, rpH + cbase, nullptr, 32, DM, DM, DM);
    }
}

// ---------------- V GEMM: weights @ V per (b,h), K clamped ------------------
__global__ __launch_bounds__(256, 2)
void vgemm(const f16* __restrict__ wt, const f16* __restrict__ qkvH,
           f16* __restrict__ attnH, f16* __restrict__ attnL) {
    int z = blockIdx.z, b = z >> 4, h = z & 15;
    int m0 = blockIdx.y * 128;
    int km = m0 + 128 + MEML;
    int Klim = (KL < km) ? KL : km;
    const f16* Ab = wt + (size_t)z * QL * KL + (size_t)m0 * KL;
    const f16* Bb = qkvH + 2 * DM + (size_t)b * KL * D3 + (size_t)h * DK;
    size_t cbase = (size_t)b * QL * DM + (size_t)h * DK + (size_t)m0 * DM;
    gemm_body<64, 0, 0, 1>(Ab, nullptr, Bb, nullptr,
                           nullptr, attnH + cbase, attnL + cbase,
                           Klim >> 5, KL, D3, DM);
}

// ---------------- out GEMM: attn @ W_o (A-split, fp32 out) ------------------
__global__ __launch_bounds__(256, 2)
void outgemm(const f16* __restrict__ attnH, const f16* __restrict__ attnL,
             const f16* __restrict__ Wo1, float* __restrict__ out) {
    int m0 = blockIdx.y * 128, n0 = blockIdx.x * 128;
    gemm_body<128, 1, 0, 0>(
        attnH + (size_t)m0 * DM, attnL + (size_t)m0 * DM,
        Wo1 + n0, nullptr,
        out + (size_t)m0 * DM + n0, nullptr, nullptr,
        32, DM, DM, DM);
}

// ---------------- merged score GEMM + bias add: z<32 AC, z>=32 BD -----------
#define SSTR 72
#define SPL  (128 * SSTR)

__global__ __launch_bounds__(256, 2)
void score_f16(const f16* __restrict__ qH, const f16* __restrict__ rp,
               const float* __restrict__ bU, const float* __restrict__ bV,
               f16* __restrict__ AC, f16* __restrict__ BD) {
    int z = blockIdx.z;
    int mode = (z >= BB * NH) ? 1 : 0;
    int bh = mode ? (z - BB * NH) : z;
    int b = bh >> 4, h = bh & 15;
    int i0 = blockIdx.y * 128, j0 = blockIdx.x * 256;
    bool act[2];
    if (mode == 0) {
        act[0] = (j0 - i0) < 1152;
        act[1] = (j0 + 128 - i0) < 1152;
        if (!act[0]) return;
    } else {
        act[0] = (i0 + j0) > 768;
        act[1] = (i0 + j0 + 128) > 768;
        if (!act[1]) return;
    }
    int tid = threadIdx.x, lane = tid & 31, wid = tid >> 5;
    int wy = wid & 3, wx = wid >> 2;

    const float* bias = mode ? (bV + h * KL) : (bU + bh * KL);

    f16* sm = (f16*)dynsm;
    {
        const f16* AbH = qH + (size_t)(b * KL + MEML + i0) * D3 + h * DK;
        uint32_t dh = (uint32_t)__cvta_generic_to_shared(sm);
#pragma unroll
        for (int it = 0; it < 4; it++) {
            int e = tid + it * 256;
            int row = e >> 3, ch = (e & 7) << 3;
            cp16(dh + (uint32_t)(row * SSTR + ch) * 2,
                 AbH + (size_t)row * D3 + ch);
        }
    }
#pragma unroll
    for (int jt = 0; jt < 2; jt++) {
        if (!act[jt]) continue;
        int j1 = j0 + jt * 128;
        const f16* Bb;
        size_t ldrow;
        if (mode == 0) { Bb = qH + (size_t)(b * KL + j1) * D3 + DM + h * DK; ldrow = D3; }
        else           { Bb = rp + (size_t)j1 * DM + h * DK; ldrow = DM; }
        uint32_t dh = (uint32_t)__cvta_generic_to_shared(sm + (1 + jt) * SPL);
#pragma unroll
        for (int it = 0; it < 4; it++) {
            int e = tid + it * 256;
            int row = e >> 3, ch = (e & 7) << 3;
            cp16(dh + (uint32_t)(row * SSTR + ch) * 2, Bb + (size_t)row * ldrow + ch);
        }
    }
    cp_commit();
    cp_wait0();
    __syncthreads();

    int arow = (lane & 15);
    int acol = (lane & 16) >> 1;
    int brow = (lane & 7) + ((lane & 16) >> 1);
    int bcol = (lane & 8);
    uint32_t sa = (uint32_t)__cvta_generic_to_shared(sm);

    f16* Cb = (mode ? BD : AC) + (size_t)bh * QL * KL;
#pragma unroll
    for (int jt = 0; jt < 2; jt++) {
        if (!act[jt]) continue;
        uint32_t sb = sa + (1 + jt) * SPL * 2;
        float acc[2][8][4];
#pragma unroll
        for (int mi = 0; mi < 2; mi++)
#pragma unroll
            for (int nj = 0; nj < 8; nj++)
#pragma unroll
                for (int q = 0; q < 4; q++) acc[mi][nj][q] = 0.0f;
#pragma unroll
        for (int kk = 0; kk < 64; kk += 16) {
            uint32_t ah[2][4];
#pragma unroll
            for (int mi = 0; mi < 2; mi++) {
                int r = wy * 32 + mi * 16 + arow;
                uint32_t ad = sa + (uint32_t)(r * SSTR + kk + acol) * 2;
                LDSM4(ah[mi], ad);
            }
#pragma unroll
            for (int njp = 0; njp < 4; njp++) {
                int n = wx * 64 + njp * 16 + brow;
                uint32_t bd = sb + (uint32_t)(n * SSTR + kk + bcol) * 2;
                uint32_t bf[4];
                LDSM4(bf, bd);
#pragma unroll
                for (int mi = 0; mi < 2; mi++) {
                    mmaf16(acc[mi][2 * njp + 0], ah[mi], bf + 0);
                    mmaf16(acc[mi][2 * njp + 1], ah[mi], bf + 2);
                }
            }
        }
        int j1 = j0 + jt * 128;
#pragma unroll
        for (int mi = 0; mi < 2; mi++) {
#pragma unroll
            for (int nj = 0; nj < 8; nj++) {
                int r = i0 + wy * 32 + mi * 16 + (lane >> 2);
                int ncol = j1 + wx * 64 + nj * 8 + ((lane & 3) << 1);
                float2 bb0 = *(const float2*)(bias + ncol);
                *(f162*)&Cb[(size_t)r * KL + ncol] =
                    __floats2half2_rn(acc[mi][nj][0] * 0.125f + bb0.x,
                                      acc[mi][nj][1] * 0.125f + bb0.y);
                *(f162*)&Cb[(size_t)(r + 8) * KL + ncol] =
                    __floats2half2_rn(acc[mi][nj][2] * 0.125f + bb0.x,
                                      acc[mi][nj][3] * 0.125f + bb0.y);
            }
        }
    }
}

// ---------------- merged vectorized bias kernel ----------------
// outputs: bU (65536) then bV (32768); one thread per output, 8x 16B loads
__global__ void bias_all(const f16* __restrict__ qkvH,
                         const f16* __restrict__ rpH,
                         const float* __restrict__ u,
                         const float* __restrict__ v,
                         float* __restrict__ bU, float* __restrict__ bV) {
    int idx = blockIdx.x * 256 + threadIdx.x;
    const f16* ph;
    const float* w;
    float* outp;
    int oi;
    if (idx < BB * NH * KL) {
        int bh = idx >> 11, j = idx & 2047;
        int b = bh >> 4, h = bh & 15;
        ph = qkvH + (size_t)(b * KL + j) * D3 + DM + h * DK;
        w = u + h * DK;
        outp = bU; oi = idx;
    } else {
        int t = idx - BB * NH * KL;
        int h = t >> 11, p = t & 2047;
        ph = rpH + (size_t)p * DM + h * DK;
        w = v + h * DK;
        outp = bV; oi = t;
    }
    float s = 0.0f;
#pragma unroll
    for (int c = 0; c < 8; c++) {
        uint4 pk = *(const uint4*)(ph + c * 8);       // 8 halves
        float4 w0 = *(const float4*)(w + c * 8);
        float4 w1 = *(const float4*)(w + c * 8 + 4);
        f162 p0 = *(f162*)&pk.x, p1 = *(f162*)&pk.y;
        f162 p2 = *(f162*)&pk.z, p3 = *(f162*)&pk.w;
        s += __half2float(p0.x) * w0.x + __half2float(p0.y) * w0.y;
        s += __half2float(p1.x) * w0.z + __half2float(p1.y) * w0.w;
        s += __half2float(p2.x) * w1.x + __half2float(p2.y) * w1.y;
        s += __half2float(p3.x) * w1.z + __half2float(p3.y) * w1.w;
    }
    outp[oi] = s * 0.125f;
}

// ---------------- fused shift+mask+softmax -> fp16 weights ------------------
__global__ __launch_bounds__(256)
void fused_softmax3(const f16* __restrict__ AC, const f16* __restrict__ U,
                    f16* __restrict__ WT) {
    int rid = blockIdx.x;
    int i = rid & 1023;
    const f16* p = AC + (size_t)rid * KL;
    const f16* q = U + (size_t)rid * KL + (QL - 1 - i);   // odd offset — scalar loads only
    int jmax = i + MEML;
    int tile_end = (i & ~127) + 128 + MEML;
    int tid = threadIdx.x;
    __shared__ float red[256];
    float x[8];
    float mx = -INFINITY;
#pragma unroll
    for (int t = 0; t < 4; t++) {
        int j = 2 * (tid + t * 256);
        float x0 = -INFINITY, x1 = -INFINITY;
        if (j < jmax) {
            f162 pv = *(const f162*)(p + j);
            x0 = __half2float(pv.x) + __half2float(q[j]);
            x1 = __half2float(pv.y) + __half2float(q[j + 1]);
        } else if (j == jmax) {
            x0 = __half2float(p[j]) + __half2float(q[j]);
        }
        x[2 * t + 0] = x0;
        x[2 * t + 1] = x1;
        mx = fmaxf(mx, fmaxf(x0, x1));
    }
    red[tid] = mx;
    __syncthreads();
    for (int s = 128; s > 0; s >>= 1) {
        if (tid < s) red[tid] = fmaxf(red[tid], red[tid + s]);
        __syncthreads();
    }
    mx = red[0];
    __syncthreads();
    float sum = 0.0f;
#pragma unroll
    for (int t = 0; t < 8; t++) {
        x[t] = __expf(x[t] - mx);
        sum += x[t];
    }
    red[tid] = sum;
    __syncthreads();
    for (int s = 128; s > 0; s >>= 1) {
        if (tid < s) red[tid] += red[tid + s];
        __syncthreads();
    }
    float inv = 1.0f / red[0];
    f16* w = WT + (size_t)rid * KL;
#pragma unroll
    for (int t = 0; t < 4; t++) {
        int j = 2 * (tid + t * 256);
        if (j < tile_end)
            *(f162*)(w + j) = __floats2half2_rn(x[2 * t] * inv, x[2 * t + 1] * inv);
    }
}

// ---------------------------------------------------------------------------
extern "C" void kernel_launch(void* const* d_in, const int* in_sizes, int n_in,
                              void* d_out, int out_size) {
    const float* inputs     = (const float*)d_in[0];
    const float* inputs_mem = (const float*)d_in[1];
    const float* r          = (const float*)d_in[2];
    const float* W          = (const float*)d_in[3];
    const float* W_r        = (const float*)d_in[4];
    const float* W_o        = (const float*)d_in[5];
    const float* u          = (const float*)d_in[6];
    const float* v          = (const float*)d_in[7];
    float* out = (float*)d_out;

    f16 *catH, *W1, *Wr1, *Wo1, *rsH;
    f16 *qkvH, *rpH, *attnH, *attnL, *wt, *scores, *bdu;
    float *biasU, *biasV;
    cudaGetSymbolAddress((void**)&catH, g_catH);
    cudaGetSymbolAddress((void**)&W1, g_W1);
    cudaGetSymbolAddress((void**)&Wr1, g_Wr1);
    cudaGetSymbolAddress((void**)&Wo1, g_Wo1);
    cudaGetSymbolAddress((void**)&rsH, g_rsH);
    cudaGetSymbolAddress((void**)&qkvH, g_qkvH);
    cudaGetSymbolAddress((void**)&rpH, g_rpH);
    cudaGetSymbolAddress((void**)&attnH, g_attnH);cudaGetSymbolAddress((void**)&attnL, g_attnL);
    cudaGetSymbolAddress((void**)&wt, g_wt);
    cudaGetSymbolAddress((void**)&scores, g_scores);
    cudaGetSymbolAddress((void**)&bdu, g_bdu);
    cudaGetSymbolAddress((void**)&biasU, g_biasU);
    cudaGetSymbolAddress((void**)&biasV, g_biasV);

    // smem sizes (bytes)
    const int SM_PROJ = (APL2 + 32 * 136) * 3 * 2;       // 56832
    const int SM_OUT  = (2 * APL2 + 32 * 136) * 3 * 2;   // 87552
    const int SM_V    = (APL2 + 32 * 72) * 3 * 2;        // 44544
    const int SMSC    = 3 * SPL * 2;                     // 55296
    cudaFuncSetAttribute(proj_all, cudaFuncAttributeMaxDynamicSharedMemorySize, SM_PROJ);
    cudaFuncSetAttribute(outgemm,  cudaFuncAttributeMaxDynamicSharedMemorySize, SM_OUT);
    cudaFuncSetAttribute(vgemm,    cudaFuncAttributeMaxDynamicSharedMemorySize, SM_V);
    cudaFuncSetAttribute(score_f16, cudaFuncAttributeMaxDynamicSharedMemorySize, SMSC);

    // 0. merged ingest
    ingest_all<<<NB_W + NB_WR + NB_WO + NB_R + NB_CAT, 256>>>(
        W, W_r, W_o, r, inputs, inputs_mem, W1, Wr1, Wo1, rsH, catH);
    // 1. merged projections (single-plane out): KV + Q + rproj
    proj_all<<<768, 256, SM_PROJ>>>(catH, rsH, W1, Wr1, qkvH, rpH);
    // 2. merged vectorized biases (pre-scaled)
    bias_all<<<(BB * NH * KL + NH * KL) / 256, 256>>>(qkvH, rpH, u, v, biasU, biasV);
    // 3. merged score GEMMs + bias add: z<32 AC, z>=32 BD
    score_f16<<<dim3(KL / 256, QL / 128, 2 * BB * NH), 256, SMSC>>>(
        qkvH, rpH, biasU, biasV, scores, bdu);
    // 4. fused shift+mask+softmax -> fp16 weights
    fused_softmax3<<<BB * NH * QL, 256>>>(scores, bdu, wt);
    // 5. attn = weights @ V -> planes, K clamped
    vgemm<<<dim3(1, QL / 128, BB * NH), 256, SM_V>>>(wt, qkvH, attnH, attnL);
    // 6. out = attn @ W_o (A split, fp32 out)
    outgemm<<<dim3(DM / 128, BB * QL / 128), 256, SM_OUT>>>(attnH, attnL, Wo1, out);
}